// round 2
// baseline (speedup 1.0000x reference)
#include <cuda_runtime.h>

#define E_DIM 1024
#define H_DIM 16
#define D_DIM 64
#define SEQ 2048
#define NB 2
#define NHTOT (NB * H_DIM)

// Scratch: Q/K/V in [n, h, t, d] layout (d contiguous), plus per-(n,h) column mean of V.
__device__ float g_q[NHTOT * SEQ * D_DIM];
__device__ float g_k[NHTOT * SEQ * D_DIM];
__device__ float g_v[NHTOT * SEQ * D_DIM];
__device__ float g_vmean[NHTOT * D_DIM];

// ---------------------------------------------------------------------------
// Projection GEMM: out[i, j] = sum_k X[i,k] * W[j,k] + bias[j]
// X: [4096, 1024] row-major (i = n*SEQ + s), W: [1024, 1024] row-major.
// Result scattered into [n, h, s, d] layout.
// Tiles: BM=64, BN=64, BK=16; 256 threads; 4x4 register blocking.
// ---------------------------------------------------------------------------
__global__ __launch_bounds__(256) void proj_kernel(
    const float* __restrict__ X, const float* __restrict__ W,
    const float* __restrict__ bias, float* __restrict__ out)
{
    __shared__ float As[16][68];  // [k][m]
    __shared__ float Bs[16][68];  // [k][n]

    const int tid = threadIdx.x;
    const int tx = tid & 15;
    const int ty = tid >> 4;
    const int i0 = blockIdx.y * 64;
    const int j0 = blockIdx.x * 64;

    float acc[4][4];
#pragma unroll
    for (int a = 0; a < 4; a++)
#pragma unroll
        for (int b = 0; b < 4; b++) acc[a][b] = 0.0f;

    const int lm = tid >> 2;        // 0..63
    const int lk = (tid & 3) * 4;   // 0,4,8,12

    for (int k0 = 0; k0 < E_DIM; k0 += 16) {
        float4 xa = *(const float4*)(X + (size_t)(i0 + lm) * E_DIM + k0 + lk);
        As[lk + 0][lm] = xa.x; As[lk + 1][lm] = xa.y;
        As[lk + 2][lm] = xa.z; As[lk + 3][lm] = xa.w;
        float4 wb = *(const float4*)(W + (size_t)(j0 + lm) * E_DIM + k0 + lk);
        Bs[lk + 0][lm] = wb.x; Bs[lk + 1][lm] = wb.y;
        Bs[lk + 2][lm] = wb.z; Bs[lk + 3][lm] = wb.w;
        __syncthreads();

#pragma unroll
        for (int k = 0; k < 16; k++) {
            float a[4], b[4];
#pragma unroll
            for (int u = 0; u < 4; u++) a[u] = As[k][ty * 4 + u];
#pragma unroll
            for (int u = 0; u < 4; u++) b[u] = Bs[k][tx * 4 + u];
#pragma unroll
            for (int ii = 0; ii < 4; ii++)
#pragma unroll
                for (int jj = 0; jj < 4; jj++)
                    acc[ii][jj] += a[ii] * b[jj];
        }
        __syncthreads();
    }

#pragma unroll
    for (int ii = 0; ii < 4; ii++) {
        const int gi = i0 + ty * 4 + ii;
        const int n = gi >> 11;          // / SEQ
        const int s = gi & (SEQ - 1);
#pragma unroll
        for (int jj = 0; jj < 4; jj++) {
            const int gj = j0 + tx * 4 + jj;
            const int h = gj >> 6;
            const int dd = gj & 63;
            out[(((size_t)(n * H_DIM + h) * SEQ) + s) * D_DIM + dd] =
                acc[ii][jj] + bias[gj];
        }
    }
}

// ---------------------------------------------------------------------------
// Column mean of V per (n, h): vmean[nh, d] = (1/T) * sum_t V[nh, t, d]
// ---------------------------------------------------------------------------
__global__ __launch_bounds__(256) void vmean_kernel()
{
    __shared__ float red[256];
    const int nh = blockIdx.x;
    const int dd = threadIdx.x & 63;
    const int part = threadIdx.x >> 6;  // 0..3

    float sum = 0.0f;
    const int t0 = part * (SEQ / 4);
    for (int t = t0; t < t0 + SEQ / 4; t++)
        sum += g_v[((size_t)nh * SEQ + t) * D_DIM + dd];

    red[threadIdx.x] = sum;
    __syncthreads();
    if (part == 0) {
        float tot = red[dd] + red[64 + dd] + red[128 + dd] + red[192 + dd];
        g_vmean[nh * D_DIM + dd] = tot * (1.0f / (float)SEQ);
    }
}

// ---------------------------------------------------------------------------
// Flash attention, fp32 SIMT. Tile: 64 query rows x 64 key cols.
// Grid: (S/64 query tiles, N*H). Block: 256 threads = 16x16, 4x4 reg tiles.
// Causal tile skip is exact (exp underflow == reference). Rows whose visible
// scores were ALL -1e9 match the reference's uniform-softmax-over-all-T via
// the vmean fallback.
// ---------------------------------------------------------------------------
__global__ __launch_bounds__(256) void attn_kernel(
    const int* __restrict__ pad, float* __restrict__ out)
{
    extern __shared__ float smem[];
    float* Qs = smem;            // [64][65]
    float* Ks = smem + 4160;     // [64][65]
    float* Vs = smem + 8320;     // [64][65]
    float* Ps = smem + 12480;    // [64][65]

    const int tid = threadIdx.x;
    const int tx = tid & 15;
    const int ty = tid >> 4;
    const int itile = blockIdx.x;       // query tile
    const int nh = blockIdx.y;
    const int nbatch = nh >> 4;         // / H_DIM
    const int h = nh & 15;
    const int i0 = itile * 64;

    // Load Q tile: 64 rows x 64 floats
    for (int idx = tid; idx < 64 * 16; idx += 256) {
        const int row = idx >> 4;
        const int c4 = (idx & 15) * 4;
        float4 v = *(const float4*)(g_q + ((size_t)nh * SEQ + i0 + row) * D_DIM + c4);
        Qs[row * 65 + c4 + 0] = v.x; Qs[row * 65 + c4 + 1] = v.y;
        Qs[row * 65 + c4 + 2] = v.z; Qs[row * 65 + c4 + 3] = v.w;
    }

    float m[4], l[4], acc[4][4];
#pragma unroll
    for (int ii = 0; ii < 4; ii++) {
        m[ii] = -1e9f;
        l[ii] = 0.0f;
#pragma unroll
        for (int jj = 0; jj < 4; jj++) acc[ii][jj] = 0.0f;
    }

    const int jmax = itile;  // causal: visit key tiles 0..itile
    for (int j = 0; j <= jmax; j++) {
        const int t0 = j * 64;
        __syncthreads();  // prior iteration done with Ks/Vs/Ps

        // Load K and V tiles
        for (int idx = tid; idx < 64 * 16; idx += 256) {
            const int row = idx >> 4;
            const int c4 = (idx & 15) * 4;
            float4 kv = *(const float4*)(g_k + ((size_t)nh * SEQ + t0 + row) * D_DIM + c4);
            Ks[row * 65 + c4 + 0] = kv.x; Ks[row * 65 + c4 + 1] = kv.y;
            Ks[row * 65 + c4 + 2] = kv.z; Ks[row * 65 + c4 + 3] = kv.w;
            float4 vv = *(const float4*)(g_v + ((size_t)nh * SEQ + t0 + row) * D_DIM + c4);
            Vs[row * 65 + c4 + 0] = vv.x; Vs[row * 65 + c4 + 1] = vv.y;
            Vs[row * 65 + c4 + 2] = vv.z; Vs[row * 65 + c4 + 3] = vv.w;
        }
        __syncthreads();

        // Scores: S[r][c] = sum_d Q[r][d] * K[c][d]
        float s[4][4];
#pragma unroll
        for (int ii = 0; ii < 4; ii++)
#pragma unroll
            for (int jj = 0; jj < 4; jj++) s[ii][jj] = 0.0f;

#pragma unroll 8
        for (int d = 0; d < 64; d++) {
            float a[4], b[4];
#pragma unroll
            for (int u = 0; u < 4; u++) a[u] = Qs[(ty * 4 + u) * 65 + d];
#pragma unroll
            for (int u = 0; u < 4; u++) b[u] = Ks[(tx * 4 + u) * 65 + d];
#pragma unroll
            for (int ii = 0; ii < 4; ii++)
#pragma unroll
                for (int jj = 0; jj < 4; jj++)
                    s[ii][jj] += a[ii] * b[jj];
        }

        // Scale + mask
#pragma unroll
        for (int ii = 0; ii < 4; ii++) {
            const int qrow = i0 + ty * 4 + ii;
#pragma unroll
            for (int jj = 0; jj < 4; jj++) {
                const int kcol = t0 + tx * 4 + jj;
                float v = s[ii][jj] * 0.125f;
                if (kcol > qrow || pad[nbatch * SEQ + kcol] == 0) v = -1e9f;
                s[ii][jj] = v;
            }
        }

        // Online softmax per row (reduce across the 16 tx lanes)
#pragma unroll
        for (int ii = 0; ii < 4; ii++) {
            float mx = fmaxf(fmaxf(s[ii][0], s[ii][1]), fmaxf(s[ii][2], s[ii][3]));
#pragma unroll
            for (int o = 8; o >= 1; o >>= 1)
                mx = fmaxf(mx, __shfl_xor_sync(0xffffffffu, mx, o));
            const float m_new = fmaxf(m[ii], mx);
            const float corr = __expf(m[ii] - m_new);

            float p[4], rs = 0.0f;
#pragma unroll
            for (int jj = 0; jj < 4; jj++) {
                p[jj] = __expf(s[ii][jj] - m_new);
                rs += p[jj];
            }
#pragma unroll
            for (int o = 8; o >= 1; o >>= 1)
                rs += __shfl_xor_sync(0xffffffffu, rs, o);

            l[ii] = l[ii] * corr + rs;
            m[ii] = m_new;
#pragma unroll
            for (int jj = 0; jj < 4; jj++) acc[ii][jj] *= corr;
#pragma unroll
            for (int jj = 0; jj < 4; jj++)
                Ps[(ty * 4 + ii) * 65 + tx * 4 + jj] = p[jj];
        }
        __syncthreads();

        // acc[r][d] += sum_c P[r][c] * V[c][d]
#pragma unroll 8
        for (int c = 0; c < 64; c++) {
            float a[4], b[4];
#pragma unroll
            for (int u = 0; u < 4; u++) a[u] = Ps[(ty * 4 + u) * 65 + c];
#pragma unroll
            for (int u = 0; u < 4; u++) b[u] = Vs[c * 65 + tx * 4 + u];
#pragma unroll
            for (int ii = 0; ii < 4; ii++)
#pragma unroll
                for (int jj = 0; jj < 4; jj++)
                    acc[ii][jj] += a[ii] * b[jj];
        }
    }

    // Epilogue
#pragma unroll
    for (int ii = 0; ii < 4; ii++) {
        const int srow = i0 + ty * 4 + ii;
        const bool degen = (m[ii] < -1e8f);   // never saw a finite score
        const float invl = 1.0f / l[ii];
#pragma unroll
        for (int jj = 0; jj < 4; jj++) {
            const int dd = tx * 4 + jj;
            float o = degen ? g_vmean[nh * D_DIM + dd] : acc[ii][jj] * invl;
            out[((size_t)(nbatch * SEQ + srow)) * E_DIM + h * D_DIM + dd] = o;
        }
    }
}

// ---------------------------------------------------------------------------
// Launch
// ---------------------------------------------------------------------------
extern "C" void kernel_launch(void* const* d_in, const int* in_sizes, int n_in,
                              void* d_out, int out_size)
{
    const float* query = (const float*)d_in[0];
    const float* key   = (const float*)d_in[1];
    const float* value = (const float*)d_in[2];
    const int*   pad   = (const int*)d_in[3];
    // d_in[4] = subsq_mask (tril, handled analytically)
    const float* Wq = (const float*)d_in[5];
    const float* bq = (const float*)d_in[6];
    const float* Wk = (const float*)d_in[7];
    const float* bk = (const float*)d_in[8];
    const float* Wv = (const float*)d_in[9];
    const float* bv = (const float*)d_in[10];
    float* out = (float*)d_out;

    float *q_buf, *k_buf, *v_buf;
    cudaGetSymbolAddress((void**)&q_buf, g_q);
    cudaGetSymbolAddress((void**)&k_buf, g_k);
    cudaGetSymbolAddress((void**)&v_buf, g_v);

    const int attn_smem = 4 * 64 * 65 * (int)sizeof(float);  // 66560 B
    cudaFuncSetAttribute(attn_kernel, cudaFuncAttributeMaxDynamicSharedMemorySize,
                         attn_smem);

    dim3 pgrid(E_DIM / 64, (NB * SEQ) / 64);
    proj_kernel<<<pgrid, 256>>>(query, Wq, bq, q_buf);
    proj_kernel<<<pgrid, 256>>>(key, Wk, bk, k_buf);
    proj_kernel<<<pgrid, 256>>>(value, Wv, bv, v_buf);

    vmean_kernel<<<NHTOT, 256>>>();

    dim3 agrid(SEQ / 64, NHTOT);
    attn_kernel<<<agrid, 256, attn_smem>>>(pad, out);
}

// round 4
// speedup vs baseline: 2.3667x; 2.3667x over previous
#include <cuda_runtime.h>
#include <cuda_bf16.h>
#include <cstdint>

#define E_DIM 1024
#define H_DIM 16
#define D_DIM 64
#define SEQ 2048
#define NB 2
#define NHTOT (NB * H_DIM)
#define XSZ (NB * SEQ * E_DIM)
#define WSZ (E_DIM * E_DIM)
#define QKV_SZ (NHTOT * SEQ * D_DIM)

// Split bf16 inputs for projections
__device__ __nv_bfloat16 g_xhi[3 * XSZ];
__device__ __nv_bfloat16 g_xlo[3 * XSZ];
__device__ __nv_bfloat16 g_whi[3 * WSZ];
__device__ __nv_bfloat16 g_wlo[3 * WSZ];
// Projected Q/K split bf16, [nh][t][d] (d contiguous)
__device__ __nv_bfloat16 g_qhi[QKV_SZ], g_qlo[QKV_SZ];
__device__ __nv_bfloat16 g_khi[QKV_SZ], g_klo[QKV_SZ];
// Projected V split bf16, TRANSPOSED: [nh][d][t] (t contiguous)
__device__ __nv_bfloat16 g_vthi[QKV_SZ], g_vtlo[QKV_SZ];
__device__ float g_vmean[NHTOT * D_DIM];

// ---------------------------------------------------------------------------
// bf16 MMA m16n8k16 (baseline ISA, runs on tensor pipe as HMMA)
// ---------------------------------------------------------------------------
__device__ __forceinline__ void mma_bf16(float c[4], const uint32_t a[4],
                                         uint32_t b0, uint32_t b1) {
    asm("mma.sync.aligned.m16n8k16.row.col.f32.bf16.bf16.f32 "
        "{%0,%1,%2,%3}, {%4,%5,%6,%7}, {%8,%9}, {%0,%1,%2,%3};"
        : "+f"(c[0]), "+f"(c[1]), "+f"(c[2]), "+f"(c[3])
        : "r"(a[0]), "r"(a[1]), "r"(a[2]), "r"(a[3]), "r"(b0), "r"(b1));
}

__device__ __forceinline__ uint32_t pack_hi(float x, float y) {
    __nv_bfloat162 h(__float2bfloat16(x), __float2bfloat16(y));
    return *reinterpret_cast<uint32_t*>(&h);
}
__device__ __forceinline__ uint32_t pack_lo(float x, float y) {
    float hx = __bfloat162float(__float2bfloat16(x));
    float hy = __bfloat162float(__float2bfloat16(y));
    __nv_bfloat162 l(__float2bfloat16(x - hx), __float2bfloat16(y - hy));
    return *reinterpret_cast<uint32_t*>(&l);
}

// ---------------------------------------------------------------------------
// Split conversion: fp32 -> bf16 hi + lo
// ---------------------------------------------------------------------------
__global__ __launch_bounds__(256) void conv_kernel(
    const float* __restrict__ x, __nv_bfloat16* __restrict__ hi,
    __nv_bfloat16* __restrict__ lo, int n4)
{
    int i = blockIdx.x * blockDim.x + threadIdx.x;
    if (i >= n4) return;
    float4 v = ((const float4*)x)[i];
    ((uint32_t*)hi)[2 * i + 0] = pack_hi(v.x, v.y);
    ((uint32_t*)hi)[2 * i + 1] = pack_hi(v.z, v.w);
    ((uint32_t*)lo)[2 * i + 0] = pack_lo(v.x, v.y);
    ((uint32_t*)lo)[2 * i + 1] = pack_lo(v.z, v.w);
}

// ---------------------------------------------------------------------------
// Projection GEMM via mma.sync: C[i,j] = sum_k X[i,k] W[j,k] + bias[j]
// Block 128x128, 8 warps (4m x 2n), warp tile 32x64. K-chunk 32 in smem.
// z selects q/k/v. Output: split bf16; q/k -> [nh][t][d], v -> [nh][d][t].
// ---------------------------------------------------------------------------
__global__ __launch_bounds__(256) void proj_mma_kernel(
    const float* __restrict__ bq, const float* __restrict__ bk,
    const float* __restrict__ bv)
{
    __shared__ __nv_bfloat16 Ahi[128][40], Alo[128][40];
    __shared__ __nv_bfloat16 Bhi[128][40], Blo[128][40];

    const int tid = threadIdx.x;
    const int w = tid >> 5;
    const int lane = tid & 31;
    const int g = lane >> 2;
    const int tq = lane & 3;
    const int z = blockIdx.z;
    const int j0 = blockIdx.x * 128;
    const int i0 = blockIdx.y * 128;
    const int mrow = (w & 3) * 32;
    const int ncol = (w >> 2) * 64;

    const __nv_bfloat16* xhi = g_xhi + (size_t)z * XSZ;
    const __nv_bfloat16* xlo = g_xlo + (size_t)z * XSZ;
    const __nv_bfloat16* whi = g_whi + (size_t)z * WSZ;
    const __nv_bfloat16* wlo = g_wlo + (size_t)z * WSZ;
    const float* bias = (z == 0) ? bq : (z == 1) ? bk : bv;

    float c[2][8][4];
#pragma unroll
    for (int mt = 0; mt < 2; mt++)
#pragma unroll
        for (int nt = 0; nt < 8; nt++)
#pragma unroll
            for (int u = 0; u < 4; u++) c[mt][nt][u] = 0.0f;

    for (int k0 = 0; k0 < E_DIM; k0 += 32) {
        // Load A/B chunks: 128 rows x 32 bf16 each tensor
#pragma unroll
        for (int it = 0; it < 2; it++) {
            const int idx = tid + it * 256;
            const int row = idx >> 2;
            const int seg = (idx & 3) * 8;
            const size_t ga = (size_t)(i0 + row) * E_DIM + k0 + seg;
            const size_t gb = (size_t)(j0 + row) * E_DIM + k0 + seg;
            *(uint4*)&Ahi[row][seg] = *(const uint4*)(xhi + ga);
            *(uint4*)&Alo[row][seg] = *(const uint4*)(xlo + ga);
            *(uint4*)&Bhi[row][seg] = *(const uint4*)(whi + gb);
            *(uint4*)&Blo[row][seg] = *(const uint4*)(wlo + gb);
        }
        __syncthreads();

#pragma unroll
        for (int kc = 0; kc < 32; kc += 16) {
            uint32_t ah[2][4], al[2][4];
#pragma unroll
            for (int mt = 0; mt < 2; mt++) {
                const int r0 = mrow + mt * 16 + g;
                ah[mt][0] = *(const uint32_t*)&Ahi[r0][kc + 2 * tq];
                ah[mt][1] = *(const uint32_t*)&Ahi[r0 + 8][kc + 2 * tq];
                ah[mt][2] = *(const uint32_t*)&Ahi[r0][kc + 2 * tq + 8];
                ah[mt][3] = *(const uint32_t*)&Ahi[r0 + 8][kc + 2 * tq + 8];
                al[mt][0] = *(const uint32_t*)&Alo[r0][kc + 2 * tq];
                al[mt][1] = *(const uint32_t*)&Alo[r0 + 8][kc + 2 * tq];
                al[mt][2] = *(const uint32_t*)&Alo[r0][kc + 2 * tq + 8];
                al[mt][3] = *(const uint32_t*)&Alo[r0 + 8][kc + 2 * tq + 8];
            }
#pragma unroll
            for (int nt = 0; nt < 8; nt++) {
                const int nr = ncol + nt * 8 + g;
                uint32_t bh0 = *(const uint32_t*)&Bhi[nr][kc + 2 * tq];
                uint32_t bh1 = *(const uint32_t*)&Bhi[nr][kc + 2 * tq + 8];
                uint32_t bl0 = *(const uint32_t*)&Blo[nr][kc + 2 * tq];
                uint32_t bl1 = *(const uint32_t*)&Blo[nr][kc + 2 * tq + 8];
#pragma unroll
                for (int mt = 0; mt < 2; mt++) {
                    mma_bf16(c[mt][nt], ah[mt], bh0, bh1);
                    mma_bf16(c[mt][nt], ah[mt], bl0, bl1);
                    mma_bf16(c[mt][nt], al[mt], bh0, bh1);
                }
            }
        }
        __syncthreads();
    }

    // Epilogue
#pragma unroll
    for (int mt = 0; mt < 2; mt++) {
#pragma unroll
        for (int nt = 0; nt < 8; nt++) {
            const int gj = j0 + ncol + nt * 8 + 2 * tq;
            const int h = gj >> 6;
            const int dd = gj & 63;
            const float b0v = bias[gj], b1v = bias[gj + 1];
            const int r0 = i0 + mrow + mt * 16 + g;
            const int r1 = r0 + 8;
            const float v00 = c[mt][nt][0] + b0v, v01 = c[mt][nt][1] + b1v;
            const float v10 = c[mt][nt][2] + b0v, v11 = c[mt][nt][3] + b1v;
            if (z < 2) {
                __nv_bfloat16* ohi = (z == 0) ? g_qhi : g_khi;
                __nv_bfloat16* olo = (z == 0) ? g_qlo : g_klo;
                const size_t a0 =
                    ((size_t)((r0 >> 11) * H_DIM + h) * SEQ + (r0 & 2047)) * D_DIM + dd;
                const size_t a1 =
                    ((size_t)((r1 >> 11) * H_DIM + h) * SEQ + (r1 & 2047)) * D_DIM + dd;
                *(uint32_t*)(ohi + a0) = pack_hi(v00, v01);
                *(uint32_t*)(olo + a0) = pack_lo(v00, v01);
                *(uint32_t*)(ohi + a1) = pack_hi(v10, v11);
                *(uint32_t*)(olo + a1) = pack_lo(v10, v11);
            } else {
                // V transposed: [nh][d][t]
                const int nh0 = (r0 >> 11) * H_DIM + h;
                const size_t b0 = ((size_t)nh0 * D_DIM + dd) * SEQ;
                const size_t b1 = ((size_t)nh0 * D_DIM + dd + 1) * SEQ;
                const int t0a = r0 & 2047, t1a = r1 & 2047;
                float h00 = __bfloat162float(__float2bfloat16(v00));
                float h01 = __bfloat162float(__float2bfloat16(v01));
                float h10 = __bfloat162float(__float2bfloat16(v10));
                float h11 = __bfloat162float(__float2bfloat16(v11));
                g_vthi[b0 + t0a] = __float2bfloat16(v00);
                g_vtlo[b0 + t0a] = __float2bfloat16(v00 - h00);
                g_vthi[b1 + t0a] = __float2bfloat16(v01);
                g_vtlo[b1 + t0a] = __float2bfloat16(v01 - h01);
                g_vthi[b0 + t1a] = __float2bfloat16(v10);
                g_vtlo[b0 + t1a] = __float2bfloat16(v10 - h10);
                g_vthi[b1 + t1a] = __float2bfloat16(v11);
                g_vtlo[b1 + t1a] = __float2bfloat16(v11 - h11);
            }
        }
    }
}

// ---------------------------------------------------------------------------
// Column mean of V per (n,h) from transposed split V
// ---------------------------------------------------------------------------
__global__ __launch_bounds__(256) void vmean_kernel()
{
    const int nh = blockIdx.x;
    const int w = threadIdx.x >> 5;
    const int lane = threadIdx.x & 31;
    for (int dd = w; dd < D_DIM; dd += 8) {
        const size_t base = ((size_t)nh * D_DIM + dd) * SEQ;
        float sum = 0.0f;
        for (int cI = 0; cI < SEQ / 32 / 2; cI++) {
            const int off = lane * (SEQ / 32) + cI * 2;
            uint32_t uh = *(const uint32_t*)(g_vthi + base + off);
            uint32_t ul = *(const uint32_t*)(g_vtlo + base + off);
            __nv_bfloat162 h2 = *reinterpret_cast<__nv_bfloat162*>(&uh);
            __nv_bfloat162 l2 = *reinterpret_cast<__nv_bfloat162*>(&ul);
            sum += __bfloat162float(h2.x) + __bfloat162float(l2.x);
            sum += __bfloat162float(h2.y) + __bfloat162float(l2.y);
        }
#pragma unroll
        for (int o = 16; o >= 1; o >>= 1)
            sum += __shfl_xor_sync(0xffffffffu, sum, o);
        if (lane == 0) g_vmean[nh * D_DIM + dd] = sum * (1.0f / (float)SEQ);
    }
}

// ---------------------------------------------------------------------------
// Flash attention with mma.sync, split-bf16 precision.
// Block: 64 q-rows x 64 kv, 4 warps; each warp owns 16 q-rows.
// ---------------------------------------------------------------------------
__global__ __launch_bounds__(128) void attn_mma_kernel(
    const int* __restrict__ pad, float* __restrict__ out)
{
    __shared__ __nv_bfloat16 Khi[64][72], Klo[64][72];
    __shared__ __nv_bfloat16 Vhi[64][72], Vlo[64][72];
    __shared__ int pads[64];

    const int tid = threadIdx.x;
    const int w = tid >> 5;
    const int lane = tid & 31;
    const int g = lane >> 2;
    const int tq = lane & 3;
    const int qt = blockIdx.x;
    const int nh = blockIdx.y;
    const int nb = nh >> 4;
    const int h = nh & 15;
    const int i0 = qt * 64;
    const int qr0 = i0 + w * 16 + g;   // row for c0/c1
    const int qr1 = qr0 + 8;           // row for c2/c3

    // Q fragments in registers (hi + lo)
    uint32_t qh[4][4], ql[4][4];
    {
        const size_t b0 = ((size_t)nh * SEQ + qr0) * D_DIM;
        const size_t b1 = ((size_t)nh * SEQ + qr1) * D_DIM;
#pragma unroll
        for (int kd = 0; kd < 4; kd++) {
            const int cO = kd * 16 + 2 * tq;
            qh[kd][0] = *(const uint32_t*)(g_qhi + b0 + cO);
            qh[kd][1] = *(const uint32_t*)(g_qhi + b1 + cO);
            qh[kd][2] = *(const uint32_t*)(g_qhi + b0 + cO + 8);
            qh[kd][3] = *(const uint32_t*)(g_qhi + b1 + cO + 8);
            ql[kd][0] = *(const uint32_t*)(g_qlo + b0 + cO);
            ql[kd][1] = *(const uint32_t*)(g_qlo + b1 + cO);
            ql[kd][2] = *(const uint32_t*)(g_qlo + b0 + cO + 8);
            ql[kd][3] = *(const uint32_t*)(g_qlo + b1 + cO + 8);
        }
    }

    float o[8][4];
#pragma unroll
    for (int dt = 0; dt < 8; dt++)
#pragma unroll
        for (int u = 0; u < 4; u++) o[dt][u] = 0.0f;
    float m0 = -1e9f, m1 = -1e9f, l0 = 0.0f, l1 = 0.0f;

    for (int j = 0; j <= qt; j++) {
        const int t0 = j * 64;
        __syncthreads();
        // Load K and V^T tiles (hi/lo)
#pragma unroll
        for (int it = 0; it < 4; it++) {
            const int idx = tid + it * 128;
            const int row = idx >> 3;
            const int seg = (idx & 7) * 8;
            const size_t gk = ((size_t)nh * SEQ + t0 + row) * D_DIM + seg;
            const size_t gv = ((size_t)nh * D_DIM + row) * SEQ + t0 + seg;
            *(uint4*)&Khi[row][seg] = *(const uint4*)(g_khi + gk);
            *(uint4*)&Klo[row][seg] = *(const uint4*)(g_klo + gk);
            *(uint4*)&Vhi[row][seg] = *(const uint4*)(g_vthi + gv);
            *(uint4*)&Vlo[row][seg] = *(const uint4*)(g_vtlo + gv);
        }
        if (tid < 64) pads[tid] = pad[nb * SEQ + t0 + tid];
        __syncthreads();

        // S = Q K^T (split, fp32 acc)
        float s[8][4];
#pragma unroll
        for (int nt = 0; nt < 8; nt++) {
#pragma unroll
            for (int u = 0; u < 4; u++) s[nt][u] = 0.0f;
            const int nr = nt * 8 + g;
#pragma unroll
            for (int kd = 0; kd < 4; kd++) {
                const int cO = kd * 16 + 2 * tq;
                uint32_t bh0 = *(const uint32_t*)&Khi[nr][cO];
                uint32_t bh1 = *(const uint32_t*)&Khi[nr][cO + 8];
                uint32_t bl0 = *(const uint32_t*)&Klo[nr][cO];
                uint32_t bl1 = *(const uint32_t*)&Klo[nr][cO + 8];
                mma_bf16(s[nt], qh[kd], bh0, bh1);
                mma_bf16(s[nt], qh[kd], bl0, bl1);
                mma_bf16(s[nt], ql[kd], bh0, bh1);
            }
        }

        // Scale + mask
#pragma unroll
        for (int nt = 0; nt < 8; nt++) {
            const int c0 = nt * 8 + 2 * tq;
#pragma unroll
            for (int u = 0; u < 4; u++) {
                const int cl = c0 + (u & 1);
                const int kcol = t0 + cl;
                const int qrow = (u < 2) ? qr0 : qr1;
                float v = s[nt][u] * 0.125f;
                if (kcol > qrow || pads[cl] == 0) v = -1e9f;
                s[nt][u] = v;
            }
        }

        // Online softmax (rows qr0, qr1)
        float mx0 = -1e30f, mx1 = -1e30f;
#pragma unroll
        for (int nt = 0; nt < 8; nt++) {
            mx0 = fmaxf(mx0, fmaxf(s[nt][0], s[nt][1]));
            mx1 = fmaxf(mx1, fmaxf(s[nt][2], s[nt][3]));
        }
#pragma unroll
        for (int off = 1; off <= 2; off <<= 1) {
            mx0 = fmaxf(mx0, __shfl_xor_sync(0xffffffffu, mx0, off));
            mx1 = fmaxf(mx1, __shfl_xor_sync(0xffffffffu, mx1, off));
        }
        const float mn0 = fmaxf(m0, mx0), mn1 = fmaxf(m1, mx1);
        const float cr0 = __expf(m0 - mn0), cr1 = __expf(m1 - mn1);
        float rs0 = 0.0f, rs1 = 0.0f;
#pragma unroll
        for (int nt = 0; nt < 8; nt++) {
            s[nt][0] = __expf(s[nt][0] - mn0);
            s[nt][1] = __expf(s[nt][1] - mn0);
            s[nt][2] = __expf(s[nt][2] - mn1);
            s[nt][3] = __expf(s[nt][3] - mn1);
            rs0 += s[nt][0] + s[nt][1];
            rs1 += s[nt][2] + s[nt][3];
        }
#pragma unroll
        for (int off = 1; off <= 2; off <<= 1) {
            rs0 += __shfl_xor_sync(0xffffffffu, rs0, off);
            rs1 += __shfl_xor_sync(0xffffffffu, rs1, off);
        }
        l0 = l0 * cr0 + rs0;
        l1 = l1 * cr1 + rs1;
        m0 = mn0;
        m1 = mn1;
#pragma unroll
        for (int dt = 0; dt < 8; dt++) {
            o[dt][0] *= cr0; o[dt][1] *= cr0;
            o[dt][2] *= cr1; o[dt][3] *= cr1;
        }

        // O += P V (split P in registers via C->A fragment repack)
#pragma unroll
        for (int kc = 0; kc < 4; kc++) {
            uint32_t ph[4], pl[4];
            ph[0] = pack_hi(s[2 * kc][0], s[2 * kc][1]);
            ph[1] = pack_hi(s[2 * kc][2], s[2 * kc][3]);
            ph[2] = pack_hi(s[2 * kc + 1][0], s[2 * kc + 1][1]);
            ph[3] = pack_hi(s[2 * kc + 1][2], s[2 * kc + 1][3]);
            pl[0] = pack_lo(s[2 * kc][0], s[2 * kc][1]);
            pl[1] = pack_lo(s[2 * kc][2], s[2 * kc][3]);
            pl[2] = pack_lo(s[2 * kc + 1][0], s[2 * kc + 1][1]);
            pl[3] = pack_lo(s[2 * kc + 1][2], s[2 * kc + 1][3]);
            const int cO = kc * 16 + 2 * tq;
#pragma unroll
            for (int dt = 0; dt < 8; dt++) {
                const int dr = dt * 8 + g;
                uint32_t bh0 = *(const uint32_t*)&Vhi[dr][cO];
                uint32_t bh1 = *(const uint32_t*)&Vhi[dr][cO + 8];
                uint32_t bl0 = *(const uint32_t*)&Vlo[dr][cO];
                uint32_t bl1 = *(const uint32_t*)&Vlo[dr][cO + 8];
                mma_bf16(o[dt], ph, bh0, bh1);
                mma_bf16(o[dt], ph, bl0, bl1);
                mma_bf16(o[dt], pl, bh0, bh1);
            }
        }
    }

    // Epilogue
    const float inv0 = 1.0f / l0, inv1 = 1.0f / l1;
    const bool dg0 = (m0 < -5e8f), dg1 = (m1 < -5e8f);
#pragma unroll
    for (int dt = 0; dt < 8; dt++) {
        const int dd = dt * 8 + 2 * tq;
        float o00 = dg0 ? g_vmean[nh * D_DIM + dd] : o[dt][0] * inv0;
        float o01 = dg0 ? g_vmean[nh * D_DIM + dd + 1] : o[dt][1] * inv0;
        float o10 = dg1 ? g_vmean[nh * D_DIM + dd] : o[dt][2] * inv1;
        float o11 = dg1 ? g_vmean[nh * D_DIM + dd + 1] : o[dt][3] * inv1;
        float2* p0 = (float2*)(out + ((size_t)(nb * SEQ + qr0)) * E_DIM + h * D_DIM + dd);
        float2* p1 = (float2*)(out + ((size_t)(nb * SEQ + qr1)) * E_DIM + h * D_DIM + dd);
        *p0 = make_float2(o00, o01);
        *p1 = make_float2(o10, o11);
    }
}

// ---------------------------------------------------------------------------
// Launch
// ---------------------------------------------------------------------------
extern "C" void kernel_launch(void* const* d_in, const int* in_sizes, int n_in,
                              void* d_out, int out_size)
{
    const float* query = (const float*)d_in[0];
    const float* key   = (const float*)d_in[1];
    const float* value = (const float*)d_in[2];
    const int*   pad   = (const int*)d_in[3];
    const float* Wq = (const float*)d_in[5];
    const float* bq = (const float*)d_in[6];
    const float* Wk = (const float*)d_in[7];
    const float* bk = (const float*)d_in[8];
    const float* Wv = (const float*)d_in[9];
    const float* bv = (const float*)d_in[10];
    float* out = (float*)d_out;

    __nv_bfloat16 *xhi, *xlo, *whi, *wlo;
    cudaGetSymbolAddress((void**)&xhi, g_xhi);
    cudaGetSymbolAddress((void**)&xlo, g_xlo);
    cudaGetSymbolAddress((void**)&whi, g_whi);
    cudaGetSymbolAddress((void**)&wlo, g_wlo);

    conv_kernel<<<XSZ / 4 / 256, 256>>>(query, xhi + 0 * (size_t)XSZ, xlo + 0 * (size_t)XSZ, XSZ / 4);
    conv_kernel<<<XSZ / 4 / 256, 256>>>(key,   xhi + 1 * (size_t)XSZ, xlo + 1 * (size_t)XSZ, XSZ / 4);
    conv_kernel<<<XSZ / 4 / 256, 256>>>(value, xhi + 2 * (size_t)XSZ, xlo + 2 * (size_t)XSZ, XSZ / 4);
    conv_kernel<<<WSZ / 4 / 256, 256>>>(Wq, whi + 0 * (size_t)WSZ, wlo + 0 * (size_t)WSZ, WSZ / 4);
    conv_kernel<<<WSZ / 4 / 256, 256>>>(Wk, whi + 1 * (size_t)WSZ, wlo + 1 * (size_t)WSZ, WSZ / 4);
    conv_kernel<<<WSZ / 4 / 256, 256>>>(Wv, whi + 2 * (size_t)WSZ, wlo + 2 * (size_t)WSZ, WSZ / 4);

    dim3 pgrid(E_DIM / 128, (NB * SEQ) / 128, 3);
    proj_mma_kernel<<<pgrid, 256>>>(bq, bk, bv);

    vmean_kernel<<<NHTOT, 256>>>();

    dim3 agrid(SEQ / 64, NHTOT);
    attn_mma_kernel<<<agrid, 128>>>(pad, out);
}

// round 6
// speedup vs baseline: 2.4751x; 1.0458x over previous
#include <cuda_runtime.h>
#include <cuda_bf16.h>
#include <cstdint>

#define E_DIM 1024
#define H_DIM 16
#define D_DIM 64
#define SEQ 2048
#define NB 2
#define NHTOT (NB * H_DIM)
#define XSZ (NB * SEQ * E_DIM)
#define WSZ (E_DIM * E_DIM)
#define QKV_SZ (NHTOT * SEQ * D_DIM)

// Split bf16 inputs for projections
__device__ __nv_bfloat16 g_xhi[3 * XSZ];
__device__ __nv_bfloat16 g_xlo[3 * XSZ];
__device__ __nv_bfloat16 g_whi[3 * WSZ];
__device__ __nv_bfloat16 g_wlo[3 * WSZ];
// Projected Q/K split bf16, [nh][t][d] (d contiguous)
__device__ __nv_bfloat16 g_qhi[QKV_SZ], g_qlo[QKV_SZ];
__device__ __nv_bfloat16 g_khi[QKV_SZ], g_klo[QKV_SZ];
// Projected V split bf16, TRANSPOSED: [nh][d][t] (t contiguous)
__device__ __nv_bfloat16 g_vthi[QKV_SZ], g_vtlo[QKV_SZ];
__device__ float g_vmean[NHTOT * D_DIM];

// ---------------------------------------------------------------------------
// Helpers
// ---------------------------------------------------------------------------
__device__ __forceinline__ void mma_bf16(float c[4], const uint32_t a[4],
                                         uint32_t b0, uint32_t b1) {
    asm("mma.sync.aligned.m16n8k16.row.col.f32.bf16.bf16.f32 "
        "{%0,%1,%2,%3}, {%4,%5,%6,%7}, {%8,%9}, {%0,%1,%2,%3};"
        : "+f"(c[0]), "+f"(c[1]), "+f"(c[2]), "+f"(c[3])
        : "r"(a[0]), "r"(a[1]), "r"(a[2]), "r"(a[3]), "r"(b0), "r"(b1));
}

__device__ __forceinline__ uint32_t smem_u32(const void* p) {
    uint32_t a;
    asm("{ .reg .u64 t; cvta.to.shared.u64 t, %1; cvt.u32.u64 %0, t; }"
        : "=r"(a) : "l"(p));
    return a;
}

__device__ __forceinline__ void cp16(uint32_t dst, const void* src) {
    asm volatile("cp.async.cg.shared.global [%0], [%1], 16;" :: "r"(dst), "l"(src));
}
#define CP_COMMIT() asm volatile("cp.async.commit_group;" ::: "memory")
#define CP_WAIT0() asm volatile("cp.async.wait_group 0;" ::: "memory")
#define CP_WAIT1() asm volatile("cp.async.wait_group 1;" ::: "memory")

__device__ __forceinline__ uint32_t pack_hi(float x, float y) {
    __nv_bfloat162 h(__float2bfloat16(x), __float2bfloat16(y));
    return *reinterpret_cast<uint32_t*>(&h);
}
__device__ __forceinline__ uint32_t pack_lo(float x, float y) {
    float hx = __bfloat162float(__float2bfloat16(x));
    float hy = __bfloat162float(__float2bfloat16(y));
    __nv_bfloat162 l(__float2bfloat16(x - hx), __float2bfloat16(y - hy));
    return *reinterpret_cast<uint32_t*>(&l);
}

// ---------------------------------------------------------------------------
// Split conversion: fp32 -> bf16 hi + lo
// ---------------------------------------------------------------------------
__global__ __launch_bounds__(256) void conv_kernel(
    const float* __restrict__ x, __nv_bfloat16* __restrict__ hi,
    __nv_bfloat16* __restrict__ lo, int n4)
{
    int i = blockIdx.x * blockDim.x + threadIdx.x;
    if (i >= n4) return;
    float4 v = ((const float4*)x)[i];
    ((uint32_t*)hi)[2 * i + 0] = pack_hi(v.x, v.y);
    ((uint32_t*)hi)[2 * i + 1] = pack_hi(v.z, v.w);
    ((uint32_t*)lo)[2 * i + 0] = pack_lo(v.x, v.y);
    ((uint32_t*)lo)[2 * i + 1] = pack_lo(v.z, v.w);
}

// ---------------------------------------------------------------------------
// Projection GEMM (EXACT R4 kernel — known good).
// ---------------------------------------------------------------------------
__global__ __launch_bounds__(256) void proj_mma_kernel(
    const float* __restrict__ bq, const float* __restrict__ bk,
    const float* __restrict__ bv)
{
    __shared__ __nv_bfloat16 Ahi[128][40], Alo[128][40];
    __shared__ __nv_bfloat16 Bhi[128][40], Blo[128][40];

    const int tid = threadIdx.x;
    const int w = tid >> 5;
    const int lane = tid & 31;
    const int g = lane >> 2;
    const int tq = lane & 3;
    const int z = blockIdx.z;
    const int j0 = blockIdx.x * 128;
    const int i0 = blockIdx.y * 128;
    const int mrow = (w & 3) * 32;
    const int ncol = (w >> 2) * 64;

    const __nv_bfloat16* xhi = g_xhi + (size_t)z * XSZ;
    const __nv_bfloat16* xlo = g_xlo + (size_t)z * XSZ;
    const __nv_bfloat16* whi = g_whi + (size_t)z * WSZ;
    const __nv_bfloat16* wlo = g_wlo + (size_t)z * WSZ;
    const float* bias = (z == 0) ? bq : (z == 1) ? bk : bv;

    float c[2][8][4];
#pragma unroll
    for (int mt = 0; mt < 2; mt++)
#pragma unroll
        for (int nt = 0; nt < 8; nt++)
#pragma unroll
            for (int u = 0; u < 4; u++) c[mt][nt][u] = 0.0f;

    for (int k0 = 0; k0 < E_DIM; k0 += 32) {
#pragma unroll
        for (int it = 0; it < 2; it++) {
            const int idx = tid + it * 256;
            const int row = idx >> 2;
            const int seg = (idx & 3) * 8;
            const size_t ga = (size_t)(i0 + row) * E_DIM + k0 + seg;
            const size_t gb = (size_t)(j0 + row) * E_DIM + k0 + seg;
            *(uint4*)&Ahi[row][seg] = *(const uint4*)(xhi + ga);
            *(uint4*)&Alo[row][seg] = *(const uint4*)(xlo + ga);
            *(uint4*)&Bhi[row][seg] = *(const uint4*)(whi + gb);
            *(uint4*)&Blo[row][seg] = *(const uint4*)(wlo + gb);
        }
        __syncthreads();

#pragma unroll
        for (int kc = 0; kc < 32; kc += 16) {
            uint32_t ah[2][4], al[2][4];
#pragma unroll
            for (int mt = 0; mt < 2; mt++) {
                const int r0 = mrow + mt * 16 + g;
                ah[mt][0] = *(const uint32_t*)&Ahi[r0][kc + 2 * tq];
                ah[mt][1] = *(const uint32_t*)&Ahi[r0 + 8][kc + 2 * tq];
                ah[mt][2] = *(const uint32_t*)&Ahi[r0][kc + 2 * tq + 8];
                ah[mt][3] = *(const uint32_t*)&Ahi[r0 + 8][kc + 2 * tq + 8];
                al[mt][0] = *(const uint32_t*)&Alo[r0][kc + 2 * tq];
                al[mt][1] = *(const uint32_t*)&Alo[r0 + 8][kc + 2 * tq];
                al[mt][2] = *(const uint32_t*)&Alo[r0][kc + 2 * tq + 8];
                al[mt][3] = *(const uint32_t*)&Alo[r0 + 8][kc + 2 * tq + 8];
            }
#pragma unroll
            for (int nt = 0; nt < 8; nt++) {
                const int nr = ncol + nt * 8 + g;
                uint32_t bh0 = *(const uint32_t*)&Bhi[nr][kc + 2 * tq];
                uint32_t bh1 = *(const uint32_t*)&Bhi[nr][kc + 2 * tq + 8];
                uint32_t bl0 = *(const uint32_t*)&Blo[nr][kc + 2 * tq];
                uint32_t bl1 = *(const uint32_t*)&Blo[nr][kc + 2 * tq + 8];
#pragma unroll
                for (int mt = 0; mt < 2; mt++) {
                    mma_bf16(c[mt][nt], ah[mt], bh0, bh1);
                    mma_bf16(c[mt][nt], ah[mt], bl0, bl1);
                    mma_bf16(c[mt][nt], al[mt], bh0, bh1);
                }
            }
        }
        __syncthreads();
    }

#pragma unroll
    for (int mt = 0; mt < 2; mt++) {
#pragma unroll
        for (int nt = 0; nt < 8; nt++) {
            const int gj = j0 + ncol + nt * 8 + 2 * tq;
            const int h = gj >> 6;
            const int dd = gj & 63;
            const float b0v = bias[gj], b1v = bias[gj + 1];
            const int r0 = i0 + mrow + mt * 16 + g;
            const int r1 = r0 + 8;
            const float v00 = c[mt][nt][0] + b0v, v01 = c[mt][nt][1] + b1v;
            const float v10 = c[mt][nt][2] + b0v, v11 = c[mt][nt][3] + b1v;
            if (z < 2) {
                __nv_bfloat16* ohi = (z == 0) ? g_qhi : g_khi;
                __nv_bfloat16* olo = (z == 0) ? g_qlo : g_klo;
                const size_t a0 =
                    ((size_t)((r0 >> 11) * H_DIM + h) * SEQ + (r0 & 2047)) * D_DIM + dd;
                const size_t a1 =
                    ((size_t)((r1 >> 11) * H_DIM + h) * SEQ + (r1 & 2047)) * D_DIM + dd;
                *(uint32_t*)(ohi + a0) = pack_hi(v00, v01);
                *(uint32_t*)(olo + a0) = pack_lo(v00, v01);
                *(uint32_t*)(ohi + a1) = pack_hi(v10, v11);
                *(uint32_t*)(olo + a1) = pack_lo(v10, v11);
            } else {
                const int nh0 = (r0 >> 11) * H_DIM + h;
                const size_t b0 = ((size_t)nh0 * D_DIM + dd) * SEQ;
                const size_t b1 = ((size_t)nh0 * D_DIM + dd + 1) * SEQ;
                const int t0a = r0 & 2047, t1a = r1 & 2047;
                float h00 = __bfloat162float(__float2bfloat16(v00));
                float h01 = __bfloat162float(__float2bfloat16(v01));
                float h10 = __bfloat162float(__float2bfloat16(v10));
                float h11 = __bfloat162float(__float2bfloat16(v11));
                g_vthi[b0 + t0a] = __float2bfloat16(v00);
                g_vtlo[b0 + t0a] = __float2bfloat16(v00 - h00);
                g_vthi[b1 + t0a] = __float2bfloat16(v01);
                g_vtlo[b1 + t0a] = __float2bfloat16(v01 - h01);
                g_vthi[b0 + t1a] = __float2bfloat16(v10);
                g_vtlo[b0 + t1a] = __float2bfloat16(v10 - h10);
                g_vthi[b1 + t1a] = __float2bfloat16(v11);
                g_vtlo[b1 + t1a] = __float2bfloat16(v11 - h11);
            }
        }
    }
}

// ---------------------------------------------------------------------------
// Column mean of V per (n,h); grid (NHTOT, 8), warp per d column.
// ---------------------------------------------------------------------------
__global__ __launch_bounds__(256) void vmean_kernel()
{
    const int nh = blockIdx.x;
    const int w = threadIdx.x >> 5;
    const int lane = threadIdx.x & 31;
    const int dd = blockIdx.y * 8 + w;
    const size_t base = ((size_t)nh * D_DIM + dd) * SEQ;
    float sum = 0.0f;
    for (int cI = 0; cI < SEQ / 32 / 2; cI++) {
        const int off = lane * (SEQ / 32) + cI * 2;
        uint32_t uh = *(const uint32_t*)(g_vthi + base + off);
        uint32_t ul = *(const uint32_t*)(g_vtlo + base + off);
        __nv_bfloat162 h2 = *reinterpret_cast<__nv_bfloat162*>(&uh);
        __nv_bfloat162 l2 = *reinterpret_cast<__nv_bfloat162*>(&ul);
        sum += __bfloat162float(h2.x) + __bfloat162float(l2.x);
        sum += __bfloat162float(h2.y) + __bfloat162float(l2.y);
    }
#pragma unroll
    for (int o = 16; o >= 1; o >>= 1)
        sum += __shfl_xor_sync(0xffffffffu, sum, o);
    if (lane == 0) g_vmean[nh * D_DIM + dd] = sum * (1.0f / (float)SEQ);
}

// ---------------------------------------------------------------------------
// Flash attention: 128 q-rows x 64 kv per block, 8 warps, cp.async double
// buffer, DIRECT LDS fragment loads (R4-proven), heavy-tile-first.
// ---------------------------------------------------------------------------
#define AT_STRIDE 72
#define AT_T (64 * AT_STRIDE)                   // elements per tensor tile
#define AT_BUF (4 * AT_T)                       // elements per buffer
#define AT_PADS_OFF (2 * AT_BUF * 2)            // byte offset of pads[2][64]
#define AT_SMEM (AT_PADS_OFF + 2 * 64 * 4)      // 74240 bytes

__global__ __launch_bounds__(256) void attn_mma_kernel(
    const int* __restrict__ pad, float* __restrict__ out)
{
    extern __shared__ __nv_bfloat16 sm[];
    const uint32_t smb = smem_u32(sm);

    const int tid = threadIdx.x;
    const int w = tid >> 5;
    const int lane = tid & 31;
    const int g = lane >> 2;
    const int tq = lane & 3;
    const int qt = (int)(gridDim.x - 1 - blockIdx.x);  // heavy tiles first
    const int nh = blockIdx.y;
    const int nb = nh >> 4;
    const int h = nh & 15;
    const int i0 = qt * 128;
    const int qr0 = i0 + w * 16 + g;
    const int qr1 = qr0 + 8;

    // Q fragments in registers (hi + lo)
    uint32_t qh[4][4], ql[4][4];
    {
        const size_t b0 = ((size_t)nh * SEQ + qr0) * D_DIM;
        const size_t b1 = ((size_t)nh * SEQ + qr1) * D_DIM;
#pragma unroll
        for (int kd = 0; kd < 4; kd++) {
            const int cO = kd * 16 + 2 * tq;
            qh[kd][0] = *(const uint32_t*)(g_qhi + b0 + cO);
            qh[kd][1] = *(const uint32_t*)(g_qhi + b1 + cO);
            qh[kd][2] = *(const uint32_t*)(g_qhi + b0 + cO + 8);
            qh[kd][3] = *(const uint32_t*)(g_qhi + b1 + cO + 8);
            ql[kd][0] = *(const uint32_t*)(g_qlo + b0 + cO);
            ql[kd][1] = *(const uint32_t*)(g_qlo + b1 + cO);
            ql[kd][2] = *(const uint32_t*)(g_qlo + b0 + cO + 8);
            ql[kd][3] = *(const uint32_t*)(g_qlo + b1 + cO + 8);
        }
    }

    auto load_tiles = [&](int buf, int t0) {
        const uint32_t base = smb + buf * (AT_BUF * 2);
        const __nv_bfloat16* kh = g_khi + ((size_t)nh * SEQ + t0) * D_DIM;
        const __nv_bfloat16* kl = g_klo + ((size_t)nh * SEQ + t0) * D_DIM;
        const __nv_bfloat16* vh = g_vthi + (size_t)nh * D_DIM * SEQ + t0;
        const __nv_bfloat16* vl = g_vtlo + (size_t)nh * D_DIM * SEQ + t0;
#pragma unroll
        for (int it = 0; it < 2; it++) {
            const int idx = tid + it * 256;
            const int row = idx >> 3;
            const int seg = (idx & 7) * 8;
            const uint32_t so = (uint32_t)(row * AT_STRIDE + seg) * 2;
            cp16(base + 0 * AT_T * 2 + so, kh + (size_t)row * D_DIM + seg);
            cp16(base + 1 * AT_T * 2 + so, kl + (size_t)row * D_DIM + seg);
            cp16(base + 2 * AT_T * 2 + so, vh + (size_t)row * SEQ + seg);
            cp16(base + 3 * AT_T * 2 + so, vl + (size_t)row * SEQ + seg);
        }
        if (tid < 16)
            cp16(smb + AT_PADS_OFF + buf * 256 + tid * 16,
                 pad + nb * SEQ + t0 + tid * 4);
        CP_COMMIT();
    };

    float o[8][4];
#pragma unroll
    for (int dt = 0; dt < 8; dt++)
#pragma unroll
        for (int u = 0; u < 4; u++) o[dt][u] = 0.0f;
    float m0 = -1e9f, m1 = -1e9f, l0 = 0.0f, l1 = 0.0f;

    const int jmax = 2 * qt + 1;
    load_tiles(0, 0);

    for (int j = 0; j <= jmax; j++) {
        const int t0 = j * 64;
        if (j < jmax) load_tiles((j + 1) & 1, (j + 1) * 64);
        if (j < jmax) { CP_WAIT1(); } else { CP_WAIT0(); }
        __syncthreads();

        const __nv_bfloat16* Kh = sm + (j & 1) * AT_BUF + 0 * AT_T;
        const __nv_bfloat16* Kl = sm + (j & 1) * AT_BUF + 1 * AT_T;
        const __nv_bfloat16* Vh = sm + (j & 1) * AT_BUF + 2 * AT_T;
        const __nv_bfloat16* Vl = sm + (j & 1) * AT_BUF + 3 * AT_T;
        const int* pads = (const int*)((const char*)sm + AT_PADS_OFF + (j & 1) * 256);

        // S = Q K^T (split, fp32 acc) — direct LDS fragment loads (R4 pattern)
        float s[8][4];
#pragma unroll
        for (int nt = 0; nt < 8; nt++) {
#pragma unroll
            for (int u = 0; u < 4; u++) s[nt][u] = 0.0f;
            const int nr = nt * 8 + g;
#pragma unroll
            for (int kd = 0; kd < 4; kd++) {
                const int cO = kd * 16 + 2 * tq;
                uint32_t bh0 = *(const uint32_t*)(Kh + nr * AT_STRIDE + cO);
                uint32_t bh1 = *(const uint32_t*)(Kh + nr * AT_STRIDE + cO + 8);
                uint32_t bl0 = *(const uint32_t*)(Kl + nr * AT_STRIDE + cO);
                uint32_t bl1 = *(const uint32_t*)(Kl + nr * AT_STRIDE + cO + 8);
                mma_bf16(s[nt], qh[kd], bh0, bh1);
                mma_bf16(s[nt], qh[kd], bl0, bl1);
                mma_bf16(s[nt], ql[kd], bh0, bh1);
            }
        }

        // Scale + mask
#pragma unroll
        for (int nt = 0; nt < 8; nt++) {
            const int c0 = nt * 8 + 2 * tq;
#pragma unroll
            for (int u = 0; u < 4; u++) {
                const int cl = c0 + (u & 1);
                const int kcol = t0 + cl;
                const int qrow = (u < 2) ? qr0 : qr1;
                float v = s[nt][u] * 0.125f;
                if (kcol > qrow || pads[cl] == 0) v = -1e9f;
                s[nt][u] = v;
            }
        }

        // Online softmax
        float mx0 = -1e30f, mx1 = -1e30f;
#pragma unroll
        for (int nt = 0; nt < 8; nt++) {
            mx0 = fmaxf(mx0, fmaxf(s[nt][0], s[nt][1]));
            mx1 = fmaxf(mx1, fmaxf(s[nt][2], s[nt][3]));
        }
#pragma unroll
        for (int off = 1; off <= 2; off <<= 1) {
            mx0 = fmaxf(mx0, __shfl_xor_sync(0xffffffffu, mx0, off));
            mx1 = fmaxf(mx1, __shfl_xor_sync(0xffffffffu, mx1, off));
        }
        const float mn0 = fmaxf(m0, mx0), mn1 = fmaxf(m1, mx1);
        const float cr0 = __expf(m0 - mn0), cr1 = __expf(m1 - mn1);
        float rs0 = 0.0f, rs1 = 0.0f;
#pragma unroll
        for (int nt = 0; nt < 8; nt++) {
            s[nt][0] = __expf(s[nt][0] - mn0);
            s[nt][1] = __expf(s[nt][1] - mn0);
            s[nt][2] = __expf(s[nt][2] - mn1);
            s[nt][3] = __expf(s[nt][3] - mn1);
            rs0 += s[nt][0] + s[nt][1];
            rs1 += s[nt][2] + s[nt][3];
        }
#pragma unroll
        for (int off = 1; off <= 2; off <<= 1) {
            rs0 += __shfl_xor_sync(0xffffffffu, rs0, off);
            rs1 += __shfl_xor_sync(0xffffffffu, rs1, off);
        }
        l0 = l0 * cr0 + rs0;
        l1 = l1 * cr1 + rs1;
        m0 = mn0;
        m1 = mn1;
#pragma unroll
        for (int dt = 0; dt < 8; dt++) {
            o[dt][0] *= cr0; o[dt][1] *= cr0;
            o[dt][2] *= cr1; o[dt][3] *= cr1;
        }

        // O += P V (split P repack; V^T fragments via direct LDS)
#pragma unroll
        for (int kc = 0; kc < 4; kc++) {
            uint32_t ph[4], pl[4];
            ph[0] = pack_hi(s[2 * kc][0], s[2 * kc][1]);
            ph[1] = pack_hi(s[2 * kc][2], s[2 * kc][3]);
            ph[2] = pack_hi(s[2 * kc + 1][0], s[2 * kc + 1][1]);
            ph[3] = pack_hi(s[2 * kc + 1][2], s[2 * kc + 1][3]);
            pl[0] = pack_lo(s[2 * kc][0], s[2 * kc][1]);
            pl[1] = pack_lo(s[2 * kc][2], s[2 * kc][3]);
            pl[2] = pack_lo(s[2 * kc + 1][0], s[2 * kc + 1][1]);
            pl[3] = pack_lo(s[2 * kc + 1][2], s[2 * kc + 1][3]);
            const int cO = kc * 16 + 2 * tq;
#pragma unroll
            for (int dt = 0; dt < 8; dt++) {
                const int dr = dt * 8 + g;
                uint32_t vh0 = *(const uint32_t*)(Vh + dr * AT_STRIDE + cO);
                uint32_t vh1 = *(const uint32_t*)(Vh + dr * AT_STRIDE + cO + 8);
                uint32_t vl0 = *(const uint32_t*)(Vl + dr * AT_STRIDE + cO);
                uint32_t vl1 = *(const uint32_t*)(Vl + dr * AT_STRIDE + cO + 8);
                mma_bf16(o[dt], ph, vh0, vh1);
                mma_bf16(o[dt], ph, vl0, vl1);
                mma_bf16(o[dt], pl, vh0, vh1);
            }
        }
        __syncthreads();
    }

    // Epilogue
    const float inv0 = 1.0f / l0, inv1 = 1.0f / l1;
    const bool dg0 = (m0 < -5e8f), dg1 = (m1 < -5e8f);
#pragma unroll
    for (int dt = 0; dt < 8; dt++) {
        const int dd = dt * 8 + 2 * tq;
        float o00 = dg0 ? g_vmean[nh * D_DIM + dd] : o[dt][0] * inv0;
        float o01 = dg0 ? g_vmean[nh * D_DIM + dd + 1] : o[dt][1] * inv0;
        float o10 = dg1 ? g_vmean[nh * D_DIM + dd] : o[dt][2] * inv1;
        float o11 = dg1 ? g_vmean[nh * D_DIM + dd + 1] : o[dt][3] * inv1;
        float2* p0 = (float2*)(out + ((size_t)(nb * SEQ + qr0)) * E_DIM + h * D_DIM + dd);
        float2* p1 = (float2*)(out + ((size_t)(nb * SEQ + qr1)) * E_DIM + h * D_DIM + dd);
        *p0 = make_float2(o00, o01);
        *p1 = make_float2(o10, o11);
    }
}

// ---------------------------------------------------------------------------
// Launch
// ---------------------------------------------------------------------------
extern "C" void kernel_launch(void* const* d_in, const int* in_sizes, int n_in,
                              void* d_out, int out_size)
{
    const float* query = (const float*)d_in[0];
    const float* key   = (const float*)d_in[1];
    const float* value = (const float*)d_in[2];
    const int*   pad   = (const int*)d_in[3];
    const float* Wq = (const float*)d_in[5];
    const float* bq = (const float*)d_in[6];
    const float* Wk = (const float*)d_in[7];
    const float* bk = (const float*)d_in[8];
    const float* Wv = (const float*)d_in[9];
    const float* bv = (const float*)d_in[10];
    float* out = (float*)d_out;

    __nv_bfloat16 *xhi, *xlo, *whi, *wlo;
    cudaGetSymbolAddress((void**)&xhi, g_xhi);
    cudaGetSymbolAddress((void**)&xlo, g_xlo);
    cudaGetSymbolAddress((void**)&whi, g_whi);
    cudaGetSymbolAddress((void**)&wlo, g_wlo);

    conv_kernel<<<XSZ / 4 / 256, 256>>>(query, xhi + 0 * (size_t)XSZ, xlo + 0 * (size_t)XSZ, XSZ / 4);
    conv_kernel<<<XSZ / 4 / 256, 256>>>(key,   xhi + 1 * (size_t)XSZ, xlo + 1 * (size_t)XSZ, XSZ / 4);
    conv_kernel<<<XSZ / 4 / 256, 256>>>(value, xhi + 2 * (size_t)XSZ, xlo + 2 * (size_t)XSZ, XSZ / 4);
    conv_kernel<<<WSZ / 4 / 256, 256>>>(Wq, whi + 0 * (size_t)WSZ, wlo + 0 * (size_t)WSZ, WSZ / 4);
    conv_kernel<<<WSZ / 4 / 256, 256>>>(Wk, whi + 1 * (size_t)WSZ, wlo + 1 * (size_t)WSZ, WSZ / 4);
    conv_kernel<<<WSZ / 4 / 256, 256>>>(Wv, whi + 2 * (size_t)WSZ, wlo + 2 * (size_t)WSZ, WSZ / 4);

    dim3 pgrid(E_DIM / 128, (NB * SEQ) / 128, 3);
    proj_mma_kernel<<<pgrid, 256>>>(bq, bk, bv);

    dim3 vgrid(NHTOT, 8);
    vmean_kernel<<<vgrid, 256>>>();

    cudaFuncSetAttribute(attn_mma_kernel, cudaFuncAttributeMaxDynamicSharedMemorySize,
                         AT_SMEM);
    dim3 agrid(SEQ / 128, NHTOT);
    attn_mma_kernel<<<agrid, 256, AT_SMEM>>>(pad, out);
}

// round 8
// speedup vs baseline: 3.2879x; 1.3284x over previous
#include <cuda_runtime.h>
#include <cuda_fp16.h>
#include <cstdint>

#define E_DIM 1024
#define H_DIM 16
#define D_DIM 64
#define SEQ 2048
#define NB 2
#define NHTOT (NB * H_DIM)
#define XSZ (NB * SEQ * E_DIM)
#define WSZ (E_DIM * E_DIM)
#define QKV_SZ (NHTOT * SEQ * D_DIM)

// fp16 split inputs: X as hi+lo (exact), W single
__device__ __half g_xhi[3 * XSZ];
__device__ __half g_xlo[3 * XSZ];
__device__ __half g_wh[3 * WSZ];
// Q: fp16 hi/lo [nh][t][d]; K: single fp16 [nh][t][d]
__device__ __half g_qhi[QKV_SZ], g_qlo[QKV_SZ];
__device__ __half g_kh[QKV_SZ];
// V transposed [nh][d][t], fp16 hi/lo
__device__ __half g_vthi[QKV_SZ], g_vtlo[QKV_SZ];
__device__ float g_vmean[NHTOT * D_DIM];

// ---------------------------------------------------------------------------
// Helpers
// ---------------------------------------------------------------------------
__device__ __forceinline__ void mma_f16(float c[4], const uint32_t a[4],
                                        uint32_t b0, uint32_t b1) {
    asm("mma.sync.aligned.m16n8k16.row.col.f32.f16.f16.f32 "
        "{%0,%1,%2,%3}, {%4,%5,%6,%7}, {%8,%9}, {%0,%1,%2,%3};"
        : "+f"(c[0]), "+f"(c[1]), "+f"(c[2]), "+f"(c[3])
        : "r"(a[0]), "r"(a[1]), "r"(a[2]), "r"(a[3]), "r"(b0), "r"(b1));
}

__device__ __forceinline__ uint32_t smem_u32(const void* p) {
    uint32_t a;
    asm("{ .reg .u64 t; cvta.to.shared.u64 t, %1; cvt.u32.u64 %0, t; }"
        : "=r"(a) : "l"(p));
    return a;
}

__device__ __forceinline__ void cp16(uint32_t dst, const void* src) {
    asm volatile("cp.async.cg.shared.global [%0], [%1], 16;" :: "r"(dst), "l"(src));
}
#define CP_COMMIT() asm volatile("cp.async.commit_group;" ::: "memory")
#define CP_WAIT0() asm volatile("cp.async.wait_group 0;" ::: "memory")
#define CP_WAIT1() asm volatile("cp.async.wait_group 1;" ::: "memory")

__device__ __forceinline__ uint32_t pack_h(float x, float y) {
    __half2 h = __floats2half2_rn(x, y);
    return *reinterpret_cast<uint32_t*>(&h);
}
__device__ __forceinline__ uint32_t pack_l(float x, float y) {
    float hx = __half2float(__float2half_rn(x));
    float hy = __half2float(__float2half_rn(y));
    __half2 l = __floats2half2_rn(x - hx, y - hy);
    return *reinterpret_cast<uint32_t*>(&l);
}

// ---------------------------------------------------------------------------
// Conversions
// ---------------------------------------------------------------------------
__global__ __launch_bounds__(256) void conv_x_kernel(
    const float* __restrict__ x, __half* __restrict__ hi,
    __half* __restrict__ lo, int n4)
{
    int i = blockIdx.x * blockDim.x + threadIdx.x;
    if (i >= n4) return;
    float4 v = ((const float4*)x)[i];
    ((uint32_t*)hi)[2 * i + 0] = pack_h(v.x, v.y);
    ((uint32_t*)hi)[2 * i + 1] = pack_h(v.z, v.w);
    ((uint32_t*)lo)[2 * i + 0] = pack_l(v.x, v.y);
    ((uint32_t*)lo)[2 * i + 1] = pack_l(v.z, v.w);
}

__global__ __launch_bounds__(256) void conv_w_kernel(
    const float* __restrict__ x, __half* __restrict__ hi, int n4)
{
    int i = blockIdx.x * blockDim.x + threadIdx.x;
    if (i >= n4) return;
    float4 v = ((const float4*)x)[i];
    ((uint32_t*)hi)[2 * i + 0] = pack_h(v.x, v.y);
    ((uint32_t*)hi)[2 * i + 1] = pack_h(v.z, v.w);
}

// ---------------------------------------------------------------------------
// Projection GEMM — R6 structure verbatim (static smem, sync loads), fp16
// 2-term: C = (Xh+Xl)*Wh^T + bias.
// ---------------------------------------------------------------------------
__global__ __launch_bounds__(256) void proj_mma_kernel(
    const float* __restrict__ bq, const float* __restrict__ bk,
    const float* __restrict__ bv)
{
    __shared__ __half Ahi[128][40], Alo[128][40];
    __shared__ __half Bh[128][40];

    const int tid = threadIdx.x;
    const int w = tid >> 5;
    const int lane = tid & 31;
    const int g = lane >> 2;
    const int tq = lane & 3;
    const int z = blockIdx.z;
    const int j0 = blockIdx.x * 128;
    const int i0 = blockIdx.y * 128;
    const int mrow = (w & 3) * 32;
    const int ncol = (w >> 2) * 64;

    const __half* xhi = g_xhi + (size_t)z * XSZ;
    const __half* xlo = g_xlo + (size_t)z * XSZ;
    const __half* wh  = g_wh  + (size_t)z * WSZ;
    const float* bias = (z == 0) ? bq : (z == 1) ? bk : bv;

    float c[2][8][4];
#pragma unroll
    for (int mt = 0; mt < 2; mt++)
#pragma unroll
        for (int nt = 0; nt < 8; nt++)
#pragma unroll
            for (int u = 0; u < 4; u++) c[mt][nt][u] = 0.0f;

    for (int k0 = 0; k0 < E_DIM; k0 += 32) {
#pragma unroll
        for (int it = 0; it < 2; it++) {
            const int idx = tid + it * 256;
            const int row = idx >> 2;
            const int seg = (idx & 3) * 8;
            const size_t ga = (size_t)(i0 + row) * E_DIM + k0 + seg;
            const size_t gb = (size_t)(j0 + row) * E_DIM + k0 + seg;
            *(uint4*)&Ahi[row][seg] = *(const uint4*)(xhi + ga);
            *(uint4*)&Alo[row][seg] = *(const uint4*)(xlo + ga);
            *(uint4*)&Bh[row][seg]  = *(const uint4*)(wh + gb);
        }
        __syncthreads();

#pragma unroll
        for (int kc = 0; kc < 32; kc += 16) {
            uint32_t ah[2][4], al[2][4];
#pragma unroll
            for (int mt = 0; mt < 2; mt++) {
                const int r0 = mrow + mt * 16 + g;
                ah[mt][0] = *(const uint32_t*)&Ahi[r0][kc + 2 * tq];
                ah[mt][1] = *(const uint32_t*)&Ahi[r0 + 8][kc + 2 * tq];
                ah[mt][2] = *(const uint32_t*)&Ahi[r0][kc + 2 * tq + 8];
                ah[mt][3] = *(const uint32_t*)&Ahi[r0 + 8][kc + 2 * tq + 8];
                al[mt][0] = *(const uint32_t*)&Alo[r0][kc + 2 * tq];
                al[mt][1] = *(const uint32_t*)&Alo[r0 + 8][kc + 2 * tq];
                al[mt][2] = *(const uint32_t*)&Alo[r0][kc + 2 * tq + 8];
                al[mt][3] = *(const uint32_t*)&Alo[r0 + 8][kc + 2 * tq + 8];
            }
#pragma unroll
            for (int nt = 0; nt < 8; nt++) {
                const int nr = ncol + nt * 8 + g;
                uint32_t b0 = *(const uint32_t*)&Bh[nr][kc + 2 * tq];
                uint32_t b1 = *(const uint32_t*)&Bh[nr][kc + 2 * tq + 8];
#pragma unroll
                for (int mt = 0; mt < 2; mt++) {
                    mma_f16(c[mt][nt], ah[mt], b0, b1);
                    mma_f16(c[mt][nt], al[mt], b0, b1);
                }
            }
        }
        __syncthreads();
    }

    // Epilogue
#pragma unroll
    for (int mt = 0; mt < 2; mt++) {
#pragma unroll
        for (int nt = 0; nt < 8; nt++) {
            const int gj = j0 + ncol + nt * 8 + 2 * tq;
            const int h = gj >> 6;
            const int dd = gj & 63;
            const float b0v = bias[gj], b1v = bias[gj + 1];
            const int r0 = i0 + mrow + mt * 16 + g;
            const int r1 = r0 + 8;
            const float v00 = c[mt][nt][0] + b0v, v01 = c[mt][nt][1] + b1v;
            const float v10 = c[mt][nt][2] + b0v, v11 = c[mt][nt][3] + b1v;
            if (z == 0) {
                const size_t a0 =
                    ((size_t)((r0 >> 11) * H_DIM + h) * SEQ + (r0 & 2047)) * D_DIM + dd;
                const size_t a1 =
                    ((size_t)((r1 >> 11) * H_DIM + h) * SEQ + (r1 & 2047)) * D_DIM + dd;
                *(uint32_t*)(g_qhi + a0) = pack_h(v00, v01);
                *(uint32_t*)(g_qlo + a0) = pack_l(v00, v01);
                *(uint32_t*)(g_qhi + a1) = pack_h(v10, v11);
                *(uint32_t*)(g_qlo + a1) = pack_l(v10, v11);
            } else if (z == 1) {
                const size_t a0 =
                    ((size_t)((r0 >> 11) * H_DIM + h) * SEQ + (r0 & 2047)) * D_DIM + dd;
                const size_t a1 =
                    ((size_t)((r1 >> 11) * H_DIM + h) * SEQ + (r1 & 2047)) * D_DIM + dd;
                *(uint32_t*)(g_kh + a0) = pack_h(v00, v01);
                *(uint32_t*)(g_kh + a1) = pack_h(v10, v11);
            } else {
                const int nh0 = (r0 >> 11) * H_DIM + h;
                const size_t b0 = ((size_t)nh0 * D_DIM + dd) * SEQ;
                const size_t b1 = ((size_t)nh0 * D_DIM + dd + 1) * SEQ;
                const int t0a = r0 & 2047, t1a = r1 & 2047;
                float h00 = __half2float(__float2half_rn(v00));
                float h01 = __half2float(__float2half_rn(v01));
                float h10 = __half2float(__float2half_rn(v10));
                float h11 = __half2float(__float2half_rn(v11));
                g_vthi[b0 + t0a] = __float2half_rn(v00);
                g_vtlo[b0 + t0a] = __float2half_rn(v00 - h00);
                g_vthi[b1 + t0a] = __float2half_rn(v01);
                g_vtlo[b1 + t0a] = __float2half_rn(v01 - h01);
                g_vthi[b0 + t1a] = __float2half_rn(v10);
                g_vtlo[b0 + t1a] = __float2half_rn(v10 - h10);
                g_vthi[b1 + t1a] = __float2half_rn(v11);
                g_vtlo[b1 + t1a] = __float2half_rn(v11 - h11);
            }
        }
    }
}

// ---------------------------------------------------------------------------
// Column mean of V per (n,h); grid (NHTOT, 8), warp per d column.
// ---------------------------------------------------------------------------
__global__ __launch_bounds__(256) void vmean_kernel()
{
    const int nh = blockIdx.x;
    const int w = threadIdx.x >> 5;
    const int lane = threadIdx.x & 31;
    const int dd = blockIdx.y * 8 + w;
    const size_t base = ((size_t)nh * D_DIM + dd) * SEQ;
    float sum = 0.0f;
    for (int cI = 0; cI < SEQ / 32 / 2; cI++) {
        const int off = lane * (SEQ / 32) + cI * 2;
        uint32_t uh = *(const uint32_t*)(g_vthi + base + off);
        uint32_t ul = *(const uint32_t*)(g_vtlo + base + off);
        __half2 h2 = *reinterpret_cast<__half2*>(&uh);
        __half2 l2 = *reinterpret_cast<__half2*>(&ul);
        sum += __half2float(h2.x) + __half2float(l2.x);
        sum += __half2float(h2.y) + __half2float(l2.y);
    }
#pragma unroll
    for (int o = 16; o >= 1; o >>= 1)
        sum += __shfl_xor_sync(0xffffffffu, sum, o);
    if (lane == 0) g_vmean[nh * D_DIM + dd] = sum * (1.0f / (float)SEQ);
}

// ---------------------------------------------------------------------------
// Flash attention — R6 structure (cp.async double buffer, direct LDS), fp16:
// S = (Qh+Ql)*Kh^T (2 MMA), O += Ph*(Vh+Vl) (2 MMA).
// ---------------------------------------------------------------------------
#define AT_STRIDE 72
#define AT_T (64 * AT_STRIDE)                   // elements per tensor tile
#define AT_BUF (3 * AT_T)                       // Kh, Vh, Vl
#define AT_PADS_OFF (2 * AT_BUF * 2)            // byte offset of pads[2][64]
#define AT_SMEM (AT_PADS_OFF + 2 * 64 * 4)      // 55808 bytes

__global__ __launch_bounds__(256) void attn_mma_kernel(
    const int* __restrict__ pad, float* __restrict__ out)
{
    extern __shared__ __half smh[];
    const uint32_t smb = smem_u32(smh);

    const int tid = threadIdx.x;
    const int w = tid >> 5;
    const int lane = tid & 31;
    const int g = lane >> 2;
    const int tq = lane & 3;
    const int qt = (int)(gridDim.x - 1 - blockIdx.x);  // heavy tiles first
    const int nh = blockIdx.y;
    const int nb = nh >> 4;
    const int h = nh & 15;
    const int i0 = qt * 128;
    const int qr0 = i0 + w * 16 + g;
    const int qr1 = qr0 + 8;

    // Q fragments in registers (hi + lo)
    uint32_t qh[4][4], ql[4][4];
    {
        const size_t b0 = ((size_t)nh * SEQ + qr0) * D_DIM;
        const size_t b1 = ((size_t)nh * SEQ + qr1) * D_DIM;
#pragma unroll
        for (int kd = 0; kd < 4; kd++) {
            const int cO = kd * 16 + 2 * tq;
            qh[kd][0] = *(const uint32_t*)(g_qhi + b0 + cO);
            qh[kd][1] = *(const uint32_t*)(g_qhi + b1 + cO);
            qh[kd][2] = *(const uint32_t*)(g_qhi + b0 + cO + 8);
            qh[kd][3] = *(const uint32_t*)(g_qhi + b1 + cO + 8);
            ql[kd][0] = *(const uint32_t*)(g_qlo + b0 + cO);
            ql[kd][1] = *(const uint32_t*)(g_qlo + b1 + cO);
            ql[kd][2] = *(const uint32_t*)(g_qlo + b0 + cO + 8);
            ql[kd][3] = *(const uint32_t*)(g_qlo + b1 + cO + 8);
        }
    }

    auto load_tiles = [&](int buf, int t0) {
        const uint32_t base = smb + buf * (AT_BUF * 2);
        const __half* kh = g_kh + ((size_t)nh * SEQ + t0) * D_DIM;
        const __half* vh = g_vthi + (size_t)nh * D_DIM * SEQ + t0;
        const __half* vl = g_vtlo + (size_t)nh * D_DIM * SEQ + t0;
#pragma unroll
        for (int it = 0; it < 2; it++) {
            const int idx = tid + it * 256;
            const int row = idx >> 3;
            const int seg = (idx & 7) * 8;
            const uint32_t so = (uint32_t)(row * AT_STRIDE + seg) * 2;
            cp16(base + 0 * AT_T * 2 + so, kh + (size_t)row * D_DIM + seg);
            cp16(base + 1 * AT_T * 2 + so, vh + (size_t)row * SEQ + seg);
            cp16(base + 2 * AT_T * 2 + so, vl + (size_t)row * SEQ + seg);
        }
        if (tid < 16)
            cp16(smb + AT_PADS_OFF + buf * 256 + tid * 16,
                 pad + nb * SEQ + t0 + tid * 4);
        CP_COMMIT();
    };

    float o[8][4];
#pragma unroll
    for (int dt = 0; dt < 8; dt++)
#pragma unroll
        for (int u = 0; u < 4; u++) o[dt][u] = 0.0f;
    float m0 = -1e9f, m1 = -1e9f, l0 = 0.0f, l1 = 0.0f;

    const int jmax = 2 * qt + 1;
    load_tiles(0, 0);

    for (int j = 0; j <= jmax; j++) {
        const int t0 = j * 64;
        if (j < jmax) load_tiles((j + 1) & 1, (j + 1) * 64);
        if (j < jmax) { CP_WAIT1(); } else { CP_WAIT0(); }
        __syncthreads();

        const __half* Kh = smh + (j & 1) * AT_BUF + 0 * AT_T;
        const __half* Vh = smh + (j & 1) * AT_BUF + 1 * AT_T;
        const __half* Vl = smh + (j & 1) * AT_BUF + 2 * AT_T;
        const int* pads = (const int*)((const char*)smh + AT_PADS_OFF + (j & 1) * 256);

        // S = (Qh + Ql) * Kh^T
        float s[8][4];
#pragma unroll
        for (int nt = 0; nt < 8; nt++) {
#pragma unroll
            for (int u = 0; u < 4; u++) s[nt][u] = 0.0f;
            const int nr = nt * 8 + g;
#pragma unroll
            for (int kd = 0; kd < 4; kd++) {
                const int cO = kd * 16 + 2 * tq;
                uint32_t b0 = *(const uint32_t*)(Kh + nr * AT_STRIDE + cO);
                uint32_t b1 = *(const uint32_t*)(Kh + nr * AT_STRIDE + cO + 8);
                mma_f16(s[nt], qh[kd], b0, b1);
                mma_f16(s[nt], ql[kd], b0, b1);
            }
        }

        // Scale + mask
#pragma unroll
        for (int nt = 0; nt < 8; nt++) {
            const int c0 = nt * 8 + 2 * tq;
#pragma unroll
            for (int u = 0; u < 4; u++) {
                const int cl = c0 + (u & 1);
                const int kcol = t0 + cl;
                const int qrow = (u < 2) ? qr0 : qr1;
                float v = s[nt][u] * 0.125f;
                if (kcol > qrow || pads[cl] == 0) v = -1e9f;
                s[nt][u] = v;
            }
        }

        // Online softmax
        float mx0 = -1e30f, mx1 = -1e30f;
#pragma unroll
        for (int nt = 0; nt < 8; nt++) {
            mx0 = fmaxf(mx0, fmaxf(s[nt][0], s[nt][1]));
            mx1 = fmaxf(mx1, fmaxf(s[nt][2], s[nt][3]));
        }
#pragma unroll
        for (int off = 1; off <= 2; off <<= 1) {
            mx0 = fmaxf(mx0, __shfl_xor_sync(0xffffffffu, mx0, off));
            mx1 = fmaxf(mx1, __shfl_xor_sync(0xffffffffu, mx1, off));
        }
        const float mn0 = fmaxf(m0, mx0), mn1 = fmaxf(m1, mx1);
        const float cr0 = __expf(m0 - mn0), cr1 = __expf(m1 - mn1);
        float rs0 = 0.0f, rs1 = 0.0f;
#pragma unroll
        for (int nt = 0; nt < 8; nt++) {
            s[nt][0] = __expf(s[nt][0] - mn0);
            s[nt][1] = __expf(s[nt][1] - mn0);
            s[nt][2] = __expf(s[nt][2] - mn1);
            s[nt][3] = __expf(s[nt][3] - mn1);
            rs0 += s[nt][0] + s[nt][1];
            rs1 += s[nt][2] + s[nt][3];
        }
#pragma unroll
        for (int off = 1; off <= 2; off <<= 1) {
            rs0 += __shfl_xor_sync(0xffffffffu, rs0, off);
            rs1 += __shfl_xor_sync(0xffffffffu, rs1, off);
        }
        l0 = l0 * cr0 + rs0;
        l1 = l1 * cr1 + rs1;
        m0 = mn0;
        m1 = mn1;
#pragma unroll
        for (int dt = 0; dt < 8; dt++) {
            o[dt][0] *= cr0; o[dt][1] *= cr0;
            o[dt][2] *= cr1; o[dt][3] *= cr1;
        }

        // O += P * (Vh + Vl), P single fp16
#pragma unroll
        for (int kc = 0; kc < 4; kc++) {
            uint32_t ph[4];
            ph[0] = pack_h(s[2 * kc][0], s[2 * kc][1]);
            ph[1] = pack_h(s[2 * kc][2], s[2 * kc][3]);
            ph[2] = pack_h(s[2 * kc + 1][0], s[2 * kc + 1][1]);
            ph[3] = pack_h(s[2 * kc + 1][2], s[2 * kc + 1][3]);
            const int cO = kc * 16 + 2 * tq;
#pragma unroll
            for (int dt = 0; dt < 8; dt++) {
                const int dr = dt * 8 + g;
                uint32_t vh0 = *(const uint32_t*)(Vh + dr * AT_STRIDE + cO);
                uint32_t vh1 = *(const uint32_t*)(Vh + dr * AT_STRIDE + cO + 8);
                uint32_t vl0 = *(const uint32_t*)(Vl + dr * AT_STRIDE + cO);
                uint32_t vl1 = *(const uint32_t*)(Vl + dr * AT_STRIDE + cO + 8);
                mma_f16(o[dt], ph, vh0, vh1);
                mma_f16(o[dt], ph, vl0, vl1);
            }
        }
        __syncthreads();
    }

    // Epilogue
    const float inv0 = 1.0f / l0, inv1 = 1.0f / l1;
    const bool dg0 = (m0 < -5e8f), dg1 = (m1 < -5e8f);
#pragma unroll
    for (int dt = 0; dt < 8; dt++) {
        const int dd = dt * 8 + 2 * tq;
        float o00 = dg0 ? g_vmean[nh * D_DIM + dd] : o[dt][0] * inv0;
        float o01 = dg0 ? g_vmean[nh * D_DIM + dd + 1] : o[dt][1] * inv0;
        float o10 = dg1 ? g_vmean[nh * D_DIM + dd] : o[dt][2] * inv1;
        float o11 = dg1 ? g_vmean[nh * D_DIM + dd + 1] : o[dt][3] * inv1;
        float2* p0 = (float2*)(out + ((size_t)(nb * SEQ + qr0)) * E_DIM + h * D_DIM + dd);
        float2* p1 = (float2*)(out + ((size_t)(nb * SEQ + qr1)) * E_DIM + h * D_DIM + dd);
        *p0 = make_float2(o00, o01);
        *p1 = make_float2(o10, o11);
    }
}

// ---------------------------------------------------------------------------
// Launch
// ---------------------------------------------------------------------------
extern "C" void kernel_launch(void* const* d_in, const int* in_sizes, int n_in,
                              void* d_out, int out_size)
{
    const float* query = (const float*)d_in[0];
    const float* key   = (const float*)d_in[1];
    const float* value = (const float*)d_in[2];
    const int*   pad   = (const int*)d_in[3];
    const float* Wq = (const float*)d_in[5];
    const float* bq = (const float*)d_in[6];
    const float* Wk = (const float*)d_in[7];
    const float* bk = (const float*)d_in[8];
    const float* Wv = (const float*)d_in[9];
    const float* bv = (const float*)d_in[10];
    float* out = (float*)d_out;

    __half *xhi, *xlo, *wh;
    cudaGetSymbolAddress((void**)&xhi, g_xhi);
    cudaGetSymbolAddress((void**)&xlo, g_xlo);
    cudaGetSymbolAddress((void**)&wh, g_wh);

    conv_x_kernel<<<XSZ / 4 / 256, 256>>>(query, xhi + 0 * (size_t)XSZ, xlo + 0 * (size_t)XSZ, XSZ / 4);
    conv_x_kernel<<<XSZ / 4 / 256, 256>>>(key,   xhi + 1 * (size_t)XSZ, xlo + 1 * (size_t)XSZ, XSZ / 4);
    conv_x_kernel<<<XSZ / 4 / 256, 256>>>(value, xhi + 2 * (size_t)XSZ, xlo + 2 * (size_t)XSZ, XSZ / 4);
    conv_w_kernel<<<WSZ / 4 / 256, 256>>>(Wq, wh + 0 * (size_t)WSZ, WSZ / 4);
    conv_w_kernel<<<WSZ / 4 / 256, 256>>>(Wk, wh + 1 * (size_t)WSZ, WSZ / 4);
    conv_w_kernel<<<WSZ / 4 / 256, 256>>>(Wv, wh + 2 * (size_t)WSZ, WSZ / 4);

    dim3 pgrid(E_DIM / 128, (NB * SEQ) / 128, 3);
    proj_mma_kernel<<<pgrid, 256>>>(bq, bk, bv);

    dim3 vgrid(NHTOT, 8);
    vmean_kernel<<<vgrid, 256>>>();

    cudaFuncSetAttribute(attn_mma_kernel, cudaFuncAttributeMaxDynamicSharedMemorySize,
                         AT_SMEM);
    dim3 agrid(SEQ / 128, NHTOT);
    attn_mma_kernel<<<agrid, 256, AT_SMEM>>>(pad, out);
}

// round 9
// speedup vs baseline: 4.7989x; 1.4596x over previous
#include <cuda_runtime.h>
#include <cuda_fp16.h>
#include <cstdint>

#define E_DIM 1024
#define H_DIM 16
#define D_DIM 64
#define SEQ 2048
#define NB 2
#define NHTOT (NB * H_DIM)
#define XSZ (NB * SEQ * E_DIM)
#define WSZ (E_DIM * E_DIM)
#define QKV_SZ (NHTOT * SEQ * D_DIM)

// Single fp16 inputs
__device__ __half g_xh[3 * XSZ];
__device__ __half g_wh[3 * WSZ];
// Q/K single fp16 [nh][t][d]; V transposed single fp16 [nh][d][t]
__device__ __half g_qh[QKV_SZ];
__device__ __half g_kh[QKV_SZ];
__device__ __half g_vth[QKV_SZ];
__device__ float g_vmean[NHTOT * D_DIM];

// ---------------------------------------------------------------------------
// Helpers
// ---------------------------------------------------------------------------
__device__ __forceinline__ void mma_f16(float c[4], const uint32_t a[4],
                                        uint32_t b0, uint32_t b1) {
    asm("mma.sync.aligned.m16n8k16.row.col.f32.f16.f16.f32 "
        "{%0,%1,%2,%3}, {%4,%5,%6,%7}, {%8,%9}, {%0,%1,%2,%3};"
        : "+f"(c[0]), "+f"(c[1]), "+f"(c[2]), "+f"(c[3])
        : "r"(a[0]), "r"(a[1]), "r"(a[2]), "r"(a[3]), "r"(b0), "r"(b1));
}

__device__ __forceinline__ uint32_t smem_u32(const void* p) {
    uint32_t a;
    asm("{ .reg .u64 t; cvta.to.shared.u64 t, %1; cvt.u32.u64 %0, t; }"
        : "=r"(a) : "l"(p));
    return a;
}

__device__ __forceinline__ void cp16(uint32_t dst, const void* src) {
    asm volatile("cp.async.cg.shared.global [%0], [%1], 16;" :: "r"(dst), "l"(src));
}
#define CP_COMMIT() asm volatile("cp.async.commit_group;" ::: "memory")
#define CP_WAIT0() asm volatile("cp.async.wait_group 0;" ::: "memory")
#define CP_WAIT1() asm volatile("cp.async.wait_group 1;" ::: "memory")

__device__ __forceinline__ uint32_t pack_h(float x, float y) {
    __half2 h = __floats2half2_rn(x, y);
    return *reinterpret_cast<uint32_t*>(&h);
}

// ---------------------------------------------------------------------------
// Conversion: fp32 -> fp16
// ---------------------------------------------------------------------------
__global__ __launch_bounds__(256) void conv_kernel(
    const float* __restrict__ x, __half* __restrict__ hi, int n4)
{
    int i = blockIdx.x * blockDim.x + threadIdx.x;
    if (i >= n4) return;
    float4 v = ((const float4*)x)[i];
    ((uint32_t*)hi)[2 * i + 0] = pack_h(v.x, v.y);
    ((uint32_t*)hi)[2 * i + 1] = pack_h(v.z, v.w);
}

// ---------------------------------------------------------------------------
// Projection GEMM — R6-proven structure (static smem, sync loads), single
// fp16: C = Xh*Wh^T + bias. 1 MMA per fragment pair.
// ---------------------------------------------------------------------------
__global__ __launch_bounds__(256) void proj_mma_kernel(
    const float* __restrict__ bq, const float* __restrict__ bk,
    const float* __restrict__ bv)
{
    __shared__ __half Ah[128][40];
    __shared__ __half Bh[128][40];

    const int tid = threadIdx.x;
    const int w = tid >> 5;
    const int lane = tid & 31;
    const int g = lane >> 2;
    const int tq = lane & 3;
    const int z = blockIdx.z;
    const int j0 = blockIdx.x * 128;
    const int i0 = blockIdx.y * 128;
    const int mrow = (w & 3) * 32;
    const int ncol = (w >> 2) * 64;

    const __half* xh = g_xh + (size_t)z * XSZ;
    const __half* wh = g_wh + (size_t)z * WSZ;
    const float* bias = (z == 0) ? bq : (z == 1) ? bk : bv;

    float c[2][8][4];
#pragma unroll
    for (int mt = 0; mt < 2; mt++)
#pragma unroll
        for (int nt = 0; nt < 8; nt++)
#pragma unroll
            for (int u = 0; u < 4; u++) c[mt][nt][u] = 0.0f;

    for (int k0 = 0; k0 < E_DIM; k0 += 32) {
#pragma unroll
        for (int it = 0; it < 2; it++) {
            const int idx = tid + it * 256;
            const int row = idx >> 2;
            const int seg = (idx & 3) * 8;
            const size_t ga = (size_t)(i0 + row) * E_DIM + k0 + seg;
            const size_t gb = (size_t)(j0 + row) * E_DIM + k0 + seg;
            *(uint4*)&Ah[row][seg] = *(const uint4*)(xh + ga);
            *(uint4*)&Bh[row][seg] = *(const uint4*)(wh + gb);
        }
        __syncthreads();

#pragma unroll
        for (int kc = 0; kc < 32; kc += 16) {
            uint32_t a[2][4];
#pragma unroll
            for (int mt = 0; mt < 2; mt++) {
                const int r0 = mrow + mt * 16 + g;
                a[mt][0] = *(const uint32_t*)&Ah[r0][kc + 2 * tq];
                a[mt][1] = *(const uint32_t*)&Ah[r0 + 8][kc + 2 * tq];
                a[mt][2] = *(const uint32_t*)&Ah[r0][kc + 2 * tq + 8];
                a[mt][3] = *(const uint32_t*)&Ah[r0 + 8][kc + 2 * tq + 8];
            }
#pragma unroll
            for (int nt = 0; nt < 8; nt++) {
                const int nr = ncol + nt * 8 + g;
                uint32_t b0 = *(const uint32_t*)&Bh[nr][kc + 2 * tq];
                uint32_t b1 = *(const uint32_t*)&Bh[nr][kc + 2 * tq + 8];
#pragma unroll
                for (int mt = 0; mt < 2; mt++)
                    mma_f16(c[mt][nt], a[mt], b0, b1);
            }
        }
        __syncthreads();
    }

    // Epilogue
#pragma unroll
    for (int mt = 0; mt < 2; mt++) {
#pragma unroll
        for (int nt = 0; nt < 8; nt++) {
            const int gj = j0 + ncol + nt * 8 + 2 * tq;
            const int h = gj >> 6;
            const int dd = gj & 63;
            const float b0v = bias[gj], b1v = bias[gj + 1];
            const int r0 = i0 + mrow + mt * 16 + g;
            const int r1 = r0 + 8;
            const float v00 = c[mt][nt][0] + b0v, v01 = c[mt][nt][1] + b1v;
            const float v10 = c[mt][nt][2] + b0v, v11 = c[mt][nt][3] + b1v;
            if (z < 2) {
                __half* dst = (z == 0) ? g_qh : g_kh;
                const size_t a0 =
                    ((size_t)((r0 >> 11) * H_DIM + h) * SEQ + (r0 & 2047)) * D_DIM + dd;
                const size_t a1 =
                    ((size_t)((r1 >> 11) * H_DIM + h) * SEQ + (r1 & 2047)) * D_DIM + dd;
                *(uint32_t*)(dst + a0) = pack_h(v00, v01);
                *(uint32_t*)(dst + a1) = pack_h(v10, v11);
            } else {
                const int nh0 = (r0 >> 11) * H_DIM + h;
                const size_t b0 = ((size_t)nh0 * D_DIM + dd) * SEQ;
                const size_t b1 = ((size_t)nh0 * D_DIM + dd + 1) * SEQ;
                const int t0a = r0 & 2047, t1a = r1 & 2047;
                g_vth[b0 + t0a] = __float2half_rn(v00);
                g_vth[b1 + t0a] = __float2half_rn(v01);
                g_vth[b0 + t1a] = __float2half_rn(v10);
                g_vth[b1 + t1a] = __float2half_rn(v11);
            }
        }
    }
}

// ---------------------------------------------------------------------------
// Column mean of V per (n,h); grid (NHTOT, 8), warp per d column.
// ---------------------------------------------------------------------------
__global__ __launch_bounds__(256) void vmean_kernel()
{
    const int nh = blockIdx.x;
    const int w = threadIdx.x >> 5;
    const int lane = threadIdx.x & 31;
    const int dd = blockIdx.y * 8 + w;
    const size_t base = ((size_t)nh * D_DIM + dd) * SEQ;
    float sum = 0.0f;
    for (int cI = 0; cI < SEQ / 32 / 2; cI++) {
        const int off = lane * (SEQ / 32) + cI * 2;
        uint32_t uh = *(const uint32_t*)(g_vth + base + off);
        __half2 h2 = *reinterpret_cast<__half2*>(&uh);
        sum += __half2float(h2.x) + __half2float(h2.y);
    }
#pragma unroll
    for (int o = 16; o >= 1; o >>= 1)
        sum += __shfl_xor_sync(0xffffffffu, sum, o);
    if (lane == 0) g_vmean[nh * D_DIM + dd] = sum * (1.0f / (float)SEQ);
}

// ---------------------------------------------------------------------------
// Flash attention — R6/R8-proven structure (cp.async double buffer, direct
// LDS), single fp16: S = Qh*Kh^T (1 MMA), O += Ph*Vh (1 MMA).
// ---------------------------------------------------------------------------
#define AT_STRIDE 72
#define AT_T (64 * AT_STRIDE)                   // elements per tensor tile
#define AT_BUF (2 * AT_T)                       // Kh, Vh
#define AT_PADS_OFF (2 * AT_BUF * 2)            // byte offset of pads[2][64]
#define AT_SMEM (AT_PADS_OFF + 2 * 64 * 4)      // 37376 bytes

__global__ __launch_bounds__(256) void attn_mma_kernel(
    const int* __restrict__ pad, float* __restrict__ out)
{
    extern __shared__ __half smh[];
    const uint32_t smb = smem_u32(smh);

    const int tid = threadIdx.x;
    const int w = tid >> 5;
    const int lane = tid & 31;
    const int g = lane >> 2;
    const int tq = lane & 3;
    const int qt = (int)(gridDim.x - 1 - blockIdx.x);  // heavy tiles first
    const int nh = blockIdx.y;
    const int nb = nh >> 4;
    const int h = nh & 15;
    const int i0 = qt * 128;
    const int qr0 = i0 + w * 16 + g;
    const int qr1 = qr0 + 8;

    // Q fragments in registers
    uint32_t qf[4][4];
    {
        const size_t b0 = ((size_t)nh * SEQ + qr0) * D_DIM;
        const size_t b1 = ((size_t)nh * SEQ + qr1) * D_DIM;
#pragma unroll
        for (int kd = 0; kd < 4; kd++) {
            const int cO = kd * 16 + 2 * tq;
            qf[kd][0] = *(const uint32_t*)(g_qh + b0 + cO);
            qf[kd][1] = *(const uint32_t*)(g_qh + b1 + cO);
            qf[kd][2] = *(const uint32_t*)(g_qh + b0 + cO + 8);
            qf[kd][3] = *(const uint32_t*)(g_qh + b1 + cO + 8);
        }
    }

    auto load_tiles = [&](int buf, int t0) {
        const uint32_t base = smb + buf * (AT_BUF * 2);
        const __half* kh = g_kh + ((size_t)nh * SEQ + t0) * D_DIM;
        const __half* vh = g_vth + (size_t)nh * D_DIM * SEQ + t0;
#pragma unroll
        for (int it = 0; it < 2; it++) {
            const int idx = tid + it * 256;
            const int row = idx >> 3;
            const int seg = (idx & 7) * 8;
            const uint32_t so = (uint32_t)(row * AT_STRIDE + seg) * 2;
            cp16(base + 0 * AT_T * 2 + so, kh + (size_t)row * D_DIM + seg);
            cp16(base + 1 * AT_T * 2 + so, vh + (size_t)row * SEQ + seg);
        }
        if (tid < 16)
            cp16(smb + AT_PADS_OFF + buf * 256 + tid * 16,
                 pad + nb * SEQ + t0 + tid * 4);
        CP_COMMIT();
    };

    float o[8][4];
#pragma unroll
    for (int dt = 0; dt < 8; dt++)
#pragma unroll
        for (int u = 0; u < 4; u++) o[dt][u] = 0.0f;
    float m0 = -1e9f, m1 = -1e9f, l0 = 0.0f, l1 = 0.0f;

    const int jmax = 2 * qt + 1;
    load_tiles(0, 0);

    for (int j = 0; j <= jmax; j++) {
        const int t0 = j * 64;
        if (j < jmax) load_tiles((j + 1) & 1, (j + 1) * 64);
        if (j < jmax) { CP_WAIT1(); } else { CP_WAIT0(); }
        __syncthreads();

        const __half* Kh = smh + (j & 1) * AT_BUF + 0 * AT_T;
        const __half* Vh = smh + (j & 1) * AT_BUF + 1 * AT_T;
        const int* pads = (const int*)((const char*)smh + AT_PADS_OFF + (j & 1) * 256);

        // S = Qh * Kh^T
        float s[8][4];
#pragma unroll
        for (int nt = 0; nt < 8; nt++) {
#pragma unroll
            for (int u = 0; u < 4; u++) s[nt][u] = 0.0f;
            const int nr = nt * 8 + g;
#pragma unroll
            for (int kd = 0; kd < 4; kd++) {
                const int cO = kd * 16 + 2 * tq;
                uint32_t b0 = *(const uint32_t*)(Kh + nr * AT_STRIDE + cO);
                uint32_t b1 = *(const uint32_t*)(Kh + nr * AT_STRIDE + cO + 8);
                mma_f16(s[nt], qf[kd], b0, b1);
            }
        }

        // Scale + mask
#pragma unroll
        for (int nt = 0; nt < 8; nt++) {
            const int c0 = nt * 8 + 2 * tq;
#pragma unroll
            for (int u = 0; u < 4; u++) {
                const int cl = c0 + (u & 1);
                const int kcol = t0 + cl;
                const int qrow = (u < 2) ? qr0 : qr1;
                float v = s[nt][u] * 0.125f;
                if (kcol > qrow || pads[cl] == 0) v = -1e9f;
                s[nt][u] = v;
            }
        }

        // Online softmax
        float mx0 = -1e30f, mx1 = -1e30f;
#pragma unroll
        for (int nt = 0; nt < 8; nt++) {
            mx0 = fmaxf(mx0, fmaxf(s[nt][0], s[nt][1]));
            mx1 = fmaxf(mx1, fmaxf(s[nt][2], s[nt][3]));
        }
#pragma unroll
        for (int off = 1; off <= 2; off <<= 1) {
            mx0 = fmaxf(mx0, __shfl_xor_sync(0xffffffffu, mx0, off));
            mx1 = fmaxf(mx1, __shfl_xor_sync(0xffffffffu, mx1, off));
        }
        const float mn0 = fmaxf(m0, mx0), mn1 = fmaxf(m1, mx1);
        const float cr0 = __expf(m0 - mn0), cr1 = __expf(m1 - mn1);
        float rs0 = 0.0f, rs1 = 0.0f;
#pragma unroll
        for (int nt = 0; nt < 8; nt++) {
            s[nt][0] = __expf(s[nt][0] - mn0);
            s[nt][1] = __expf(s[nt][1] - mn0);
            s[nt][2] = __expf(s[nt][2] - mn1);
            s[nt][3] = __expf(s[nt][3] - mn1);
            rs0 += s[nt][0] + s[nt][1];
            rs1 += s[nt][2] + s[nt][3];
        }
#pragma unroll
        for (int off = 1; off <= 2; off <<= 1) {
            rs0 += __shfl_xor_sync(0xffffffffu, rs0, off);
            rs1 += __shfl_xor_sync(0xffffffffu, rs1, off);
        }
        l0 = l0 * cr0 + rs0;
        l1 = l1 * cr1 + rs1;
        m0 = mn0;
        m1 = mn1;
#pragma unroll
        for (int dt = 0; dt < 8; dt++) {
            o[dt][0] *= cr0; o[dt][1] *= cr0;
            o[dt][2] *= cr1; o[dt][3] *= cr1;
        }

        // O += P * Vh
#pragma unroll
        for (int kc = 0; kc < 4; kc++) {
            uint32_t ph[4];
            ph[0] = pack_h(s[2 * kc][0], s[2 * kc][1]);
            ph[1] = pack_h(s[2 * kc][2], s[2 * kc][3]);
            ph[2] = pack_h(s[2 * kc + 1][0], s[2 * kc + 1][1]);
            ph[3] = pack_h(s[2 * kc + 1][2], s[2 * kc + 1][3]);
            const int cO = kc * 16 + 2 * tq;
#pragma unroll
            for (int dt = 0; dt < 8; dt++) {
                const int dr = dt * 8 + g;
                uint32_t vh0 = *(const uint32_t*)(Vh + dr * AT_STRIDE + cO);
                uint32_t vh1 = *(const uint32_t*)(Vh + dr * AT_STRIDE + cO + 8);
                mma_f16(o[dt], ph, vh0, vh1);
            }
        }
        __syncthreads();
    }

    // Epilogue
    const float inv0 = 1.0f / l0, inv1 = 1.0f / l1;
    const bool dg0 = (m0 < -5e8f), dg1 = (m1 < -5e8f);
#pragma unroll
    for (int dt = 0; dt < 8; dt++) {
        const int dd = dt * 8 + 2 * tq;
        float o00 = dg0 ? g_vmean[nh * D_DIM + dd] : o[dt][0] * inv0;
        float o01 = dg0 ? g_vmean[nh * D_DIM + dd + 1] : o[dt][1] * inv0;
        float o10 = dg1 ? g_vmean[nh * D_DIM + dd] : o[dt][2] * inv1;
        float o11 = dg1 ? g_vmean[nh * D_DIM + dd + 1] : o[dt][3] * inv1;
        float2* p0 = (float2*)(out + ((size_t)(nb * SEQ + qr0)) * E_DIM + h * D_DIM + dd);
        float2* p1 = (float2*)(out + ((size_t)(nb * SEQ + qr1)) * E_DIM + h * D_DIM + dd);
        *p0 = make_float2(o00, o01);
        *p1 = make_float2(o10, o11);
    }
}

// ---------------------------------------------------------------------------
// Launch
// ---------------------------------------------------------------------------
extern "C" void kernel_launch(void* const* d_in, const int* in_sizes, int n_in,
                              void* d_out, int out_size)
{
    const float* query = (const float*)d_in[0];
    const float* key   = (const float*)d_in[1];
    const float* value = (const float*)d_in[2];
    const int*   pad   = (const int*)d_in[3];
    const float* Wq = (const float*)d_in[5];
    const float* bq = (const float*)d_in[6];
    const float* Wk = (const float*)d_in[7];
    const float* bk = (const float*)d_in[8];
    const float* Wv = (const float*)d_in[9];
    const float* bv = (const float*)d_in[10];
    float* out = (float*)d_out;

    __half *xh, *wh;
    cudaGetSymbolAddress((void**)&xh, g_xh);
    cudaGetSymbolAddress((void**)&wh, g_wh);

    conv_kernel<<<XSZ / 4 / 256, 256>>>(query, xh + 0 * (size_t)XSZ, XSZ / 4);
    conv_kernel<<<XSZ / 4 / 256, 256>>>(key,   xh + 1 * (size_t)XSZ, XSZ / 4);
    conv_kernel<<<XSZ / 4 / 256, 256>>>(value, xh + 2 * (size_t)XSZ, XSZ / 4);
    conv_kernel<<<WSZ / 4 / 256, 256>>>(Wq, wh + 0 * (size_t)WSZ, WSZ / 4);
    conv_kernel<<<WSZ / 4 / 256, 256>>>(Wk, wh + 1 * (size_t)WSZ, WSZ / 4);
    conv_kernel<<<WSZ / 4 / 256, 256>>>(Wv, wh + 2 * (size_t)WSZ, WSZ / 4);

    dim3 pgrid(E_DIM / 128, (NB * SEQ) / 128, 3);
    proj_mma_kernel<<<pgrid, 256>>>(bq, bk, bv);

    dim3 vgrid(NHTOT, 8);
    vmean_kernel<<<vgrid, 256>>>();

    cudaFuncSetAttribute(attn_mma_kernel, cudaFuncAttributeMaxDynamicSharedMemorySize,
                         AT_SMEM);
    dim3 agrid(SEQ / 128, NHTOT);
    attn_mma_kernel<<<agrid, 256, AT_SMEM>>>(pad, out);
}

// round 11
// speedup vs baseline: 4.9637x; 1.0343x over previous
#include <cuda_runtime.h>
#include <cuda_fp16.h>
#include <cstdint>

#define E_DIM 1024
#define H_DIM 16
#define D_DIM 64
#define SEQ 2048
#define NB 2
#define NHTOT (NB * H_DIM)
#define XSZ (NB * SEQ * E_DIM)
#define WSZ (E_DIM * E_DIM)
#define QKV_SZ (NHTOT * SEQ * D_DIM)

// Single fp16 inputs
__device__ __half g_xh[3 * XSZ];
__device__ __half g_wh[3 * WSZ];
// Q/K single fp16 [nh][t][d]; V transposed single fp16 [nh][d][t]
__device__ __half g_qh[QKV_SZ];
__device__ __half g_kh[QKV_SZ];
__device__ __half g_vth[QKV_SZ];
__device__ float g_vmean[NHTOT * D_DIM];

// ---------------------------------------------------------------------------
// Helpers
// ---------------------------------------------------------------------------
__device__ __forceinline__ void mma_f16(float c[4], const uint32_t a[4],
                                        uint32_t b0, uint32_t b1) {
    asm("mma.sync.aligned.m16n8k16.row.col.f32.f16.f16.f32 "
        "{%0,%1,%2,%3}, {%4,%5,%6,%7}, {%8,%9}, {%0,%1,%2,%3};"
        : "+f"(c[0]), "+f"(c[1]), "+f"(c[2]), "+f"(c[3])
        : "r"(a[0]), "r"(a[1]), "r"(a[2]), "r"(a[3]), "r"(b0), "r"(b1));
}

__device__ __forceinline__ uint32_t smem_u32(const void* p) {
    uint32_t a;
    asm("{ .reg .u64 t; cvta.to.shared.u64 t, %1; cvt.u32.u64 %0, t; }"
        : "=r"(a) : "l"(p));
    return a;
}

__device__ __forceinline__ void cp16(uint32_t dst, const void* src) {
    asm volatile("cp.async.cg.shared.global [%0], [%1], 16;" :: "r"(dst), "l"(src));
}
#define CP_COMMIT() asm volatile("cp.async.commit_group;" ::: "memory")
#define CP_WAIT0() asm volatile("cp.async.wait_group 0;" ::: "memory")
#define CP_WAIT1() asm volatile("cp.async.wait_group 1;" ::: "memory")

__device__ __forceinline__ uint32_t pack_h(float x, float y) {
    __half2 h = __floats2half2_rn(x, y);
    return *reinterpret_cast<uint32_t*>(&h);
}

// ---------------------------------------------------------------------------
// Fused conversion: all six fp32 -> fp16 tensors in ONE launch.
// Blocks [0, 3*XB): X tensors; [3*XB, 3*XB + 3*WB): W tensors.
// Values computed are bit-identical to the R9 per-tensor conv kernels.
// ---------------------------------------------------------------------------
#define XB (XSZ / 4 / 256)   // 4096 blocks per X tensor
#define WB (WSZ / 4 / 256)   // 1024 blocks per W tensor

__global__ __launch_bounds__(256) void conv_all_kernel(
    const float* __restrict__ q, const float* __restrict__ k,
    const float* __restrict__ v, const float* __restrict__ wq,
    const float* __restrict__ wk, const float* __restrict__ wv)
{
    const int b = blockIdx.x;
    const float* src;
    __half* dst;
    int local;
    if (b < 3 * XB) {
        const int z = b / XB;
        local = b - z * XB;
        src = (z == 0) ? q : (z == 1) ? k : v;
        dst = g_xh + (size_t)z * XSZ;
    } else {
        const int bb = b - 3 * XB;
        const int z = bb / WB;
        local = bb - z * WB;
        src = (z == 0) ? wq : (z == 1) ? wk : wv;
        dst = g_wh + (size_t)z * WSZ;
    }
    const int i = local * 256 + threadIdx.x;
    float4 val = ((const float4*)src)[i];
    ((uint32_t*)dst)[2 * i + 0] = pack_h(val.x, val.y);
    ((uint32_t*)dst)[2 * i + 1] = pack_h(val.z, val.w);
}

// ---------------------------------------------------------------------------
// Projection GEMM — R9 kernel VERBATIM (static smem, sync loads, single fp16,
// NO pipelining — pipelined variants quarantined after R5/R7/R10 failures).
// ---------------------------------------------------------------------------
__global__ __launch_bounds__(256) void proj_mma_kernel(
    const float* __restrict__ bq, const float* __restrict__ bk,
    const float* __restrict__ bv)
{
    __shared__ __half Ah[128][40];
    __shared__ __half Bh[128][40];

    const int tid = threadIdx.x;
    const int w = tid >> 5;
    const int lane = tid & 31;
    const int g = lane >> 2;
    const int tq = lane & 3;
    const int z = blockIdx.z;
    const int j0 = blockIdx.x * 128;
    const int i0 = blockIdx.y * 128;
    const int mrow = (w & 3) * 32;
    const int ncol = (w >> 2) * 64;

    const __half* xh = g_xh + (size_t)z * XSZ;
    const __half* wh = g_wh + (size_t)z * WSZ;
    const float* bias = (z == 0) ? bq : (z == 1) ? bk : bv;

    float c[2][8][4];
#pragma unroll
    for (int mt = 0; mt < 2; mt++)
#pragma unroll
        for (int nt = 0; nt < 8; nt++)
#pragma unroll
            for (int u = 0; u < 4; u++) c[mt][nt][u] = 0.0f;

    for (int k0 = 0; k0 < E_DIM; k0 += 32) {
#pragma unroll
        for (int it = 0; it < 2; it++) {
            const int idx = tid + it * 256;
            const int row = idx >> 2;
            const int seg = (idx & 3) * 8;
            const size_t ga = (size_t)(i0 + row) * E_DIM + k0 + seg;
            const size_t gb = (size_t)(j0 + row) * E_DIM + k0 + seg;
            *(uint4*)&Ah[row][seg] = *(const uint4*)(xh + ga);
            *(uint4*)&Bh[row][seg] = *(const uint4*)(wh + gb);
        }
        __syncthreads();

#pragma unroll
        for (int kc = 0; kc < 32; kc += 16) {
            uint32_t a[2][4];
#pragma unroll
            for (int mt = 0; mt < 2; mt++) {
                const int r0 = mrow + mt * 16 + g;
                a[mt][0] = *(const uint32_t*)&Ah[r0][kc + 2 * tq];
                a[mt][1] = *(const uint32_t*)&Ah[r0 + 8][kc + 2 * tq];
                a[mt][2] = *(const uint32_t*)&Ah[r0][kc + 2 * tq + 8];
                a[mt][3] = *(const uint32_t*)&Ah[r0 + 8][kc + 2 * tq + 8];
            }
#pragma unroll
            for (int nt = 0; nt < 8; nt++) {
                const int nr = ncol + nt * 8 + g;
                uint32_t b0 = *(const uint32_t*)&Bh[nr][kc + 2 * tq];
                uint32_t b1 = *(const uint32_t*)&Bh[nr][kc + 2 * tq + 8];
#pragma unroll
                for (int mt = 0; mt < 2; mt++)
                    mma_f16(c[mt][nt], a[mt], b0, b1);
            }
        }
        __syncthreads();
    }

    // Epilogue
#pragma unroll
    for (int mt = 0; mt < 2; mt++) {
#pragma unroll
        for (int nt = 0; nt < 8; nt++) {
            const int gj = j0 + ncol + nt * 8 + 2 * tq;
            const int h = gj >> 6;
            const int dd = gj & 63;
            const float b0v = bias[gj], b1v = bias[gj + 1];
            const int r0 = i0 + mrow + mt * 16 + g;
            const int r1 = r0 + 8;
            const float v00 = c[mt][nt][0] + b0v, v01 = c[mt][nt][1] + b1v;
            const float v10 = c[mt][nt][2] + b0v, v11 = c[mt][nt][3] + b1v;
            if (z < 2) {
                __half* dst = (z == 0) ? g_qh : g_kh;
                const size_t a0 =
                    ((size_t)((r0 >> 11) * H_DIM + h) * SEQ + (r0 & 2047)) * D_DIM + dd;
                const size_t a1 =
                    ((size_t)((r1 >> 11) * H_DIM + h) * SEQ + (r1 & 2047)) * D_DIM + dd;
                *(uint32_t*)(dst + a0) = pack_h(v00, v01);
                *(uint32_t*)(dst + a1) = pack_h(v10, v11);
            } else {
                const int nh0 = (r0 >> 11) * H_DIM + h;
                const size_t b0 = ((size_t)nh0 * D_DIM + dd) * SEQ;
                const size_t b1 = ((size_t)nh0 * D_DIM + dd + 1) * SEQ;
                const int t0a = r0 & 2047, t1a = r1 & 2047;
                g_vth[b0 + t0a] = __float2half_rn(v00);
                g_vth[b1 + t0a] = __float2half_rn(v01);
                g_vth[b0 + t1a] = __float2half_rn(v10);
                g_vth[b1 + t1a] = __float2half_rn(v11);
            }
        }
    }
}

// ---------------------------------------------------------------------------
// Column mean of V per (n,h); grid (NHTOT, 8), warp per d column.
// ---------------------------------------------------------------------------
__global__ __launch_bounds__(256) void vmean_kernel()
{
    const int nh = blockIdx.x;
    const int w = threadIdx.x >> 5;
    const int lane = threadIdx.x & 31;
    const int dd = blockIdx.y * 8 + w;
    const size_t base = ((size_t)nh * D_DIM + dd) * SEQ;
    float sum = 0.0f;
    for (int cI = 0; cI < SEQ / 32 / 2; cI++) {
        const int off = lane * (SEQ / 32) + cI * 2;
        uint32_t uh = *(const uint32_t*)(g_vth + base + off);
        __half2 h2 = *reinterpret_cast<__half2*>(&uh);
        sum += __half2float(h2.x) + __half2float(h2.y);
    }
#pragma unroll
    for (int o = 16; o >= 1; o >>= 1)
        sum += __shfl_xor_sync(0xffffffffu, sum, o);
    if (lane == 0) g_vmean[nh * D_DIM + dd] = sum * (1.0f / (float)SEQ);
}

// ---------------------------------------------------------------------------
// Flash attention — R9 kernel VERBATIM (cp.async double buffer, direct LDS).
// ---------------------------------------------------------------------------
#define AT_STRIDE 72
#define AT_T (64 * AT_STRIDE)
#define AT_BUF (2 * AT_T)
#define AT_PADS_OFF (2 * AT_BUF * 2)
#define AT_SMEM (AT_PADS_OFF + 2 * 64 * 4)

__global__ __launch_bounds__(256) void attn_mma_kernel(
    const int* __restrict__ pad, float* __restrict__ out)
{
    extern __shared__ __half smh[];
    const uint32_t smb = smem_u32(smh);

    const int tid = threadIdx.x;
    const int w = tid >> 5;
    const int lane = tid & 31;
    const int g = lane >> 2;
    const int tq = lane & 3;
    const int qt = (int)(gridDim.x - 1 - blockIdx.x);
    const int nh = blockIdx.y;
    const int nb = nh >> 4;
    const int h = nh & 15;
    const int i0 = qt * 128;
    const int qr0 = i0 + w * 16 + g;
    const int qr1 = qr0 + 8;

    uint32_t qf[4][4];
    {
        const size_t b0 = ((size_t)nh * SEQ + qr0) * D_DIM;
        const size_t b1 = ((size_t)nh * SEQ + qr1) * D_DIM;
#pragma unroll
        for (int kd = 0; kd < 4; kd++) {
            const int cO = kd * 16 + 2 * tq;
            qf[kd][0] = *(const uint32_t*)(g_qh + b0 + cO);
            qf[kd][1] = *(const uint32_t*)(g_qh + b1 + cO);
            qf[kd][2] = *(const uint32_t*)(g_qh + b0 + cO + 8);
            qf[kd][3] = *(const uint32_t*)(g_qh + b1 + cO + 8);
        }
    }

    auto load_tiles = [&](int buf, int t0) {
        const uint32_t base = smb + buf * (AT_BUF * 2);
        const __half* kh = g_kh + ((size_t)nh * SEQ + t0) * D_DIM;
        const __half* vh = g_vth + (size_t)nh * D_DIM * SEQ + t0;
#pragma unroll
        for (int it = 0; it < 2; it++) {
            const int idx = tid + it * 256;
            const int row = idx >> 3;
            const int seg = (idx & 7) * 8;
            const uint32_t so = (uint32_t)(row * AT_STRIDE + seg) * 2;
            cp16(base + 0 * AT_T * 2 + so, kh + (size_t)row * D_DIM + seg);
            cp16(base + 1 * AT_T * 2 + so, vh + (size_t)row * SEQ + seg);
        }
        if (tid < 16)
            cp16(smb + AT_PADS_OFF + buf * 256 + tid * 16,
                 pad + nb * SEQ + t0 + tid * 4);
        CP_COMMIT();
    };

    float o[8][4];
#pragma unroll
    for (int dt = 0; dt < 8; dt++)
#pragma unroll
        for (int u = 0; u < 4; u++) o[dt][u] = 0.0f;
    float m0 = -1e9f, m1 = -1e9f, l0 = 0.0f, l1 = 0.0f;

    const int jmax = 2 * qt + 1;
    load_tiles(0, 0);

    for (int j = 0; j <= jmax; j++) {
        const int t0 = j * 64;
        if (j < jmax) load_tiles((j + 1) & 1, (j + 1) * 64);
        if (j < jmax) { CP_WAIT1(); } else { CP_WAIT0(); }
        __syncthreads();

        const __half* Kh = smh + (j & 1) * AT_BUF + 0 * AT_T;
        const __half* Vh = smh + (j & 1) * AT_BUF + 1 * AT_T;
        const int* pads = (const int*)((const char*)smh + AT_PADS_OFF + (j & 1) * 256);

        float s[8][4];
#pragma unroll
        for (int nt = 0; nt < 8; nt++) {
#pragma unroll
            for (int u = 0; u < 4; u++) s[nt][u] = 0.0f;
            const int nr = nt * 8 + g;
#pragma unroll
            for (int kd = 0; kd < 4; kd++) {
                const int cO = kd * 16 + 2 * tq;
                uint32_t b0 = *(const uint32_t*)(Kh + nr * AT_STRIDE + cO);
                uint32_t b1 = *(const uint32_t*)(Kh + nr * AT_STRIDE + cO + 8);
                mma_f16(s[nt], qf[kd], b0, b1);
            }
        }

#pragma unroll
        for (int nt = 0; nt < 8; nt++) {
            const int c0 = nt * 8 + 2 * tq;
#pragma unroll
            for (int u = 0; u < 4; u++) {
                const int cl = c0 + (u & 1);
                const int kcol = t0 + cl;
                const int qrow = (u < 2) ? qr0 : qr1;
                float v = s[nt][u] * 0.125f;
                if (kcol > qrow || pads[cl] == 0) v = -1e9f;
                s[nt][u] = v;
            }
        }

        float mx0 = -1e30f, mx1 = -1e30f;
#pragma unroll
        for (int nt = 0; nt < 8; nt++) {
            mx0 = fmaxf(mx0, fmaxf(s[nt][0], s[nt][1]));
            mx1 = fmaxf(mx1, fmaxf(s[nt][2], s[nt][3]));
        }
#pragma unroll
        for (int off = 1; off <= 2; off <<= 1) {
            mx0 = fmaxf(mx0, __shfl_xor_sync(0xffffffffu, mx0, off));
            mx1 = fmaxf(mx1, __shfl_xor_sync(0xffffffffu, mx1, off));
        }
        const float mn0 = fmaxf(m0, mx0), mn1 = fmaxf(m1, mx1);
        const float cr0 = __expf(m0 - mn0), cr1 = __expf(m1 - mn1);
        float rs0 = 0.0f, rs1 = 0.0f;
#pragma unroll
        for (int nt = 0; nt < 8; nt++) {
            s[nt][0] = __expf(s[nt][0] - mn0);
            s[nt][1] = __expf(s[nt][1] - mn0);
            s[nt][2] = __expf(s[nt][2] - mn1);
            s[nt][3] = __expf(s[nt][3] - mn1);
            rs0 += s[nt][0] + s[nt][1];
            rs1 += s[nt][2] + s[nt][3];
        }
#pragma unroll
        for (int off = 1; off <= 2; off <<= 1) {
            rs0 += __shfl_xor_sync(0xffffffffu, rs0, off);
            rs1 += __shfl_xor_sync(0xffffffffu, rs1, off);
        }
        l0 = l0 * cr0 + rs0;
        l1 = l1 * cr1 + rs1;
        m0 = mn0;
        m1 = mn1;
#pragma unroll
        for (int dt = 0; dt < 8; dt++) {
            o[dt][0] *= cr0; o[dt][1] *= cr0;
            o[dt][2] *= cr1; o[dt][3] *= cr1;
        }

#pragma unroll
        for (int kc = 0; kc < 4; kc++) {
            uint32_t ph[4];
            ph[0] = pack_h(s[2 * kc][0], s[2 * kc][1]);
            ph[1] = pack_h(s[2 * kc][2], s[2 * kc][3]);
            ph[2] = pack_h(s[2 * kc + 1][0], s[2 * kc + 1][1]);
            ph[3] = pack_h(s[2 * kc + 1][2], s[2 * kc + 1][3]);
            const int cO = kc * 16 + 2 * tq;
#pragma unroll
            for (int dt = 0; dt < 8; dt++) {
                const int dr = dt * 8 + g;
                uint32_t vh0 = *(const uint32_t*)(Vh + dr * AT_STRIDE + cO);
                uint32_t vh1 = *(const uint32_t*)(Vh + dr * AT_STRIDE + cO + 8);
                mma_f16(o[dt], ph, vh0, vh1);
            }
        }
        __syncthreads();
    }

    const float inv0 = 1.0f / l0, inv1 = 1.0f / l1;
    const bool dg0 = (m0 < -5e8f), dg1 = (m1 < -5e8f);
#pragma unroll
    for (int dt = 0; dt < 8; dt++) {
        const int dd = dt * 8 + 2 * tq;
        float o00 = dg0 ? g_vmean[nh * D_DIM + dd] : o[dt][0] * inv0;
        float o01 = dg0 ? g_vmean[nh * D_DIM + dd + 1] : o[dt][1] * inv0;
        float o10 = dg1 ? g_vmean[nh * D_DIM + dd] : o[dt][2] * inv1;
        float o11 = dg1 ? g_vmean[nh * D_DIM + dd + 1] : o[dt][3] * inv1;
        float2* p0 = (float2*)(out + ((size_t)(nb * SEQ + qr0)) * E_DIM + h * D_DIM + dd);
        float2* p1 = (float2*)(out + ((size_t)(nb * SEQ + qr1)) * E_DIM + h * D_DIM + dd);
        *p0 = make_float2(o00, o01);
        *p1 = make_float2(o10, o11);
    }
}

// ---------------------------------------------------------------------------
// Launch
// ---------------------------------------------------------------------------
extern "C" void kernel_launch(void* const* d_in, const int* in_sizes, int n_in,
                              void* d_out, int out_size)
{
    const float* query = (const float*)d_in[0];
    const float* key   = (const float*)d_in[1];
    const float* value = (const float*)d_in[2];
    const int*   pad   = (const int*)d_in[3];
    const float* Wq = (const float*)d_in[5];
    const float* bq = (const float*)d_in[6];
    const float* Wk = (const float*)d_in[7];
    const float* bk = (const float*)d_in[8];
    const float* Wv = (const float*)d_in[9];
    const float* bv = (const float*)d_in[10];
    float* out = (float*)d_out;

    conv_all_kernel<<<3 * XB + 3 * WB, 256>>>(query, key, value, Wq, Wk, Wv);

    dim3 pgrid(E_DIM / 128, (NB * SEQ) / 128, 3);
    proj_mma_kernel<<<pgrid, 256>>>(bq, bk, bv);

    dim3 vgrid(NHTOT, 8);
    vmean_kernel<<<vgrid, 256>>>();

    cudaFuncSetAttribute(attn_mma_kernel, cudaFuncAttributeMaxDynamicSharedMemorySize,
                         AT_SMEM);
    dim3 agrid(SEQ / 128, NHTOT);
    attn_mma_kernel<<<agrid, 256, AT_SMEM>>>(pad, out);
}

// round 12
// speedup vs baseline: 5.8079x; 1.1701x over previous
#include <cuda_runtime.h>
#include <cuda_fp16.h>
#include <cstdint>

#define E_DIM 1024
#define H_DIM 16
#define D_DIM 64
#define SEQ 2048
#define NB 2
#define NHTOT (NB * H_DIM)
#define XSZ (NB * SEQ * E_DIM)
#define WSZ (E_DIM * E_DIM)
#define QKV_SZ (NHTOT * SEQ * D_DIM)

// Single fp16 inputs
__device__ __half g_xh[3 * XSZ];
__device__ __half g_wh[3 * WSZ];
// Q/K single fp16 [nh][t][d]; V transposed single fp16 [nh][d][t]
__device__ __half g_qh[QKV_SZ];
__device__ __half g_kh[QKV_SZ];
__device__ __half g_vth[QKV_SZ];
__device__ float g_vmean[NHTOT * D_DIM];
// Additive pad mask: 0 (visible) or -1.5e9 (masked), [NB][SEQ]
__device__ float g_padf[NB * SEQ];

#define SC 0.18033688f     // 0.125 * log2(e): softmax runs in log2 domain
#define NEGB (-1.5e9f)

// ---------------------------------------------------------------------------
// Helpers
// ---------------------------------------------------------------------------
__device__ __forceinline__ void mma_f16(float c[4], const uint32_t a[4],
                                        uint32_t b0, uint32_t b1) {
    asm("mma.sync.aligned.m16n8k16.row.col.f32.f16.f16.f32 "
        "{%0,%1,%2,%3}, {%4,%5,%6,%7}, {%8,%9}, {%0,%1,%2,%3};"
        : "+f"(c[0]), "+f"(c[1]), "+f"(c[2]), "+f"(c[3])
        : "r"(a[0]), "r"(a[1]), "r"(a[2]), "r"(a[3]), "r"(b0), "r"(b1));
}

__device__ __forceinline__ void ldmx4(uint32_t r[4], uint32_t addr) {
    asm volatile("ldmatrix.sync.aligned.m8n8.x4.shared.b16 {%0,%1,%2,%3}, [%4];"
                 : "=r"(r[0]), "=r"(r[1]), "=r"(r[2]), "=r"(r[3]) : "r"(addr));
}

__device__ __forceinline__ uint32_t smem_u32(const void* p) {
    uint32_t a;
    asm("{ .reg .u64 t; cvta.to.shared.u64 t, %1; cvt.u32.u64 %0, t; }"
        : "=r"(a) : "l"(p));
    return a;
}

__device__ __forceinline__ void cp16(uint32_t dst, const void* src) {
    asm volatile("cp.async.cg.shared.global [%0], [%1], 16;" :: "r"(dst), "l"(src));
}
#define CP_COMMIT() asm volatile("cp.async.commit_group;" ::: "memory")
#define CP_WAIT0() asm volatile("cp.async.wait_group 0;" ::: "memory")
#define CP_WAIT1() asm volatile("cp.async.wait_group 1;" ::: "memory")

__device__ __forceinline__ uint32_t pack_h(float x, float y) {
    __half2 h = __floats2half2_rn(x, y);
    return *reinterpret_cast<uint32_t*>(&h);
}

// ---------------------------------------------------------------------------
// Fused conversion: six fp32->fp16 tensors + pad->additive-float, ONE launch.
// ---------------------------------------------------------------------------
#define XB (XSZ / 4 / 256)   // 4096 blocks per X tensor
#define WB (WSZ / 4 / 256)   // 1024 blocks per W tensor
#define PB (NB * SEQ / 4 / 256)  // 4 blocks for pad

__global__ __launch_bounds__(256) void conv_all_kernel(
    const float* __restrict__ q, const float* __restrict__ k,
    const float* __restrict__ v, const float* __restrict__ wq,
    const float* __restrict__ wk, const float* __restrict__ wv,
    const int* __restrict__ pad)
{
    const int b = blockIdx.x;
    const float* src;
    __half* dst;
    int local;
    if (b < 3 * XB) {
        const int z = b / XB;
        local = b - z * XB;
        src = (z == 0) ? q : (z == 1) ? k : v;
        dst = g_xh + (size_t)z * XSZ;
    } else if (b < 3 * XB + 3 * WB) {
        const int bb = b - 3 * XB;
        const int z = bb / WB;
        local = bb - z * WB;
        src = (z == 0) ? wq : (z == 1) ? wk : wv;
        dst = g_wh + (size_t)z * WSZ;
    } else {
        const int i = (b - 3 * XB - 3 * WB) * 256 + threadIdx.x;
        int4 pv = ((const int4*)pad)[i];
        float4 f;
        f.x = pv.x ? 0.0f : NEGB;
        f.y = pv.y ? 0.0f : NEGB;
        f.z = pv.z ? 0.0f : NEGB;
        f.w = pv.w ? 0.0f : NEGB;
        ((float4*)g_padf)[i] = f;
        return;
    }
    const int i = local * 256 + threadIdx.x;
    float4 val = ((const float4*)src)[i];
    ((uint32_t*)dst)[2 * i + 0] = pack_h(val.x, val.y);
    ((uint32_t*)dst)[2 * i + 1] = pack_h(val.z, val.w);
}

// ---------------------------------------------------------------------------
// Projection GEMM — R9/R11 kernel VERBATIM (static smem, NO pipelining).
// ---------------------------------------------------------------------------
__global__ __launch_bounds__(256) void proj_mma_kernel(
    const float* __restrict__ bq, const float* __restrict__ bk,
    const float* __restrict__ bv)
{
    __shared__ __half Ah[128][40];
    __shared__ __half Bh[128][40];

    const int tid = threadIdx.x;
    const int w = tid >> 5;
    const int lane = tid & 31;
    const int g = lane >> 2;
    const int tq = lane & 3;
    const int z = blockIdx.z;
    const int j0 = blockIdx.x * 128;
    const int i0 = blockIdx.y * 128;
    const int mrow = (w & 3) * 32;
    const int ncol = (w >> 2) * 64;

    const __half* xh = g_xh + (size_t)z * XSZ;
    const __half* wh = g_wh + (size_t)z * WSZ;
    const float* bias = (z == 0) ? bq : (z == 1) ? bk : bv;

    float c[2][8][4];
#pragma unroll
    for (int mt = 0; mt < 2; mt++)
#pragma unroll
        for (int nt = 0; nt < 8; nt++)
#pragma unroll
            for (int u = 0; u < 4; u++) c[mt][nt][u] = 0.0f;

    for (int k0 = 0; k0 < E_DIM; k0 += 32) {
#pragma unroll
        for (int it = 0; it < 2; it++) {
            const int idx = tid + it * 256;
            const int row = idx >> 2;
            const int seg = (idx & 3) * 8;
            const size_t ga = (size_t)(i0 + row) * E_DIM + k0 + seg;
            const size_t gb = (size_t)(j0 + row) * E_DIM + k0 + seg;
            *(uint4*)&Ah[row][seg] = *(const uint4*)(xh + ga);
            *(uint4*)&Bh[row][seg] = *(const uint4*)(wh + gb);
        }
        __syncthreads();

#pragma unroll
        for (int kc = 0; kc < 32; kc += 16) {
            uint32_t a[2][4];
#pragma unroll
            for (int mt = 0; mt < 2; mt++) {
                const int r0 = mrow + mt * 16 + g;
                a[mt][0] = *(const uint32_t*)&Ah[r0][kc + 2 * tq];
                a[mt][1] = *(const uint32_t*)&Ah[r0 + 8][kc + 2 * tq];
                a[mt][2] = *(const uint32_t*)&Ah[r0][kc + 2 * tq + 8];
                a[mt][3] = *(const uint32_t*)&Ah[r0 + 8][kc + 2 * tq + 8];
            }
#pragma unroll
            for (int nt = 0; nt < 8; nt++) {
                const int nr = ncol + nt * 8 + g;
                uint32_t b0 = *(const uint32_t*)&Bh[nr][kc + 2 * tq];
                uint32_t b1 = *(const uint32_t*)&Bh[nr][kc + 2 * tq + 8];
#pragma unroll
                for (int mt = 0; mt < 2; mt++)
                    mma_f16(c[mt][nt], a[mt], b0, b1);
            }
        }
        __syncthreads();
    }

#pragma unroll
    for (int mt = 0; mt < 2; mt++) {
#pragma unroll
        for (int nt = 0; nt < 8; nt++) {
            const int gj = j0 + ncol + nt * 8 + 2 * tq;
            const int h = gj >> 6;
            const int dd = gj & 63;
            const float b0v = bias[gj], b1v = bias[gj + 1];
            const int r0 = i0 + mrow + mt * 16 + g;
            const int r1 = r0 + 8;
            const float v00 = c[mt][nt][0] + b0v, v01 = c[mt][nt][1] + b1v;
            const float v10 = c[mt][nt][2] + b0v, v11 = c[mt][nt][3] + b1v;
            if (z < 2) {
                __half* dst = (z == 0) ? g_qh : g_kh;
                const size_t a0 =
                    ((size_t)((r0 >> 11) * H_DIM + h) * SEQ + (r0 & 2047)) * D_DIM + dd;
                const size_t a1 =
                    ((size_t)((r1 >> 11) * H_DIM + h) * SEQ + (r1 & 2047)) * D_DIM + dd;
                *(uint32_t*)(dst + a0) = pack_h(v00, v01);
                *(uint32_t*)(dst + a1) = pack_h(v10, v11);
            } else {
                const int nh0 = (r0 >> 11) * H_DIM + h;
                const size_t b0 = ((size_t)nh0 * D_DIM + dd) * SEQ;
                const size_t b1 = ((size_t)nh0 * D_DIM + dd + 1) * SEQ;
                const int t0a = r0 & 2047, t1a = r1 & 2047;
                g_vth[b0 + t0a] = __float2half_rn(v00);
                g_vth[b1 + t0a] = __float2half_rn(v01);
                g_vth[b0 + t1a] = __float2half_rn(v10);
                g_vth[b1 + t1a] = __float2half_rn(v11);
            }
        }
    }
}

// ---------------------------------------------------------------------------
// Column mean of V per (n,h); grid (NHTOT, 8), warp per d column.
// ---------------------------------------------------------------------------
__global__ __launch_bounds__(256) void vmean_kernel()
{
    const int nh = blockIdx.x;
    const int w = threadIdx.x >> 5;
    const int lane = threadIdx.x & 31;
    const int dd = blockIdx.y * 8 + w;
    const size_t base = ((size_t)nh * D_DIM + dd) * SEQ;
    float sum = 0.0f;
    for (int cI = 0; cI < SEQ / 32 / 2; cI++) {
        const int off = lane * (SEQ / 32) + cI * 2;
        uint32_t uh = *(const uint32_t*)(g_vth + base + off);
        __half2 h2 = *reinterpret_cast<__half2*>(&uh);
        sum += __half2float(h2.x) + __half2float(h2.y);
    }
#pragma unroll
    for (int o = 16; o >= 1; o >>= 1)
        sum += __shfl_xor_sync(0xffffffffu, sum, o);
    if (lane == 0) g_vmean[nh * D_DIM + dd] = sum * (1.0f / (float)SEQ);
}

// ---------------------------------------------------------------------------
// Flash attention: cp.async double buffer + ldmatrix fragments + additive
// pad mask + log2-domain softmax (exp2).
// ---------------------------------------------------------------------------
#define AT_STRIDE 72
#define AT_T (64 * AT_STRIDE)
#define AT_BUF (2 * AT_T)
#define AT_PADS_OFF (2 * AT_BUF * 2)
#define AT_SMEM (AT_PADS_OFF + 2 * 64 * 4)

__global__ __launch_bounds__(256) void attn_mma_kernel(float* __restrict__ out)
{
    extern __shared__ __half smh[];
    const uint32_t smb = smem_u32(smh);

    const int tid = threadIdx.x;
    const int w = tid >> 5;
    const int lane = tid & 31;
    const int g = lane >> 2;
    const int tq = lane & 3;
    const int qt = (int)(gridDim.x - 1 - blockIdx.x);
    const int nh = blockIdx.y;
    const int nb = nh >> 4;
    const int h = nh & 15;
    const int i0 = qt * 128;
    const int qr0 = i0 + w * 16 + g;
    const int qr1 = qr0 + 8;

    // ldmatrix lane-constant offset (in halves):
    // lane supplies row (lane&7)+8*(lane>>4), k-offset 8*((lane>>3)&1)
    const uint32_t lco =
        (uint32_t)((((lane >> 4) & 1) * 8 + (lane & 7)) * AT_STRIDE +
                   ((lane >> 3) & 1) * 8);

    uint32_t qf[4][4];
    {
        const size_t b0 = ((size_t)nh * SEQ + qr0) * D_DIM;
        const size_t b1 = ((size_t)nh * SEQ + qr1) * D_DIM;
#pragma unroll
        for (int kd = 0; kd < 4; kd++) {
            const int cO = kd * 16 + 2 * tq;
            qf[kd][0] = *(const uint32_t*)(g_qh + b0 + cO);
            qf[kd][1] = *(const uint32_t*)(g_qh + b1 + cO);
            qf[kd][2] = *(const uint32_t*)(g_qh + b0 + cO + 8);
            qf[kd][3] = *(const uint32_t*)(g_qh + b1 + cO + 8);
        }
    }

    auto load_tiles = [&](int buf, int t0) {
        const uint32_t base = smb + buf * (AT_BUF * 2);
        const __half* kh = g_kh + ((size_t)nh * SEQ + t0) * D_DIM;
        const __half* vh = g_vth + (size_t)nh * D_DIM * SEQ + t0;
#pragma unroll
        for (int it = 0; it < 2; it++) {
            const int idx = tid + it * 256;
            const int row = idx >> 3;
            const int seg = (idx & 7) * 8;
            const uint32_t so = (uint32_t)(row * AT_STRIDE + seg) * 2;
            cp16(base + 0 * AT_T * 2 + so, kh + (size_t)row * D_DIM + seg);
            cp16(base + 1 * AT_T * 2 + so, vh + (size_t)row * SEQ + seg);
        }
        if (tid < 16)
            cp16(smb + AT_PADS_OFF + buf * 256 + tid * 16,
                 g_padf + nb * SEQ + t0 + tid * 4);
        CP_COMMIT();
    };

    float o[8][4];
#pragma unroll
    for (int dt = 0; dt < 8; dt++)
#pragma unroll
        for (int u = 0; u < 4; u++) o[dt][u] = 0.0f;
    float m0 = -1e9f, m1 = -1e9f, l0 = 0.0f, l1 = 0.0f;

    const int jmax = 2 * qt + 1;
    load_tiles(0, 0);

    for (int j = 0; j <= jmax; j++) {
        const int t0 = j * 64;
        if (j < jmax) load_tiles((j + 1) & 1, (j + 1) * 64);
        if (j < jmax) { CP_WAIT1(); } else { CP_WAIT0(); }
        __syncthreads();

        const uint32_t Kb = smb + (j & 1) * (AT_BUF * 2);
        const uint32_t Vb = Kb + AT_T * 2;
        const float* padf =
            (const float*)((const char*)smh + AT_PADS_OFF + (j & 1) * 256);

        // S = Qh * Kh^T via ldmatrix fragments
        float s[8][4];
#pragma unroll
        for (int nt = 0; nt < 8; nt++)
#pragma unroll
            for (int u = 0; u < 4; u++) s[nt][u] = 0.0f;

#pragma unroll
        for (int kd = 0; kd < 4; kd++) {
#pragma unroll
            for (int p = 0; p < 4; p++) {
                uint32_t kb[4];
                ldmx4(kb, Kb + (uint32_t)(p * 16 * AT_STRIDE + kd * 16) * 2 + lco * 2);
                mma_f16(s[2 * p], qf[kd], kb[0], kb[1]);
                mma_f16(s[2 * p + 1], qf[kd], kb[2], kb[3]);
            }
        }

        // Scale (log2 domain) + additive pad mask; causal only on boundary warps
        const bool causal = (t0 + 63 > i0 + w * 16);
        if (!causal) {
#pragma unroll
            for (int nt = 0; nt < 8; nt++) {
                const int c0 = nt * 8 + 2 * tq;
                const float p0 = padf[c0], p1 = padf[c0 + 1];
                s[nt][0] = fmaf(s[nt][0], SC, p0);
                s[nt][1] = fmaf(s[nt][1], SC, p1);
                s[nt][2] = fmaf(s[nt][2], SC, p0);
                s[nt][3] = fmaf(s[nt][3], SC, p1);
            }
        } else {
#pragma unroll
            for (int nt = 0; nt < 8; nt++) {
                const int c0 = nt * 8 + 2 * tq;
#pragma unroll
                for (int u = 0; u < 4; u++) {
                    const int cl = c0 + (u & 1);
                    const int kcol = t0 + cl;
                    const int qrow = (u < 2) ? qr0 : qr1;
                    float v = fmaf(s[nt][u], SC, padf[cl]);
                    if (kcol > qrow) v = NEGB;
                    s[nt][u] = v;
                }
            }
        }

        // Online softmax (log2 domain)
        float mx0 = -1e30f, mx1 = -1e30f;
#pragma unroll
        for (int nt = 0; nt < 8; nt++) {
            mx0 = fmaxf(mx0, fmaxf(s[nt][0], s[nt][1]));
            mx1 = fmaxf(mx1, fmaxf(s[nt][2], s[nt][3]));
        }
#pragma unroll
        for (int off = 1; off <= 2; off <<= 1) {
            mx0 = fmaxf(mx0, __shfl_xor_sync(0xffffffffu, mx0, off));
            mx1 = fmaxf(mx1, __shfl_xor_sync(0xffffffffu, mx1, off));
        }
        const float mn0 = fmaxf(m0, mx0), mn1 = fmaxf(m1, mx1);
        const float cr0 = exp2f(m0 - mn0), cr1 = exp2f(m1 - mn1);
        float rs0 = 0.0f, rs1 = 0.0f;
#pragma unroll
        for (int nt = 0; nt < 8; nt++) {
            s[nt][0] = exp2f(s[nt][0] - mn0);
            s[nt][1] = exp2f(s[nt][1] - mn0);
            s[nt][2] = exp2f(s[nt][2] - mn1);
            s[nt][3] = exp2f(s[nt][3] - mn1);
            rs0 += s[nt][0] + s[nt][1];
            rs1 += s[nt][2] + s[nt][3];
        }
#pragma unroll
        for (int off = 1; off <= 2; off <<= 1) {
            rs0 += __shfl_xor_sync(0xffffffffu, rs0, off);
            rs1 += __shfl_xor_sync(0xffffffffu, rs1, off);
        }
        l0 = l0 * cr0 + rs0;
        l1 = l1 * cr1 + rs1;
        m0 = mn0;
        m1 = mn1;
#pragma unroll
        for (int dt = 0; dt < 8; dt++) {
            o[dt][0] *= cr0; o[dt][1] *= cr0;
            o[dt][2] *= cr1; o[dt][3] *= cr1;
        }

        // O += P * Vh via ldmatrix fragments
#pragma unroll
        for (int kc = 0; kc < 4; kc++) {
            uint32_t ph[4];
            ph[0] = pack_h(s[2 * kc][0], s[2 * kc][1]);
            ph[1] = pack_h(s[2 * kc][2], s[2 * kc][3]);
            ph[2] = pack_h(s[2 * kc + 1][0], s[2 * kc + 1][1]);
            ph[3] = pack_h(s[2 * kc + 1][2], s[2 * kc + 1][3]);
#pragma unroll
            for (int p = 0; p < 4; p++) {
                uint32_t vb[4];
                ldmx4(vb, Vb + (uint32_t)(p * 16 * AT_STRIDE + kc * 16) * 2 + lco * 2);
                mma_f16(o[2 * p], ph, vb[0], vb[1]);
                mma_f16(o[2 * p + 1], ph, vb[2], vb[3]);
            }
        }
        __syncthreads();
    }

    // Epilogue
    const float inv0 = 1.0f / l0, inv1 = 1.0f / l1;
    const bool dg0 = (m0 < -5e8f), dg1 = (m1 < -5e8f);
#pragma unroll
    for (int dt = 0; dt < 8; dt++) {
        const int dd = dt * 8 + 2 * tq;
        float o00 = dg0 ? g_vmean[nh * D_DIM + dd] : o[dt][0] * inv0;
        float o01 = dg0 ? g_vmean[nh * D_DIM + dd + 1] : o[dt][1] * inv0;
        float o10 = dg1 ? g_vmean[nh * D_DIM + dd] : o[dt][2] * inv1;
        float o11 = dg1 ? g_vmean[nh * D_DIM + dd + 1] : o[dt][3] * inv1;
        float2* p0 = (float2*)(out + ((size_t)(nb * SEQ + qr0)) * E_DIM + h * D_DIM + dd);
        float2* p1 = (float2*)(out + ((size_t)(nb * SEQ + qr1)) * E_DIM + h * D_DIM + dd);
        *p0 = make_float2(o00, o01);
        *p1 = make_float2(o10, o11);
    }
}

// ---------------------------------------------------------------------------
// Launch
// ---------------------------------------------------------------------------
extern "C" void kernel_launch(void* const* d_in, const int* in_sizes, int n_in,
                              void* d_out, int out_size)
{
    const float* query = (const float*)d_in[0];
    const float* key   = (const float*)d_in[1];
    const float* value = (const float*)d_in[2];
    const int*   pad   = (const int*)d_in[3];
    const float* Wq = (const float*)d_in[5];
    const float* bq = (const float*)d_in[6];
    const float* Wk = (const float*)d_in[7];
    const float* bk = (const float*)d_in[8];
    const float* Wv = (const float*)d_in[9];
    const float* bv = (const float*)d_in[10];
    float* out = (float*)d_out;

    conv_all_kernel<<<3 * XB + 3 * WB + PB, 256>>>(query, key, value, Wq, Wk, Wv, pad);

    dim3 pgrid(E_DIM / 128, (NB * SEQ) / 128, 3);
    proj_mma_kernel<<<pgrid, 256>>>(bq, bk, bv);

    dim3 vgrid(NHTOT, 8);
    vmean_kernel<<<vgrid, 256>>>();

    cudaFuncSetAttribute(attn_mma_kernel, cudaFuncAttributeMaxDynamicSharedMemorySize,
                         AT_SMEM);
    dim3 agrid(SEQ / 128, NHTOT);
    attn_mma_kernel<<<agrid, 256, AT_SMEM>>>(out);
}

// round 13
// speedup vs baseline: 6.6661x; 1.1478x over previous
#include <cuda_runtime.h>
#include <cuda_fp16.h>
#include <cstdint>

#define E_DIM 1024
#define H_DIM 16
#define D_DIM 64
#define SEQ 2048
#define NB 2
#define NHTOT (NB * H_DIM)
#define XSZ (NB * SEQ * E_DIM)
#define WSZ (E_DIM * E_DIM)
#define QKV_SZ (NHTOT * SEQ * D_DIM)

// Single fp16 inputs
__device__ __half g_xh[3 * XSZ];
__device__ __half g_wh[3 * WSZ];
// Q/K/V single fp16, all [nh][t][d] (d contiguous)
__device__ __half g_qh[QKV_SZ];
__device__ __half g_kh[QKV_SZ];
__device__ __half g_vh[QKV_SZ];
// Compressed (pad-visible) K/V, [nh][j][d]; tail rows zero-filled
__device__ __half g_khc[QKV_SZ];
__device__ __half g_vhc[QKV_SZ];
// Compression metadata
__device__ int g_pos[NB * SEQ];    // original t of j-th visible key (tail = 1<<29)
__device__ int g_pref[NB * SEQ];   // # visible keys with index <= t
__device__ int g_cnt[NB];
__device__ float g_vmean[NHTOT * D_DIM];

#define SC 0.18033688f     // 0.125 * log2(e): softmax in log2 domain
#define NEGB (-1.5e9f)

// ---------------------------------------------------------------------------
// Helpers
// ---------------------------------------------------------------------------
__device__ __forceinline__ void mma_f16(float c[4], const uint32_t a[4],
                                        uint32_t b0, uint32_t b1) {
    asm("mma.sync.aligned.m16n8k16.row.col.f32.f16.f16.f32 "
        "{%0,%1,%2,%3}, {%4,%5,%6,%7}, {%8,%9}, {%0,%1,%2,%3};"
        : "+f"(c[0]), "+f"(c[1]), "+f"(c[2]), "+f"(c[3])
        : "r"(a[0]), "r"(a[1]), "r"(a[2]), "r"(a[3]), "r"(b0), "r"(b1));
}

__device__ __forceinline__ void ldmx4(uint32_t r[4], uint32_t addr) {
    asm volatile("ldmatrix.sync.aligned.m8n8.x4.shared.b16 {%0,%1,%2,%3}, [%4];"
                 : "=r"(r[0]), "=r"(r[1]), "=r"(r[2]), "=r"(r[3]) : "r"(addr));
}
__device__ __forceinline__ void ldmx4t(uint32_t r[4], uint32_t addr) {
    asm volatile("ldmatrix.sync.aligned.m8n8.x4.trans.shared.b16 {%0,%1,%2,%3}, [%4];"
                 : "=r"(r[0]), "=r"(r[1]), "=r"(r[2]), "=r"(r[3]) : "r"(addr));
}

__device__ __forceinline__ uint32_t smem_u32(const void* p) {
    uint32_t a;
    asm("{ .reg .u64 t; cvta.to.shared.u64 t, %1; cvt.u32.u64 %0, t; }"
        : "=r"(a) : "l"(p));
    return a;
}

__device__ __forceinline__ void cp16(uint32_t dst, const void* src) {
    asm volatile("cp.async.cg.shared.global [%0], [%1], 16;" :: "r"(dst), "l"(src));
}
#define CP_COMMIT() asm volatile("cp.async.commit_group;" ::: "memory")
#define CP_WAIT0() asm volatile("cp.async.wait_group 0;" ::: "memory")
#define CP_WAIT1() asm volatile("cp.async.wait_group 1;" ::: "memory")

__device__ __forceinline__ uint32_t pack_h(float x, float y) {
    __half2 h = __floats2half2_rn(x, y);
    return *reinterpret_cast<uint32_t*>(&h);
}

// ---------------------------------------------------------------------------
// Fused conversion: six fp32->fp16 tensors, one launch.
// ---------------------------------------------------------------------------
#define XB (XSZ / 4 / 256)
#define WB (WSZ / 4 / 256)

__global__ __launch_bounds__(256) void conv_all_kernel(
    const float* __restrict__ q, const float* __restrict__ k,
    const float* __restrict__ v, const float* __restrict__ wq,
    const float* __restrict__ wk, const float* __restrict__ wv)
{
    const int b = blockIdx.x;
    const float* src;
    __half* dst;
    int local;
    if (b < 3 * XB) {
        const int z = b / XB;
        local = b - z * XB;
        src = (z == 0) ? q : (z == 1) ? k : v;
        dst = g_xh + (size_t)z * XSZ;
    } else {
        const int bb = b - 3 * XB;
        const int z = bb / WB;
        local = bb - z * WB;
        src = (z == 0) ? wq : (z == 1) ? wk : wv;
        dst = g_wh + (size_t)z * WSZ;
    }
    const int i = local * 256 + threadIdx.x;
    float4 val = ((const float4*)src)[i];
    ((uint32_t*)dst)[2 * i + 0] = pack_h(val.x, val.y);
    ((uint32_t*)dst)[2 * i + 1] = pack_h(val.z, val.w);
}

// ---------------------------------------------------------------------------
// Prefix scan of pad mask -> g_pos / g_pref / g_cnt. One block per batch.
// ---------------------------------------------------------------------------
__global__ __launch_bounds__(1024) void scan_kernel(const int* __restrict__ pad)
{
    const int n = blockIdx.x;
    const int tid = threadIdx.x;
    const int lane = tid & 31;
    const int wid = tid >> 5;
    const int e0 = pad[n * SEQ + 2 * tid] != 0;
    const int e1 = pad[n * SEQ + 2 * tid + 1] != 0;
    const int s = e0 + e1;
    int v = s;
#pragma unroll
    for (int off = 1; off < 32; off <<= 1) {
        int t = __shfl_up_sync(0xffffffffu, v, off);
        if (lane >= off) v += t;
    }
    __shared__ int wsum[32];
    if (lane == 31) wsum[wid] = v;
    __syncthreads();
    if (wid == 0) {
        int t = wsum[lane];
#pragma unroll
        for (int off = 1; off < 32; off <<= 1) {
            int u = __shfl_up_sync(0xffffffffu, t, off);
            if (lane >= off) t += u;
        }
        wsum[lane] = t;
    }
    __syncthreads();
    const int total = wsum[31];
    const int incl = (wid ? wsum[wid - 1] : 0) + v;
    const int excl = incl - s;
    if (e0) g_pos[n * SEQ + excl] = 2 * tid;
    if (e1) g_pos[n * SEQ + excl + e0] = 2 * tid + 1;
    g_pref[n * SEQ + 2 * tid] = excl + e0;
    g_pref[n * SEQ + 2 * tid + 1] = incl;
    if (tid == 0) g_cnt[n] = 0;   // placeholder; real value below
    __syncthreads();
    if (tid == 1023) g_cnt[n] = total;
    for (int i = total + tid; i < SEQ; i += 1024)
        g_pos[n * SEQ + i] = (1 << 29);
}

// ---------------------------------------------------------------------------
// Gather visible K/V rows into compressed [nh][j][d]; tail zero-filled.
// grid (NHTOT, SEQ/64, 2), block 512.
// ---------------------------------------------------------------------------
__global__ __launch_bounds__(512) void gather_kernel()
{
    const int nh = blockIdx.x;
    const int nb = nh >> 4;
    const int j = blockIdx.y * 64 + (threadIdx.x >> 3);
    const int dseg = (threadIdx.x & 7) * 8;
    const int cnt = g_cnt[nb];
    const __half* src = blockIdx.z ? g_vh : g_kh;
    __half* dst = blockIdx.z ? g_vhc : g_khc;
    uint4 val = make_uint4(0, 0, 0, 0);
    if (j < cnt) {
        const int t = g_pos[nb * SEQ + j];
        val = *(const uint4*)(src + ((size_t)nh * SEQ + t) * D_DIM + dseg);
    }
    *(uint4*)(dst + ((size_t)nh * SEQ + j) * D_DIM + dseg) = val;
}

// ---------------------------------------------------------------------------
// Projection GEMM — R9/R11 structure VERBATIM; V now row layout like Q/K.
// ---------------------------------------------------------------------------
__global__ __launch_bounds__(256) void proj_mma_kernel(
    const float* __restrict__ bq, const float* __restrict__ bk,
    const float* __restrict__ bv)
{
    __shared__ __half Ah[128][40];
    __shared__ __half Bh[128][40];

    const int tid = threadIdx.x;
    const int w = tid >> 5;
    const int lane = tid & 31;
    const int g = lane >> 2;
    const int tq = lane & 3;
    const int z = blockIdx.z;
    const int j0 = blockIdx.x * 128;
    const int i0 = blockIdx.y * 128;
    const int mrow = (w & 3) * 32;
    const int ncol = (w >> 2) * 64;

    const __half* xh = g_xh + (size_t)z * XSZ;
    const __half* wh = g_wh + (size_t)z * WSZ;
    const float* bias = (z == 0) ? bq : (z == 1) ? bk : bv;

    float c[2][8][4];
#pragma unroll
    for (int mt = 0; mt < 2; mt++)
#pragma unroll
        for (int nt = 0; nt < 8; nt++)
#pragma unroll
            for (int u = 0; u < 4; u++) c[mt][nt][u] = 0.0f;

    for (int k0 = 0; k0 < E_DIM; k0 += 32) {
#pragma unroll
        for (int it = 0; it < 2; it++) {
            const int idx = tid + it * 256;
            const int row = idx >> 2;
            const int seg = (idx & 3) * 8;
            const size_t ga = (size_t)(i0 + row) * E_DIM + k0 + seg;
            const size_t gb = (size_t)(j0 + row) * E_DIM + k0 + seg;
            *(uint4*)&Ah[row][seg] = *(const uint4*)(xh + ga);
            *(uint4*)&Bh[row][seg] = *(const uint4*)(wh + gb);
        }
        __syncthreads();

#pragma unroll
        for (int kc = 0; kc < 32; kc += 16) {
            uint32_t a[2][4];
#pragma unroll
            for (int mt = 0; mt < 2; mt++) {
                const int r0 = mrow + mt * 16 + g;
                a[mt][0] = *(const uint32_t*)&Ah[r0][kc + 2 * tq];
                a[mt][1] = *(const uint32_t*)&Ah[r0 + 8][kc + 2 * tq];
                a[mt][2] = *(const uint32_t*)&Ah[r0][kc + 2 * tq + 8];
                a[mt][3] = *(const uint32_t*)&Ah[r0 + 8][kc + 2 * tq + 8];
            }
#pragma unroll
            for (int nt = 0; nt < 8; nt++) {
                const int nr = ncol + nt * 8 + g;
                uint32_t b0 = *(const uint32_t*)&Bh[nr][kc + 2 * tq];
                uint32_t b1 = *(const uint32_t*)&Bh[nr][kc + 2 * tq + 8];
#pragma unroll
                for (int mt = 0; mt < 2; mt++)
                    mma_f16(c[mt][nt], a[mt], b0, b1);
            }
        }
        __syncthreads();
    }

#pragma unroll
    for (int mt = 0; mt < 2; mt++) {
#pragma unroll
        for (int nt = 0; nt < 8; nt++) {
            const int gj = j0 + ncol + nt * 8 + 2 * tq;
            const int h = gj >> 6;
            const int dd = gj & 63;
            const float b0v = bias[gj], b1v = bias[gj + 1];
            const int r0 = i0 + mrow + mt * 16 + g;
            const int r1 = r0 + 8;
            const float v00 = c[mt][nt][0] + b0v, v01 = c[mt][nt][1] + b1v;
            const float v10 = c[mt][nt][2] + b0v, v11 = c[mt][nt][3] + b1v;
            __half* dst = (z == 0) ? g_qh : (z == 1) ? g_kh : g_vh;
            const size_t a0 =
                ((size_t)((r0 >> 11) * H_DIM + h) * SEQ + (r0 & 2047)) * D_DIM + dd;
            const size_t a1 =
                ((size_t)((r1 >> 11) * H_DIM + h) * SEQ + (r1 & 2047)) * D_DIM + dd;
            *(uint32_t*)(dst + a0) = pack_h(v00, v01);
            *(uint32_t*)(dst + a1) = pack_h(v10, v11);
        }
    }
}

// ---------------------------------------------------------------------------
// Column mean of V per (n,h) from [nh][t][d] layout (R2 pattern).
// ---------------------------------------------------------------------------
__global__ __launch_bounds__(256) void vmean_kernel()
{
    __shared__ float red[256];
    const int nh = blockIdx.x;
    const int dd = threadIdx.x & 63;
    const int part = threadIdx.x >> 6;
    float sum = 0.0f;
    const int t0 = part * (SEQ / 4);
    for (int t = t0; t < t0 + SEQ / 4; t++)
        sum += __half2float(g_vh[((size_t)nh * SEQ + t) * D_DIM + dd]);
    red[threadIdx.x] = sum;
    __syncthreads();
    if (part == 0) {
        float tot = red[dd] + red[64 + dd] + red[128 + dd] + red[192 + dd];
        g_vmean[nh * D_DIM + dd] = tot * (1.0f / (float)SEQ);
    }
}

// ---------------------------------------------------------------------------
// Flash attention on COMPRESSED keys. K fragments via ldmatrix, V fragments
// via ldmatrix.trans from row layout. Causal via pos[]; pad mask gone.
// ---------------------------------------------------------------------------
#define AT_STRIDE 72
#define AT_T (64 * AT_STRIDE)
#define AT_BUF (2 * AT_T)
#define AT_POS_OFF (2 * AT_BUF * 2)
#define AT_SMEM (AT_POS_OFF + 2 * 64 * 4)

__global__ __launch_bounds__(256) void attn_mma_kernel(float* __restrict__ out)
{
    extern __shared__ __half smh[];
    const uint32_t smb = smem_u32(smh);

    const int tid = threadIdx.x;
    const int w = tid >> 5;
    const int lane = tid & 31;
    const int g = lane >> 2;
    const int tq = lane & 3;
    const int qt = (int)(gridDim.x - 1 - blockIdx.x);  // heavy tiles first
    const int nh = blockIdx.y;
    const int nb = nh >> 4;
    const int h = nh & 15;
    const int i0 = qt * 128;
    const int qr0 = i0 + w * 16 + g;
    const int qr1 = qr0 + 8;

    // K (non-trans) lane offset: row (l&7)+8*(l>>4), k-col 8*((l>>3)&1)
    const uint32_t lcoK =
        (uint32_t)((((lane >> 4) & 1) * 8 + (lane & 7)) * AT_STRIDE +
                   ((lane >> 3) & 1) * 8);
    // V (trans) lane offset: row (l&7)+8*((l>>3)&1), n-col 8*(l>>4)
    const uint32_t lcoV =
        (uint32_t)(((lane & 7) + ((lane >> 3) & 1) * 8) * AT_STRIDE +
                   ((lane >> 4) & 1) * 8);

    uint32_t qf[4][4];
    {
        const size_t b0 = ((size_t)nh * SEQ + qr0) * D_DIM;
        const size_t b1 = ((size_t)nh * SEQ + qr1) * D_DIM;
#pragma unroll
        for (int kd = 0; kd < 4; kd++) {
            const int cO = kd * 16 + 2 * tq;
            qf[kd][0] = *(const uint32_t*)(g_qh + b0 + cO);
            qf[kd][1] = *(const uint32_t*)(g_qh + b1 + cO);
            qf[kd][2] = *(const uint32_t*)(g_qh + b0 + cO + 8);
            qf[kd][3] = *(const uint32_t*)(g_qh + b1 + cO + 8);
        }
    }

    auto load_tiles = [&](int buf, int t0) {
        const uint32_t base = smb + buf * (AT_BUF * 2);
        const __half* kh = g_khc + ((size_t)nh * SEQ + t0) * D_DIM;
        const __half* vh = g_vhc + ((size_t)nh * SEQ + t0) * D_DIM;
#pragma unroll
        for (int it = 0; it < 2; it++) {
            const int idx = tid + it * 256;
            const int row = idx >> 3;
            const int seg = (idx & 7) * 8;
            const uint32_t so = (uint32_t)(row * AT_STRIDE + seg) * 2;
            cp16(base + 0 * AT_T * 2 + so, kh + (size_t)row * D_DIM + seg);
            cp16(base + 1 * AT_T * 2 + so, vh + (size_t)row * D_DIM + seg);
        }
        if (tid < 16)
            cp16(smb + AT_POS_OFF + buf * 256 + tid * 16,
                 g_pos + nb * SEQ + t0 + tid * 4);
        CP_COMMIT();
    };

    float o[8][4];
#pragma unroll
    for (int dt = 0; dt < 8; dt++)
#pragma unroll
        for (int u = 0; u < 4; u++) o[dt][u] = 0.0f;
    float m0 = -1e9f, m1 = -1e9f, l0 = 0.0f, l1 = 0.0f;

    const int nvis = g_pref[nb * SEQ + i0 + 127];
    const int ntiles = (nvis + 63) >> 6;

    if (ntiles > 0) {
        load_tiles(0, 0);

        for (int j = 0; j < ntiles; j++) {
            const int t0 = j * 64;
            if (j < ntiles - 1) load_tiles((j + 1) & 1, (j + 1) * 64);
            if (j < ntiles - 1) { CP_WAIT1(); } else { CP_WAIT0(); }
            __syncthreads();

            const uint32_t Kb = smb + (j & 1) * (AT_BUF * 2);
            const uint32_t Vb = Kb + AT_T * 2;
            const int* posS =
                (const int*)((const char*)smh + AT_POS_OFF + (j & 1) * 256);

            // S = Qh * Khc^T
            float s[8][4];
#pragma unroll
            for (int nt = 0; nt < 8; nt++)
#pragma unroll
                for (int u = 0; u < 4; u++) s[nt][u] = 0.0f;

#pragma unroll
            for (int kd = 0; kd < 4; kd++) {
#pragma unroll
                for (int p = 0; p < 4; p++) {
                    uint32_t kb[4];
                    ldmx4(kb, Kb + (uint32_t)(p * 16 * AT_STRIDE + kd * 16) * 2 +
                                  lcoK * 2);
                    mma_f16(s[2 * p], qf[kd], kb[0], kb[1]);
                    mma_f16(s[2 * p + 1], qf[kd], kb[2], kb[3]);
                }
            }

            // Scale + causal (pos-based). Fast path: whole tile visible to warp.
            const bool slow = (posS[63] > i0 + w * 16);
            if (!slow) {
#pragma unroll
                for (int nt = 0; nt < 8; nt++)
#pragma unroll
                    for (int u = 0; u < 4; u++) s[nt][u] *= SC;
            } else {
#pragma unroll
                for (int nt = 0; nt < 8; nt++) {
                    const int c0 = nt * 8 + 2 * tq;
#pragma unroll
                    for (int u = 0; u < 4; u++) {
                        const int cl = c0 + (u & 1);
                        const int qrow = (u < 2) ? qr0 : qr1;
                        float v = s[nt][u] * SC;
                        if (posS[cl] > qrow) v = NEGB;
                        s[nt][u] = v;
                    }
                }
            }

            // Online softmax (log2 domain)
            float mx0 = -1e30f, mx1 = -1e30f;
#pragma unroll
            for (int nt = 0; nt < 8; nt++) {
                mx0 = fmaxf(mx0, fmaxf(s[nt][0], s[nt][1]));
                mx1 = fmaxf(mx1, fmaxf(s[nt][2], s[nt][3]));
            }
#pragma unroll
            for (int off = 1; off <= 2; off <<= 1) {
                mx0 = fmaxf(mx0, __shfl_xor_sync(0xffffffffu, mx0, off));
                mx1 = fmaxf(mx1, __shfl_xor_sync(0xffffffffu, mx1, off));
            }
            const float mn0 = fmaxf(m0, mx0), mn1 = fmaxf(m1, mx1);
            const float cr0 = exp2f(m0 - mn0), cr1 = exp2f(m1 - mn1);
            float rs0 = 0.0f, rs1 = 0.0f;
#pragma unroll
            for (int nt = 0; nt < 8; nt++) {
                s[nt][0] = exp2f(s[nt][0] - mn0);
                s[nt][1] = exp2f(s[nt][1] - mn0);
                s[nt][2] = exp2f(s[nt][2] - mn1);
                s[nt][3] = exp2f(s[nt][3] - mn1);
                rs0 += s[nt][0] + s[nt][1];
                rs1 += s[nt][2] + s[nt][3];
            }
#pragma unroll
            for (int off = 1; off <= 2; off <<= 1) {
                rs0 += __shfl_xor_sync(0xffffffffu, rs0, off);
                rs1 += __shfl_xor_sync(0xffffffffu, rs1, off);
            }
            l0 = l0 * cr0 + rs0;
            l1 = l1 * cr1 + rs1;
            m0 = mn0;
            m1 = mn1;
#pragma unroll
            for (int dt = 0; dt < 8; dt++) {
                o[dt][0] *= cr0; o[dt][1] *= cr0;
                o[dt][2] *= cr1; o[dt][3] *= cr1;
            }

            // O += P * Vhc  (V row-layout, fragments via ldmatrix.trans)
#pragma unroll
            for (int kc = 0; kc < 4; kc++) {
                uint32_t ph[4];
                ph[0] = pack_h(s[2 * kc][0], s[2 * kc][1]);
                ph[1] = pack_h(s[2 * kc][2], s[2 * kc][3]);
                ph[2] = pack_h(s[2 * kc + 1][0], s[2 * kc + 1][1]);
                ph[3] = pack_h(s[2 * kc + 1][2], s[2 * kc + 1][3]);
#pragma unroll
                for (int dp = 0; dp < 4; dp++) {
                    uint32_t vb[4];
                    ldmx4t(vb, Vb + (uint32_t)(kc * 16 * AT_STRIDE + dp * 16) * 2 +
                                   lcoV * 2);
                    mma_f16(o[2 * dp], ph, vb[0], vb[1]);
                    mma_f16(o[2 * dp + 1], ph, vb[2], vb[3]);
                }
            }
            __syncthreads();
        }
    }

    // Epilogue
    const float inv0 = 1.0f / l0, inv1 = 1.0f / l1;
    const bool dg0 = (m0 < -5e8f), dg1 = (m1 < -5e8f);
#pragma unroll
    for (int dt = 0; dt < 8; dt++) {
        const int dd = dt * 8 + 2 * tq;
        float o00 = dg0 ? g_vmean[nh * D_DIM + dd] : o[dt][0] * inv0;
        float o01 = dg0 ? g_vmean[nh * D_DIM + dd + 1] : o[dt][1] * inv0;
        float o10 = dg1 ? g_vmean[nh * D_DIM + dd] : o[dt][2] * inv1;
        float o11 = dg1 ? g_vmean[nh * D_DIM + dd + 1] : o[dt][3] * inv1;
        float2* p0 = (float2*)(out + ((size_t)(nb * SEQ + qr0)) * E_DIM + h * D_DIM + dd);
        float2* p1 = (float2*)(out + ((size_t)(nb * SEQ + qr1)) * E_DIM + h * D_DIM + dd);
        *p0 = make_float2(o00, o01);
        *p1 = make_float2(o10, o11);
    }
}

// ---------------------------------------------------------------------------
// Launch
// ---------------------------------------------------------------------------
extern "C" void kernel_launch(void* const* d_in, const int* in_sizes, int n_in,
                              void* d_out, int out_size)
{
    const float* query = (const float*)d_in[0];
    const float* key   = (const float*)d_in[1];
    const float* value = (const float*)d_in[2];
    const int*   pad   = (const int*)d_in[3];
    const float* Wq = (const float*)d_in[5];
    const float* bq = (const float*)d_in[6];
    const float* Wk = (const float*)d_in[7];
    const float* bk = (const float*)d_in[8];
    const float* Wv = (const float*)d_in[9];
    const float* bv = (const float*)d_in[10];
    float* out = (float*)d_out;

    conv_all_kernel<<<3 * XB + 3 * WB, 256>>>(query, key, value, Wq, Wk, Wv);
    scan_kernel<<<NB, 1024>>>(pad);

    dim3 pgrid(E_DIM / 128, (NB * SEQ) / 128, 3);
    proj_mma_kernel<<<pgrid, 256>>>(bq, bk, bv);

    vmean_kernel<<<NHTOT, 256>>>();

    dim3 ggrid(NHTOT, SEQ / 64, 2);
    gather_kernel<<<ggrid, 512>>>();

    cudaFuncSetAttribute(attn_mma_kernel, cudaFuncAttributeMaxDynamicSharedMemorySize,
                         AT_SMEM);
    dim3 agrid(SEQ / 128, NHTOT);
    attn_mma_kernel<<<agrid, 256, AT_SMEM>>>(out);
}

// round 14
// speedup vs baseline: 6.8667x; 1.0301x over previous
#include <cuda_runtime.h>
#include <cuda_fp16.h>
#include <cstdint>

#define E_DIM 1024
#define H_DIM 16
#define D_DIM 64
#define SEQ 2048
#define NB 2
#define NHTOT (NB * H_DIM)
#define XSZ (NB * SEQ * E_DIM)
#define WSZ (E_DIM * E_DIM)
#define QKV_SZ (NHTOT * SEQ * D_DIM)

// Single fp16 inputs
__device__ __half g_xh[3 * XSZ];
__device__ __half g_wh[3 * WSZ];
// Q/K/V single fp16, all [nh][t][d] (d contiguous)
__device__ __half g_qh[QKV_SZ];
__device__ __half g_kh[QKV_SZ];
__device__ __half g_vh[QKV_SZ];
// Compressed (pad-visible) K/V, [nh][j][d]; tail rows zero-filled
__device__ __half g_khc[QKV_SZ];
__device__ __half g_vhc[QKV_SZ];
// Compression metadata
__device__ int g_pos[NB * SEQ];    // original t of j-th visible key (tail = 1<<29)
__device__ int g_pref[NB * SEQ];   // # visible keys with index <= t
__device__ int g_cnt[NB];
// vmean: two-stage deterministic reduction
__device__ float g_vpart[NHTOT * 8 * D_DIM];
__device__ float g_vmean[NHTOT * D_DIM];

#define SC 0.18033688f     // 0.125 * log2(e): softmax in log2 domain
#define NEGB (-1.5e9f)

// ---------------------------------------------------------------------------
// Helpers
// ---------------------------------------------------------------------------
__device__ __forceinline__ void mma_f16(float c[4], const uint32_t a[4],
                                        uint32_t b0, uint32_t b1) {
    asm("mma.sync.aligned.m16n8k16.row.col.f32.f16.f16.f32 "
        "{%0,%1,%2,%3}, {%4,%5,%6,%7}, {%8,%9}, {%0,%1,%2,%3};"
        : "+f"(c[0]), "+f"(c[1]), "+f"(c[2]), "+f"(c[3])
        : "r"(a[0]), "r"(a[1]), "r"(a[2]), "r"(a[3]), "r"(b0), "r"(b1));
}

__device__ __forceinline__ void ldmx4(uint32_t r[4], uint32_t addr) {
    asm volatile("ldmatrix.sync.aligned.m8n8.x4.shared.b16 {%0,%1,%2,%3}, [%4];"
                 : "=r"(r[0]), "=r"(r[1]), "=r"(r[2]), "=r"(r[3]) : "r"(addr));
}
__device__ __forceinline__ void ldmx4t(uint32_t r[4], uint32_t addr) {
    asm volatile("ldmatrix.sync.aligned.m8n8.x4.trans.shared.b16 {%0,%1,%2,%3}, [%4];"
                 : "=r"(r[0]), "=r"(r[1]), "=r"(r[2]), "=r"(r[3]) : "r"(addr));
}

__device__ __forceinline__ uint32_t smem_u32(const void* p) {
    uint32_t a;
    asm("{ .reg .u64 t; cvta.to.shared.u64 t, %1; cvt.u32.u64 %0, t; }"
        : "=r"(a) : "l"(p));
    return a;
}

__device__ __forceinline__ void cp16(uint32_t dst, const void* src) {
    asm volatile("cp.async.cg.shared.global [%0], [%1], 16;" :: "r"(dst), "l"(src));
}
#define CP_COMMIT() asm volatile("cp.async.commit_group;" ::: "memory")
#define CP_WAIT0() asm volatile("cp.async.wait_group 0;" ::: "memory")
#define CP_WAIT1() asm volatile("cp.async.wait_group 1;" ::: "memory")

__device__ __forceinline__ uint32_t pack_h(float x, float y) {
    __half2 h = __floats2half2_rn(x, y);
    return *reinterpret_cast<uint32_t*>(&h);
}

// ---------------------------------------------------------------------------
// Fused conversion: six fp32->fp16 tensors, one launch.
// ---------------------------------------------------------------------------
#define XB (XSZ / 4 / 256)
#define WB (WSZ / 4 / 256)

__global__ __launch_bounds__(256) void conv_all_kernel(
    const float* __restrict__ q, const float* __restrict__ k,
    const float* __restrict__ v, const float* __restrict__ wq,
    const float* __restrict__ wk, const float* __restrict__ wv)
{
    const int b = blockIdx.x;
    const float* src;
    __half* dst;
    int local;
    if (b < 3 * XB) {
        const int z = b / XB;
        local = b - z * XB;
        src = (z == 0) ? q : (z == 1) ? k : v;
        dst = g_xh + (size_t)z * XSZ;
    } else {
        const int bb = b - 3 * XB;
        const int z = bb / WB;
        local = bb - z * WB;
        src = (z == 0) ? wq : (z == 1) ? wk : wv;
        dst = g_wh + (size_t)z * WSZ;
    }
    const int i = local * 256 + threadIdx.x;
    float4 val = ((const float4*)src)[i];
    ((uint32_t*)dst)[2 * i + 0] = pack_h(val.x, val.y);
    ((uint32_t*)dst)[2 * i + 1] = pack_h(val.z, val.w);
}

// ---------------------------------------------------------------------------
// Prefix scan of pad mask -> g_pos / g_pref / g_cnt. One block per batch.
// ---------------------------------------------------------------------------
__global__ __launch_bounds__(1024) void scan_kernel(const int* __restrict__ pad)
{
    const int n = blockIdx.x;
    const int tid = threadIdx.x;
    const int lane = tid & 31;
    const int wid = tid >> 5;
    const int e0 = pad[n * SEQ + 2 * tid] != 0;
    const int e1 = pad[n * SEQ + 2 * tid + 1] != 0;
    const int s = e0 + e1;
    int v = s;
#pragma unroll
    for (int off = 1; off < 32; off <<= 1) {
        int t = __shfl_up_sync(0xffffffffu, v, off);
        if (lane >= off) v += t;
    }
    __shared__ int wsum[32];
    if (lane == 31) wsum[wid] = v;
    __syncthreads();
    if (wid == 0) {
        int t = wsum[lane];
#pragma unroll
        for (int off = 1; off < 32; off <<= 1) {
            int u = __shfl_up_sync(0xffffffffu, t, off);
            if (lane >= off) t += u;
        }
        wsum[lane] = t;
    }
    __syncthreads();
    const int total = wsum[31];
    const int incl = (wid ? wsum[wid - 1] : 0) + v;
    const int excl = incl - s;
    if (e0) g_pos[n * SEQ + excl] = 2 * tid;
    if (e1) g_pos[n * SEQ + excl + e0] = 2 * tid + 1;
    g_pref[n * SEQ + 2 * tid] = excl + e0;
    g_pref[n * SEQ + 2 * tid + 1] = incl;
    if (tid == 1023) g_cnt[n] = total;
    __syncthreads();
    for (int i = total + tid; i < SEQ; i += 1024)
        g_pos[n * SEQ + i] = (1 << 29);
}

// ---------------------------------------------------------------------------
// Gather visible K/V rows into compressed [nh][j][d]; tail zero-filled.
// grid (NHTOT, SEQ/64, 2), block 512.
// ---------------------------------------------------------------------------
__global__ __launch_bounds__(512) void gather_kernel()
{
    const int nh = blockIdx.x;
    const int nb = nh >> 4;
    const int j = blockIdx.y * 64 + (threadIdx.x >> 3);
    const int dseg = (threadIdx.x & 7) * 8;
    const int cnt = g_cnt[nb];
    const __half* src = blockIdx.z ? g_vh : g_kh;
    __half* dst = blockIdx.z ? g_vhc : g_khc;
    uint4 val = make_uint4(0, 0, 0, 0);
    if (j < cnt) {
        const int t = g_pos[nb * SEQ + j];
        val = *(const uint4*)(src + ((size_t)nh * SEQ + t) * D_DIM + dseg);
    }
    *(uint4*)(dst + ((size_t)nh * SEQ + j) * D_DIM + dseg) = val;
}

// ---------------------------------------------------------------------------
// Projection GEMM — R9/R11 structure VERBATIM; V row layout like Q/K.
// ---------------------------------------------------------------------------
__global__ __launch_bounds__(256) void proj_mma_kernel(
    const float* __restrict__ bq, const float* __restrict__ bk,
    const float* __restrict__ bv)
{
    __shared__ __half Ah[128][40];
    __shared__ __half Bh[128][40];

    const int tid = threadIdx.x;
    const int w = tid >> 5;
    const int lane = tid & 31;
    const int g = lane >> 2;
    const int tq = lane & 3;
    const int z = blockIdx.z;
    const int j0 = blockIdx.x * 128;
    const int i0 = blockIdx.y * 128;
    const int mrow = (w & 3) * 32;
    const int ncol = (w >> 2) * 64;

    const __half* xh = g_xh + (size_t)z * XSZ;
    const __half* wh = g_wh + (size_t)z * WSZ;
    const float* bias = (z == 0) ? bq : (z == 1) ? bk : bv;

    float c[2][8][4];
#pragma unroll
    for (int mt = 0; mt < 2; mt++)
#pragma unroll
        for (int nt = 0; nt < 8; nt++)
#pragma unroll
            for (int u = 0; u < 4; u++) c[mt][nt][u] = 0.0f;

    for (int k0 = 0; k0 < E_DIM; k0 += 32) {
#pragma unroll
        for (int it = 0; it < 2; it++) {
            const int idx = tid + it * 256;
            const int row = idx >> 2;
            const int seg = (idx & 3) * 8;
            const size_t ga = (size_t)(i0 + row) * E_DIM + k0 + seg;
            const size_t gb = (size_t)(j0 + row) * E_DIM + k0 + seg;
            *(uint4*)&Ah[row][seg] = *(const uint4*)(xh + ga);
            *(uint4*)&Bh[row][seg] = *(const uint4*)(wh + gb);
        }
        __syncthreads();

#pragma unroll
        for (int kc = 0; kc < 32; kc += 16) {
            uint32_t a[2][4];
#pragma unroll
            for (int mt = 0; mt < 2; mt++) {
                const int r0 = mrow + mt * 16 + g;
                a[mt][0] = *(const uint32_t*)&Ah[r0][kc + 2 * tq];
                a[mt][1] = *(const uint32_t*)&Ah[r0 + 8][kc + 2 * tq];
                a[mt][2] = *(const uint32_t*)&Ah[r0][kc + 2 * tq + 8];
                a[mt][3] = *(const uint32_t*)&Ah[r0 + 8][kc + 2 * tq + 8];
            }
#pragma unroll
            for (int nt = 0; nt < 8; nt++) {
                const int nr = ncol + nt * 8 + g;
                uint32_t b0 = *(const uint32_t*)&Bh[nr][kc + 2 * tq];
                uint32_t b1 = *(const uint32_t*)&Bh[nr][kc + 2 * tq + 8];
#pragma unroll
                for (int mt = 0; mt < 2; mt++)
                    mma_f16(c[mt][nt], a[mt], b0, b1);
            }
        }
        __syncthreads();
    }

#pragma unroll
    for (int mt = 0; mt < 2; mt++) {
#pragma unroll
        for (int nt = 0; nt < 8; nt++) {
            const int gj = j0 + ncol + nt * 8 + 2 * tq;
            const int h = gj >> 6;
            const int dd = gj & 63;
            const float b0v = bias[gj], b1v = bias[gj + 1];
            const int r0 = i0 + mrow + mt * 16 + g;
            const int r1 = r0 + 8;
            const float v00 = c[mt][nt][0] + b0v, v01 = c[mt][nt][1] + b1v;
            const float v10 = c[mt][nt][2] + b0v, v11 = c[mt][nt][3] + b1v;
            __half* dst = (z == 0) ? g_qh : (z == 1) ? g_kh : g_vh;
            const size_t a0 =
                ((size_t)((r0 >> 11) * H_DIM + h) * SEQ + (r0 & 2047)) * D_DIM + dd;
            const size_t a1 =
                ((size_t)((r1 >> 11) * H_DIM + h) * SEQ + (r1 & 2047)) * D_DIM + dd;
            *(uint32_t*)(dst + a0) = pack_h(v00, v01);
            *(uint32_t*)(dst + a1) = pack_h(v10, v11);
        }
    }
}

// ---------------------------------------------------------------------------
// vmean stage 1: grid (NHTOT, 8). Each block sums a 256-row t-slab with
// coalesced reads; partial -> g_vpart[nh][slab][dd]. Deterministic.
// ---------------------------------------------------------------------------
__global__ __launch_bounds__(256) void vmean1_kernel()
{
    __shared__ float red[256];
    const int nh = blockIdx.x;
    const int slab = blockIdx.y;
    const int dd = threadIdx.x & 63;
    const int part = threadIdx.x >> 6;
    float sum = 0.0f;
    const int t0 = slab * 256 + part * 64;
    for (int t = t0; t < t0 + 64; t++)
        sum += __half2float(g_vh[((size_t)nh * SEQ + t) * D_DIM + dd]);
    red[threadIdx.x] = sum;
    __syncthreads();
    if (part == 0) {
        float tot = red[dd] + red[64 + dd] + red[128 + dd] + red[192 + dd];
        g_vpart[(nh * 8 + slab) * D_DIM + dd] = tot;
    }
}

// vmean stage 2: grid NHTOT, 64 threads; fixed-order fold of 8 partials.
__global__ __launch_bounds__(64) void vmean2_kernel()
{
    const int nh = blockIdx.x;
    const int dd = threadIdx.x;
    float tot = 0.0f;
#pragma unroll
    for (int s = 0; s < 8; s++)
        tot += g_vpart[(nh * 8 + s) * D_DIM + dd];
    g_vmean[nh * D_DIM + dd] = tot * (1.0f / (float)SEQ);
}

// ---------------------------------------------------------------------------
// Flash attention on compressed keys — R13 kernel VERBATIM.
// ---------------------------------------------------------------------------
#define AT_STRIDE 72
#define AT_T (64 * AT_STRIDE)
#define AT_BUF (2 * AT_T)
#define AT_POS_OFF (2 * AT_BUF * 2)
#define AT_SMEM (AT_POS_OFF + 2 * 64 * 4)

__global__ __launch_bounds__(256) void attn_mma_kernel(float* __restrict__ out)
{
    extern __shared__ __half smh[];
    const uint32_t smb = smem_u32(smh);

    const int tid = threadIdx.x;
    const int w = tid >> 5;
    const int lane = tid & 31;
    const int g = lane >> 2;
    const int tq = lane & 3;
    const int qt = (int)(gridDim.x - 1 - blockIdx.x);
    const int nh = blockIdx.y;
    const int nb = nh >> 4;
    const int h = nh & 15;
    const int i0 = qt * 128;
    const int qr0 = i0 + w * 16 + g;
    const int qr1 = qr0 + 8;

    const uint32_t lcoK =
        (uint32_t)((((lane >> 4) & 1) * 8 + (lane & 7)) * AT_STRIDE +
                   ((lane >> 3) & 1) * 8);
    const uint32_t lcoV =
        (uint32_t)(((lane & 7) + ((lane >> 3) & 1) * 8) * AT_STRIDE +
                   ((lane >> 4) & 1) * 8);

    uint32_t qf[4][4];
    {
        const size_t b0 = ((size_t)nh * SEQ + qr0) * D_DIM;
        const size_t b1 = ((size_t)nh * SEQ + qr1) * D_DIM;
#pragma unroll
        for (int kd = 0; kd < 4; kd++) {
            const int cO = kd * 16 + 2 * tq;
            qf[kd][0] = *(const uint32_t*)(g_qh + b0 + cO);
            qf[kd][1] = *(const uint32_t*)(g_qh + b1 + cO);
            qf[kd][2] = *(const uint32_t*)(g_qh + b0 + cO + 8);
            qf[kd][3] = *(const uint32_t*)(g_qh + b1 + cO + 8);
        }
    }

    auto load_tiles = [&](int buf, int t0) {
        const uint32_t base = smb + buf * (AT_BUF * 2);
        const __half* kh = g_khc + ((size_t)nh * SEQ + t0) * D_DIM;
        const __half* vh = g_vhc + ((size_t)nh * SEQ + t0) * D_DIM;
#pragma unroll
        for (int it = 0; it < 2; it++) {
            const int idx = tid + it * 256;
            const int row = idx >> 3;
            const int seg = (idx & 7) * 8;
            const uint32_t so = (uint32_t)(row * AT_STRIDE + seg) * 2;
            cp16(base + 0 * AT_T * 2 + so, kh + (size_t)row * D_DIM + seg);
            cp16(base + 1 * AT_T * 2 + so, vh + (size_t)row * D_DIM + seg);
        }
        if (tid < 16)
            cp16(smb + AT_POS_OFF + buf * 256 + tid * 16,
                 g_pos + nb * SEQ + t0 + tid * 4);
        CP_COMMIT();
    };

    float o[8][4];
#pragma unroll
    for (int dt = 0; dt < 8; dt++)
#pragma unroll
        for (int u = 0; u < 4; u++) o[dt][u] = 0.0f;
    float m0 = -1e9f, m1 = -1e9f, l0 = 0.0f, l1 = 0.0f;

    const int nvis = g_pref[nb * SEQ + i0 + 127];
    const int ntiles = (nvis + 63) >> 6;

    if (ntiles > 0) {
        load_tiles(0, 0);

        for (int j = 0; j < ntiles; j++) {
            if (j < ntiles - 1) load_tiles((j + 1) & 1, (j + 1) * 64);
            if (j < ntiles - 1) { CP_WAIT1(); } else { CP_WAIT0(); }
            __syncthreads();

            const uint32_t Kb = smb + (j & 1) * (AT_BUF * 2);
            const uint32_t Vb = Kb + AT_T * 2;
            const int* posS =
                (const int*)((const char*)smh + AT_POS_OFF + (j & 1) * 256);

            float s[8][4];
#pragma unroll
            for (int nt = 0; nt < 8; nt++)
#pragma unroll
                for (int u = 0; u < 4; u++) s[nt][u] = 0.0f;

#pragma unroll
            for (int kd = 0; kd < 4; kd++) {
#pragma unroll
                for (int p = 0; p < 4; p++) {
                    uint32_t kb[4];
                    ldmx4(kb, Kb + (uint32_t)(p * 16 * AT_STRIDE + kd * 16) * 2 +
                                  lcoK * 2);
                    mma_f16(s[2 * p], qf[kd], kb[0], kb[1]);
                    mma_f16(s[2 * p + 1], qf[kd], kb[2], kb[3]);
                }
            }

            const bool slow = (posS[63] > i0 + w * 16);
            if (!slow) {
#pragma unroll
                for (int nt = 0; nt < 8; nt++)
#pragma unroll
                    for (int u = 0; u < 4; u++) s[nt][u] *= SC;
            } else {
#pragma unroll
                for (int nt = 0; nt < 8; nt++) {
                    const int c0 = nt * 8 + 2 * tq;
#pragma unroll
                    for (int u = 0; u < 4; u++) {
                        const int cl = c0 + (u & 1);
                        const int qrow = (u < 2) ? qr0 : qr1;
                        float v = s[nt][u] * SC;
                        if (posS[cl] > qrow) v = NEGB;
                        s[nt][u] = v;
                    }
                }
            }

            float mx0 = -1e30f, mx1 = -1e30f;
#pragma unroll
            for (int nt = 0; nt < 8; nt++) {
                mx0 = fmaxf(mx0, fmaxf(s[nt][0], s[nt][1]));
                mx1 = fmaxf(mx1, fmaxf(s[nt][2], s[nt][3]));
            }
#pragma unroll
            for (int off = 1; off <= 2; off <<= 1) {
                mx0 = fmaxf(mx0, __shfl_xor_sync(0xffffffffu, mx0, off));
                mx1 = fmaxf(mx1, __shfl_xor_sync(0xffffffffu, mx1, off));
            }
            const float mn0 = fmaxf(m0, mx0), mn1 = fmaxf(m1, mx1);
            const float cr0 = exp2f(m0 - mn0), cr1 = exp2f(m1 - mn1);
            float rs0 = 0.0f, rs1 = 0.0f;
#pragma unroll
            for (int nt = 0; nt < 8; nt++) {
                s[nt][0] = exp2f(s[nt][0] - mn0);
                s[nt][1] = exp2f(s[nt][1] - mn0);
                s[nt][2] = exp2f(s[nt][2] - mn1);
                s[nt][3] = exp2f(s[nt][3] - mn1);
                rs0 += s[nt][0] + s[nt][1];
                rs1 += s[nt][2] + s[nt][3];
            }
#pragma unroll
            for (int off = 1; off <= 2; off <<= 1) {
                rs0 += __shfl_xor_sync(0xffffffffu, rs0, off);
                rs1 += __shfl_xor_sync(0xffffffffu, rs1, off);
            }
            l0 = l0 * cr0 + rs0;
            l1 = l1 * cr1 + rs1;
            m0 = mn0;
            m1 = mn1;
#pragma unroll
            for (int dt = 0; dt < 8; dt++) {
                o[dt][0] *= cr0; o[dt][1] *= cr0;
                o[dt][2] *= cr1; o[dt][3] *= cr1;
            }

#pragma unroll
            for (int kc = 0; kc < 4; kc++) {
                uint32_t ph[4];
                ph[0] = pack_h(s[2 * kc][0], s[2 * kc][1]);
                ph[1] = pack_h(s[2 * kc][2], s[2 * kc][3]);
                ph[2] = pack_h(s[2 * kc + 1][0], s[2 * kc + 1][1]);
                ph[3] = pack_h(s[2 * kc + 1][2], s[2 * kc + 1][3]);
#pragma unroll
                for (int dp = 0; dp < 4; dp++) {
                    uint32_t vb[4];
                    ldmx4t(vb, Vb + (uint32_t)(kc * 16 * AT_STRIDE + dp * 16) * 2 +
                                   lcoV * 2);
                    mma_f16(o[2 * dp], ph, vb[0], vb[1]);
                    mma_f16(o[2 * dp + 1], ph, vb[2], vb[3]);
                }
            }
            __syncthreads();
        }
    }

    const float inv0 = 1.0f / l0, inv1 = 1.0f / l1;
    const bool dg0 = (m0 < -5e8f), dg1 = (m1 < -5e8f);
#pragma unroll
    for (int dt = 0; dt < 8; dt++) {
        const int dd = dt * 8 + 2 * tq;
        float o00 = dg0 ? g_vmean[nh * D_DIM + dd] : o[dt][0] * inv0;
        float o01 = dg0 ? g_vmean[nh * D_DIM + dd + 1] : o[dt][1] * inv0;
        float o10 = dg1 ? g_vmean[nh * D_DIM + dd] : o[dt][2] * inv1;
        float o11 = dg1 ? g_vmean[nh * D_DIM + dd + 1] : o[dt][3] * inv1;
        float2* p0 = (float2*)(out + ((size_t)(nb * SEQ + qr0)) * E_DIM + h * D_DIM + dd);
        float2* p1 = (float2*)(out + ((size_t)(nb * SEQ + qr1)) * E_DIM + h * D_DIM + dd);
        *p0 = make_float2(o00, o01);
        *p1 = make_float2(o10, o11);
    }
}

// ---------------------------------------------------------------------------
// Launch
// ---------------------------------------------------------------------------
extern "C" void kernel_launch(void* const* d_in, const int* in_sizes, int n_in,
                              void* d_out, int out_size)
{
    const float* query = (const float*)d_in[0];
    const float* key   = (const float*)d_in[1];
    const float* value = (const float*)d_in[2];
    const int*   pad   = (const int*)d_in[3];
    const float* Wq = (const float*)d_in[5];
    const float* bq = (const float*)d_in[6];
    const float* Wk = (const float*)d_in[7];
    const float* bk = (const float*)d_in[8];
    const float* Wv = (const float*)d_in[9];
    const float* bv = (const float*)d_in[10];
    float* out = (float*)d_out;

    conv_all_kernel<<<3 * XB + 3 * WB, 256>>>(query, key, value, Wq, Wk, Wv);
    scan_kernel<<<NB, 1024>>>(pad);

    dim3 pgrid(E_DIM / 128, (NB * SEQ) / 128, 3);
    proj_mma_kernel<<<pgrid, 256>>>(bq, bk, bv);

    dim3 v1grid(NHTOT, 8);
    vmean1_kernel<<<v1grid, 256>>>();
    vmean2_kernel<<<NHTOT, 64>>>();

    dim3 ggrid(NHTOT, SEQ / 64, 2);
    gather_kernel<<<ggrid, 512>>>();

    cudaFuncSetAttribute(attn_mma_kernel, cudaFuncAttributeMaxDynamicSharedMemorySize,
                         AT_SMEM);
    dim3 agrid(SEQ / 128, NHTOT);
    attn_mma_kernel<<<agrid, 256, AT_SMEM>>>(out);
}

// round 15
// speedup vs baseline: 7.1756x; 1.0450x over previous
#include <cuda_runtime.h>
#include <cuda_fp16.h>
#include <cstdint>

#define E_DIM 1024
#define H_DIM 16
#define D_DIM 64
#define SEQ 2048
#define NB 2
#define NHTOT (NB * H_DIM)
#define XSZ (NB * SEQ * E_DIM)
#define WSZ (E_DIM * E_DIM)
#define QKV_SZ (NHTOT * SEQ * D_DIM)

// Single fp16 inputs
__device__ __half g_xh[3 * XSZ];
__device__ __half g_wh[3 * WSZ];
// Q full [nh][t][d]; V full [nh][t][d] (for vmean); K/V compressed [nh][j][d]
__device__ __half g_qh[QKV_SZ];
__device__ __half g_vh[QKV_SZ];
__device__ __half g_khc[QKV_SZ];   // tail rows stay zero (never written)
__device__ __half g_vhc[QKV_SZ];
// Compression metadata
__device__ int g_pos[NB * SEQ];    // original t of j-th visible key (tail = 1<<29)
__device__ int g_pref[NB * SEQ];   // # visible keys with index <= t
__device__ int g_slot[NB * SEQ];   // compressed slot of row t, or -1 if masked
// vmean two-stage
__device__ float g_vpart[NHTOT * 8 * D_DIM];
__device__ float g_vmean[NHTOT * D_DIM];

#define SC 0.18033688f     // 0.125 * log2(e)
#define NEGB (-1.5e9f)

// ---------------------------------------------------------------------------
// Helpers
// ---------------------------------------------------------------------------
__device__ __forceinline__ void mma_f16(float c[4], const uint32_t a[4],
                                        uint32_t b0, uint32_t b1) {
    asm("mma.sync.aligned.m16n8k16.row.col.f32.f16.f16.f32 "
        "{%0,%1,%2,%3}, {%4,%5,%6,%7}, {%8,%9}, {%0,%1,%2,%3};"
        : "+f"(c[0]), "+f"(c[1]), "+f"(c[2]), "+f"(c[3])
        : "r"(a[0]), "r"(a[1]), "r"(a[2]), "r"(a[3]), "r"(b0), "r"(b1));
}

__device__ __forceinline__ void ldmx4(uint32_t r[4], uint32_t addr) {
    asm volatile("ldmatrix.sync.aligned.m8n8.x4.shared.b16 {%0,%1,%2,%3}, [%4];"
                 : "=r"(r[0]), "=r"(r[1]), "=r"(r[2]), "=r"(r[3]) : "r"(addr));
}
__device__ __forceinline__ void ldmx4t(uint32_t r[4], uint32_t addr) {
    asm volatile("ldmatrix.sync.aligned.m8n8.x4.trans.shared.b16 {%0,%1,%2,%3}, [%4];"
                 : "=r"(r[0]), "=r"(r[1]), "=r"(r[2]), "=r"(r[3]) : "r"(addr));
}

__device__ __forceinline__ uint32_t smem_u32(const void* p) {
    uint32_t a;
    asm("{ .reg .u64 t; cvta.to.shared.u64 t, %1; cvt.u32.u64 %0, t; }"
        : "=r"(a) : "l"(p));
    return a;
}

__device__ __forceinline__ void cp16(uint32_t dst, const void* src) {
    asm volatile("cp.async.cg.shared.global [%0], [%1], 16;" :: "r"(dst), "l"(src));
}
#define CP_COMMIT() asm volatile("cp.async.commit_group;" ::: "memory")
#define CP_WAIT0() asm volatile("cp.async.wait_group 0;" ::: "memory")
#define CP_WAIT1() asm volatile("cp.async.wait_group 1;" ::: "memory")

__device__ __forceinline__ uint32_t pack_h(float x, float y) {
    __half2 h = __floats2half2_rn(x, y);
    return *reinterpret_cast<uint32_t*>(&h);
}

// ---------------------------------------------------------------------------
// Fused conversion: six fp32->fp16 tensors; 2 float4 per thread.
// ---------------------------------------------------------------------------
#define XB (XSZ / 8 / 256)   // 2048 blocks per X tensor
#define WB (WSZ / 8 / 256)   // 512 blocks per W tensor

__global__ __launch_bounds__(256) void conv_all_kernel(
    const float* __restrict__ q, const float* __restrict__ k,
    const float* __restrict__ v, const float* __restrict__ wq,
    const float* __restrict__ wk, const float* __restrict__ wv)
{
    const int b = blockIdx.x;
    const float* src;
    __half* dst;
    int local;
    if (b < 3 * XB) {
        const int z = b / XB;
        local = b - z * XB;
        src = (z == 0) ? q : (z == 1) ? k : v;
        dst = g_xh + (size_t)z * XSZ;
    } else {
        const int bb = b - 3 * XB;
        const int z = bb / WB;
        local = bb - z * WB;
        src = (z == 0) ? wq : (z == 1) ? wk : wv;
        dst = g_wh + (size_t)z * WSZ;
    }
#pragma unroll
    for (int r = 0; r < 2; r++) {
        const int i = local * 512 + r * 256 + threadIdx.x;
        float4 val = ((const float4*)src)[i];
        ((uint32_t*)dst)[2 * i + 0] = pack_h(val.x, val.y);
        ((uint32_t*)dst)[2 * i + 1] = pack_h(val.z, val.w);
    }
}

// ---------------------------------------------------------------------------
// Prefix scan of pad mask -> g_pos / g_pref / g_slot. One block per batch.
// ---------------------------------------------------------------------------
__global__ __launch_bounds__(1024) void scan_kernel(const int* __restrict__ pad)
{
    const int n = blockIdx.x;
    const int tid = threadIdx.x;
    const int lane = tid & 31;
    const int wid = tid >> 5;
    const int e0 = pad[n * SEQ + 2 * tid] != 0;
    const int e1 = pad[n * SEQ + 2 * tid + 1] != 0;
    const int s = e0 + e1;
    int v = s;
#pragma unroll
    for (int off = 1; off < 32; off <<= 1) {
        int t = __shfl_up_sync(0xffffffffu, v, off);
        if (lane >= off) v += t;
    }
    __shared__ int wsum[32];
    if (lane == 31) wsum[wid] = v;
    __syncthreads();
    if (wid == 0) {
        int t = wsum[lane];
#pragma unroll
        for (int off = 1; off < 32; off <<= 1) {
            int u = __shfl_up_sync(0xffffffffu, t, off);
            if (lane >= off) t += u;
        }
        wsum[lane] = t;
    }
    __syncthreads();
    const int total = wsum[31];
    const int incl = (wid ? wsum[wid - 1] : 0) + v;
    const int excl = incl - s;
    if (e0) g_pos[n * SEQ + excl] = 2 * tid;
    if (e1) g_pos[n * SEQ + excl + e0] = 2 * tid + 1;
    g_pref[n * SEQ + 2 * tid] = excl + e0;
    g_pref[n * SEQ + 2 * tid + 1] = incl;
    g_slot[n * SEQ + 2 * tid] = e0 ? excl : -1;
    g_slot[n * SEQ + 2 * tid + 1] = e1 ? (excl + e0) : -1;
    __syncthreads();
    for (int i = total + tid; i < SEQ; i += 1024)
        g_pos[n * SEQ + i] = (1 << 29);
}

// ---------------------------------------------------------------------------
// Projection GEMM — mainloop VERBATIM; epilogue scatters K/V directly into
// compressed layout (K has no full copy; V keeps full copy for vmean).
// ---------------------------------------------------------------------------
__global__ __launch_bounds__(256) void proj_mma_kernel(
    const float* __restrict__ bq, const float* __restrict__ bk,
    const float* __restrict__ bv)
{
    __shared__ __half Ah[128][40];
    __shared__ __half Bh[128][40];

    const int tid = threadIdx.x;
    const int w = tid >> 5;
    const int lane = tid & 31;
    const int g = lane >> 2;
    const int tq = lane & 3;
    const int z = blockIdx.z;
    const int j0 = blockIdx.x * 128;
    const int i0 = blockIdx.y * 128;
    const int mrow = (w & 3) * 32;
    const int ncol = (w >> 2) * 64;

    const __half* xh = g_xh + (size_t)z * XSZ;
    const __half* wh = g_wh + (size_t)z * WSZ;
    const float* bias = (z == 0) ? bq : (z == 1) ? bk : bv;

    float c[2][8][4];
#pragma unroll
    for (int mt = 0; mt < 2; mt++)
#pragma unroll
        for (int nt = 0; nt < 8; nt++)
#pragma unroll
            for (int u = 0; u < 4; u++) c[mt][nt][u] = 0.0f;

    for (int k0 = 0; k0 < E_DIM; k0 += 32) {
#pragma unroll
        for (int it = 0; it < 2; it++) {
            const int idx = tid + it * 256;
            const int row = idx >> 2;
            const int seg = (idx & 3) * 8;
            const size_t ga = (size_t)(i0 + row) * E_DIM + k0 + seg;
            const size_t gb = (size_t)(j0 + row) * E_DIM + k0 + seg;
            *(uint4*)&Ah[row][seg] = *(const uint4*)(xh + ga);
            *(uint4*)&Bh[row][seg] = *(const uint4*)(wh + gb);
        }
        __syncthreads();

#pragma unroll
        for (int kc = 0; kc < 32; kc += 16) {
            uint32_t a[2][4];
#pragma unroll
            for (int mt = 0; mt < 2; mt++) {
                const int r0 = mrow + mt * 16 + g;
                a[mt][0] = *(const uint32_t*)&Ah[r0][kc + 2 * tq];
                a[mt][1] = *(const uint32_t*)&Ah[r0 + 8][kc + 2 * tq];
                a[mt][2] = *(const uint32_t*)&Ah[r0][kc + 2 * tq + 8];
                a[mt][3] = *(const uint32_t*)&Ah[r0 + 8][kc + 2 * tq + 8];
            }
#pragma unroll
            for (int nt = 0; nt < 8; nt++) {
                const int nr = ncol + nt * 8 + g;
                uint32_t b0 = *(const uint32_t*)&Bh[nr][kc + 2 * tq];
                uint32_t b1 = *(const uint32_t*)&Bh[nr][kc + 2 * tq + 8];
#pragma unroll
                for (int mt = 0; mt < 2; mt++)
                    mma_f16(c[mt][nt], a[mt], b0, b1);
            }
        }
        __syncthreads();
    }

    // Epilogue with direct compressed scatter for K/V
#pragma unroll
    for (int mt = 0; mt < 2; mt++) {
        const int r0 = i0 + mrow + mt * 16 + g;
        const int r1 = r0 + 8;
        const int n0 = r0 >> 11, t0a = r0 & 2047;
        const int n1 = r1 >> 11, t1a = r1 & 2047;
        int sl0 = 0, sl1 = 0;
        if (z >= 1) {
            sl0 = g_slot[n0 * SEQ + t0a];
            sl1 = g_slot[n1 * SEQ + t1a];
        }
#pragma unroll
        for (int nt = 0; nt < 8; nt++) {
            const int gj = j0 + ncol + nt * 8 + 2 * tq;
            const int h = gj >> 6;
            const int dd = gj & 63;
            const float b0v = bias[gj], b1v = bias[gj + 1];
            const float v00 = c[mt][nt][0] + b0v, v01 = c[mt][nt][1] + b1v;
            const float v10 = c[mt][nt][2] + b0v, v11 = c[mt][nt][3] + b1v;
            if (z == 0) {
                const size_t a0 = ((size_t)(n0 * H_DIM + h) * SEQ + t0a) * D_DIM + dd;
                const size_t a1 = ((size_t)(n1 * H_DIM + h) * SEQ + t1a) * D_DIM + dd;
                *(uint32_t*)(g_qh + a0) = pack_h(v00, v01);
                *(uint32_t*)(g_qh + a1) = pack_h(v10, v11);
            } else if (z == 1) {
                if (sl0 >= 0)
                    *(uint32_t*)(g_khc + ((size_t)(n0 * H_DIM + h) * SEQ + sl0) * D_DIM + dd) =
                        pack_h(v00, v01);
                if (sl1 >= 0)
                    *(uint32_t*)(g_khc + ((size_t)(n1 * H_DIM + h) * SEQ + sl1) * D_DIM + dd) =
                        pack_h(v10, v11);
            } else {
                const size_t a0 = ((size_t)(n0 * H_DIM + h) * SEQ + t0a) * D_DIM + dd;
                const size_t a1 = ((size_t)(n1 * H_DIM + h) * SEQ + t1a) * D_DIM + dd;
                const uint32_t p0 = pack_h(v00, v01);
                const uint32_t p1 = pack_h(v10, v11);
                *(uint32_t*)(g_vh + a0) = p0;
                *(uint32_t*)(g_vh + a1) = p1;
                if (sl0 >= 0)
                    *(uint32_t*)(g_vhc + ((size_t)(n0 * H_DIM + h) * SEQ + sl0) * D_DIM + dd) = p0;
                if (sl1 >= 0)
                    *(uint32_t*)(g_vhc + ((size_t)(n1 * H_DIM + h) * SEQ + sl1) * D_DIM + dd) = p1;
            }
        }
    }
}

// ---------------------------------------------------------------------------
// vmean stage 1/2 (R14, unchanged)
// ---------------------------------------------------------------------------
__global__ __launch_bounds__(256) void vmean1_kernel()
{
    __shared__ float red[256];
    const int nh = blockIdx.x;
    const int slab = blockIdx.y;
    const int dd = threadIdx.x & 63;
    const int part = threadIdx.x >> 6;
    float sum = 0.0f;
    const int t0 = slab * 256 + part * 64;
    for (int t = t0; t < t0 + 64; t++)
        sum += __half2float(g_vh[((size_t)nh * SEQ + t) * D_DIM + dd]);
    red[threadIdx.x] = sum;
    __syncthreads();
    if (part == 0) {
        float tot = red[dd] + red[64 + dd] + red[128 + dd] + red[192 + dd];
        g_vpart[(nh * 8 + slab) * D_DIM + dd] = tot;
    }
}

__global__ __launch_bounds__(64) void vmean2_kernel()
{
    const int nh = blockIdx.x;
    const int dd = threadIdx.x;
    float tot = 0.0f;
#pragma unroll
    for (int s = 0; s < 8; s++)
        tot += g_vpart[(nh * 8 + s) * D_DIM + dd];
    g_vmean[nh * D_DIM + dd] = tot * (1.0f / (float)SEQ);
}

// ---------------------------------------------------------------------------
// Flash attention on compressed keys — R13/R14 kernel VERBATIM.
// ---------------------------------------------------------------------------
#define AT_STRIDE 72
#define AT_T (64 * AT_STRIDE)
#define AT_BUF (2 * AT_T)
#define AT_POS_OFF (2 * AT_BUF * 2)
#define AT_SMEM (AT_POS_OFF + 2 * 64 * 4)

__global__ __launch_bounds__(256) void attn_mma_kernel(float* __restrict__ out)
{
    extern __shared__ __half smh[];
    const uint32_t smb = smem_u32(smh);

    const int tid = threadIdx.x;
    const int w = tid >> 5;
    const int lane = tid & 31;
    const int g = lane >> 2;
    const int tq = lane & 3;
    const int qt = (int)(gridDim.x - 1 - blockIdx.x);
    const int nh = blockIdx.y;
    const int nb = nh >> 4;
    const int h = nh & 15;
    const int i0 = qt * 128;
    const int qr0 = i0 + w * 16 + g;
    const int qr1 = qr0 + 8;

    const uint32_t lcoK =
        (uint32_t)((((lane >> 4) & 1) * 8 + (lane & 7)) * AT_STRIDE +
                   ((lane >> 3) & 1) * 8);
    const uint32_t lcoV =
        (uint32_t)(((lane & 7) + ((lane >> 3) & 1) * 8) * AT_STRIDE +
                   ((lane >> 4) & 1) * 8);

    uint32_t qf[4][4];
    {
        const size_t b0 = ((size_t)nh * SEQ + qr0) * D_DIM;
        const size_t b1 = ((size_t)nh * SEQ + qr1) * D_DIM;
#pragma unroll
        for (int kd = 0; kd < 4; kd++) {
            const int cO = kd * 16 + 2 * tq;
            qf[kd][0] = *(const uint32_t*)(g_qh + b0 + cO);
            qf[kd][1] = *(const uint32_t*)(g_qh + b1 + cO);
            qf[kd][2] = *(const uint32_t*)(g_qh + b0 + cO + 8);
            qf[kd][3] = *(const uint32_t*)(g_qh + b1 + cO + 8);
        }
    }

    auto load_tiles = [&](int buf, int t0) {
        const uint32_t base = smb + buf * (AT_BUF * 2);
        const __half* kh = g_khc + ((size_t)nh * SEQ + t0) * D_DIM;
        const __half* vh = g_vhc + ((size_t)nh * SEQ + t0) * D_DIM;
#pragma unroll
        for (int it = 0; it < 2; it++) {
            const int idx = tid + it * 256;
            const int row = idx >> 3;
            const int seg = (idx & 7) * 8;
            const uint32_t so = (uint32_t)(row * AT_STRIDE + seg) * 2;
            cp16(base + 0 * AT_T * 2 + so, kh + (size_t)row * D_DIM + seg);
            cp16(base + 1 * AT_T * 2 + so, vh + (size_t)row * D_DIM + seg);
        }
        if (tid < 16)
            cp16(smb + AT_POS_OFF + buf * 256 + tid * 16,
                 g_pos + nb * SEQ + t0 + tid * 4);
        CP_COMMIT();
    };

    float o[8][4];
#pragma unroll
    for (int dt = 0; dt < 8; dt++)
#pragma unroll
        for (int u = 0; u < 4; u++) o[dt][u] = 0.0f;
    float m0 = -1e9f, m1 = -1e9f, l0 = 0.0f, l1 = 0.0f;

    const int nvis = g_pref[nb * SEQ + i0 + 127];
    const int ntiles = (nvis + 63) >> 6;

    if (ntiles > 0) {
        load_tiles(0, 0);

        for (int j = 0; j < ntiles; j++) {
            if (j < ntiles - 1) load_tiles((j + 1) & 1, (j + 1) * 64);
            if (j < ntiles - 1) { CP_WAIT1(); } else { CP_WAIT0(); }
            __syncthreads();

            const uint32_t Kb = smb + (j & 1) * (AT_BUF * 2);
            const uint32_t Vb = Kb + AT_T * 2;
            const int* posS =
                (const int*)((const char*)smh + AT_POS_OFF + (j & 1) * 256);

            float s[8][4];
#pragma unroll
            for (int nt = 0; nt < 8; nt++)
#pragma unroll
                for (int u = 0; u < 4; u++) s[nt][u] = 0.0f;

#pragma unroll
            for (int kd = 0; kd < 4; kd++) {
#pragma unroll
                for (int p = 0; p < 4; p++) {
                    uint32_t kb[4];
                    ldmx4(kb, Kb + (uint32_t)(p * 16 * AT_STRIDE + kd * 16) * 2 +
                                  lcoK * 2);
                    mma_f16(s[2 * p], qf[kd], kb[0], kb[1]);
                    mma_f16(s[2 * p + 1], qf[kd], kb[2], kb[3]);
                }
            }

            const bool slow = (posS[63] > i0 + w * 16);
            if (!slow) {
#pragma unroll
                for (int nt = 0; nt < 8; nt++)
#pragma unroll
                    for (int u = 0; u < 4; u++) s[nt][u] *= SC;
            } else {
#pragma unroll
                for (int nt = 0; nt < 8; nt++) {
                    const int c0 = nt * 8 + 2 * tq;
#pragma unroll
                    for (int u = 0; u < 4; u++) {
                        const int cl = c0 + (u & 1);
                        const int qrow = (u < 2) ? qr0 : qr1;
                        float v = s[nt][u] * SC;
                        if (posS[cl] > qrow) v = NEGB;
                        s[nt][u] = v;
                    }
                }
            }

            float mx0 = -1e30f, mx1 = -1e30f;
#pragma unroll
            for (int nt = 0; nt < 8; nt++) {
                mx0 = fmaxf(mx0, fmaxf(s[nt][0], s[nt][1]));
                mx1 = fmaxf(mx1, fmaxf(s[nt][2], s[nt][3]));
            }
#pragma unroll
            for (int off = 1; off <= 2; off <<= 1) {
                mx0 = fmaxf(mx0, __shfl_xor_sync(0xffffffffu, mx0, off));
                mx1 = fmaxf(mx1, __shfl_xor_sync(0xffffffffu, mx1, off));
            }
            const float mn0 = fmaxf(m0, mx0), mn1 = fmaxf(m1, mx1);
            const float cr0 = exp2f(m0 - mn0), cr1 = exp2f(m1 - mn1);
            float rs0 = 0.0f, rs1 = 0.0f;
#pragma unroll
            for (int nt = 0; nt < 8; nt++) {
                s[nt][0] = exp2f(s[nt][0] - mn0);
                s[nt][1] = exp2f(s[nt][1] - mn0);
                s[nt][2] = exp2f(s[nt][2] - mn1);
                s[nt][3] = exp2f(s[nt][3] - mn1);
                rs0 += s[nt][0] + s[nt][1];
                rs1 += s[nt][2] + s[nt][3];
            }
#pragma unroll
            for (int off = 1; off <= 2; off <<= 1) {
                rs0 += __shfl_xor_sync(0xffffffffu, rs0, off);
                rs1 += __shfl_xor_sync(0xffffffffu, rs1, off);
            }
            l0 = l0 * cr0 + rs0;
            l1 = l1 * cr1 + rs1;
            m0 = mn0;
            m1 = mn1;
#pragma unroll
            for (int dt = 0; dt < 8; dt++) {
                o[dt][0] *= cr0; o[dt][1] *= cr0;
                o[dt][2] *= cr1; o[dt][3] *= cr1;
            }

#pragma unroll
            for (int kc = 0; kc < 4; kc++) {
                uint32_t ph[4];
                ph[0] = pack_h(s[2 * kc][0], s[2 * kc][1]);
                ph[1] = pack_h(s[2 * kc][2], s[2 * kc][3]);
                ph[2] = pack_h(s[2 * kc + 1][0], s[2 * kc + 1][1]);
                ph[3] = pack_h(s[2 * kc + 1][2], s[2 * kc + 1][3]);
#pragma unroll
                for (int dp = 0; dp < 4; dp++) {
                    uint32_t vb[4];
                    ldmx4t(vb, Vb + (uint32_t)(kc * 16 * AT_STRIDE + dp * 16) * 2 +
                                   lcoV * 2);
                    mma_f16(o[2 * dp], ph, vb[0], vb[1]);
                    mma_f16(o[2 * dp + 1], ph, vb[2], vb[3]);
                }
            }
            __syncthreads();
        }
    }

    const float inv0 = 1.0f / l0, inv1 = 1.0f / l1;
    const bool dg0 = (m0 < -5e8f), dg1 = (m1 < -5e8f);
#pragma unroll
    for (int dt = 0; dt < 8; dt++) {
        const int dd = dt * 8 + 2 * tq;
        float o00 = dg0 ? g_vmean[nh * D_DIM + dd] : o[dt][0] * inv0;
        float o01 = dg0 ? g_vmean[nh * D_DIM + dd + 1] : o[dt][1] * inv0;
        float o10 = dg1 ? g_vmean[nh * D_DIM + dd] : o[dt][2] * inv1;
        float o11 = dg1 ? g_vmean[nh * D_DIM + dd + 1] : o[dt][3] * inv1;
        float2* p0 = (float2*)(out + ((size_t)(nb * SEQ + qr0)) * E_DIM + h * D_DIM + dd);
        float2* p1 = (float2*)(out + ((size_t)(nb * SEQ + qr1)) * E_DIM + h * D_DIM + dd);
        *p0 = make_float2(o00, o01);
        *p1 = make_float2(o10, o11);
    }
}

// ---------------------------------------------------------------------------
// Launch
// ---------------------------------------------------------------------------
extern "C" void kernel_launch(void* const* d_in, const int* in_sizes, int n_in,
                              void* d_out, int out_size)
{
    const float* query = (const float*)d_in[0];
    const float* key   = (const float*)d_in[1];
    const float* value = (const float*)d_in[2];
    const int*   pad   = (const int*)d_in[3];
    const float* Wq = (const float*)d_in[5];
    const float* bq = (const float*)d_in[6];
    const float* Wk = (const float*)d_in[7];
    const float* bk = (const float*)d_in[8];
    const float* Wv = (const float*)d_in[9];
    const float* bv = (const float*)d_in[10];
    float* out = (float*)d_out;

    conv_all_kernel<<<3 * XB + 3 * WB, 256>>>(query, key, value, Wq, Wk, Wv);
    scan_kernel<<<NB, 1024>>>(pad);

    dim3 pgrid(E_DIM / 128, (NB * SEQ) / 128, 3);
    proj_mma_kernel<<<pgrid, 256>>>(bq, bk, bv);

    dim3 v1grid(NHTOT, 8);
    vmean1_kernel<<<v1grid, 256>>>();
    vmean2_kernel<<<NHTOT, 64>>>();

    cudaFuncSetAttribute(attn_mma_kernel, cudaFuncAttributeMaxDynamicSharedMemorySize,
                         AT_SMEM);
    dim3 agrid(SEQ / 128, NHTOT);
    attn_mma_kernel<<<agrid, 256, AT_SMEM>>>(out);
}